// round 1
// baseline (speedup 1.0000x reference)
#include <cuda_runtime.h>
#include <math.h>

#define BB  8
#define NN  128
#define XDIM 256
#define EDIM 128
#define FFX 1024
#define FFE 512
#define ROWS_X (BB*NN)          // 1024
#define ROWS_E (BB*NN*NN)       // 131072

#define INV_SQRT_DF 0.17677669529663687f   // 1/sqrt(32)

// ---------------- scratch (static device globals; no runtime alloc) ----------------
__device__ float g_Q   [ROWS_X * XDIM];
__device__ float g_Km  [ROWS_X * XDIM];
__device__ float g_V   [ROWS_X * XDIM];
__device__ float g_newX[ROWS_X * XDIM];
__device__ float g_hx  [ROWS_X * XDIM];
__device__ float g_h1x [ROWS_X * FFX];
__device__ float g_h2x [ROWS_X * XDIM];
__device__ float g_Y   [(size_t)ROWS_E * XDIM];   // 134 MB
__device__ float g_newE[(size_t)ROWS_E * EDIM];   // 67 MB
__device__ float g_he  [(size_t)ROWS_E * EDIM];   // 67 MB
__device__ float g_h1e [(size_t)ROWS_E * FFE];    // 268 MB
__device__ float g_h2e [(size_t)ROWS_E * EDIM];   // 67 MB

// ---------------- generic tiled fp32 GEMM: C = alpha*(A@W + bias), opt ReLU ----------------
// A: MxK row-major, W: KxN row-major, bias: N, C: MxN. M,N,K multiples of 64.
template<bool RELU>
__global__ void __launch_bounds__(256) gemm_kernel(
    const float* __restrict__ A, const float* __restrict__ W,
    const float* __restrict__ bias, float* __restrict__ C,
    int M, int N, int K, float alpha)
{
    __shared__ __align__(16) float aS[64][68];
    __shared__ __align__(16) float wS[64][68];

    const int tid = threadIdx.x;
    const int tx  = tid & 15;
    const int ty  = tid >> 4;
    const size_t row0 = (size_t)blockIdx.y * 64;
    const int    col0 = blockIdx.x * 64;

    float acc[4][4] = {};

    for (int k0 = 0; k0 < K; k0 += 64) {
        #pragma unroll
        for (int t = tid; t < 1024; t += 256) {
            int r  = t >> 4;
            int c4 = (t & 15) << 2;
            float4 av = *(const float4*)(A + (row0 + r) * K + k0 + c4);
            aS[r][c4+0] = av.x; aS[r][c4+1] = av.y; aS[r][c4+2] = av.z; aS[r][c4+3] = av.w;
            float4 wv = *(const float4*)(W + (size_t)(k0 + r) * N + col0 + c4);
            wS[r][c4+0] = wv.x; wS[r][c4+1] = wv.y; wS[r][c4+2] = wv.z; wS[r][c4+3] = wv.w;
        }
        __syncthreads();

        #pragma unroll 16
        for (int k = 0; k < 64; ++k) {
            float a0 = aS[ty*4+0][k];
            float a1 = aS[ty*4+1][k];
            float a2 = aS[ty*4+2][k];
            float a3 = aS[ty*4+3][k];
            float4 bv = *(const float4*)&wS[k][tx*4];
            acc[0][0] += a0*bv.x; acc[0][1] += a0*bv.y; acc[0][2] += a0*bv.z; acc[0][3] += a0*bv.w;
            acc[1][0] += a1*bv.x; acc[1][1] += a1*bv.y; acc[1][2] += a1*bv.z; acc[1][3] += a1*bv.w;
            acc[2][0] += a2*bv.x; acc[2][1] += a2*bv.y; acc[2][2] += a2*bv.z; acc[2][3] += a2*bv.w;
            acc[3][0] += a3*bv.x; acc[3][1] += a3*bv.y; acc[3][2] += a3*bv.z; acc[3][3] += a3*bv.w;
        }
        __syncthreads();
    }

    const int c = col0 + tx * 4;
    float b0 = bias[c+0], b1 = bias[c+1], b2 = bias[c+2], b3 = bias[c+3];
    #pragma unroll
    for (int m = 0; m < 4; ++m) {
        float4 o;
        o.x = alpha * (acc[m][0] + b0);
        o.y = alpha * (acc[m][1] + b1);
        o.z = alpha * (acc[m][2] + b2);
        o.w = alpha * (acc[m][3] + b3);
        if (RELU) {
            o.x = fmaxf(o.x, 0.f); o.y = fmaxf(o.y, 0.f);
            o.z = fmaxf(o.z, 0.f); o.w = fmaxf(o.w, 0.f);
        }
        *(float4*)(C + (row0 + ty*4 + m) * N + c) = o;
    }
}

// ---------------- fused edge Y kernel ----------------
// For each edge row r=(b,i,j):
//   E1 = e_row@wem + bem, E2 = e_row@wea + bea (K=128, N=256 each)
//   Y[r][c] = Qs[b,i,c] * Km[b,j,c] * (E1[c]+1) + E2[c]   (Qs pre-scaled by 1/sqrt(32))
// Block: 256 threads, 64 rows (fixed b,i; 64 consecutive j).
__global__ void __launch_bounds__(256) edge_y_kernel(
    const float* __restrict__ e,
    const float* __restrict__ wem, const float* __restrict__ bem,
    const float* __restrict__ wea, const float* __restrict__ bea,
    const float* __restrict__ Qs,  const float* __restrict__ Km,
    float* __restrict__ Y)
{
    extern __shared__ float sm[];
    float (*eS)[132] = (float(*)[132])sm;                       // 64 x 128 (pitch 132)
    float (*wS)[68]  = (float(*)[68])(sm + 64*132);             // 128 x 64 (pitch 68)
    float (*kS)[68]  = (float(*)[68])(sm + 64*132 + 128*68);    // 64 x 64 (pitch 68)

    const int tid = threadIdx.x;
    const int tx  = tid & 15;
    const int ty  = tid >> 4;
    const size_t row0 = (size_t)blockIdx.x * 64;
    const int b  = (int)(row0 >> 14);          // / (128*128)
    const int i  = (int)((row0 >> 7) & 127);
    const int j0 = (int)(row0 & 127);          // 0 or 64

    // load e tile: 64 rows x 128 (contiguous block in memory)
    #pragma unroll
    for (int t = tid; t < 64*32; t += 256) {
        int r  = t >> 5;
        int c4 = (t & 31) << 2;
        float4 v = *(const float4*)(e + (row0 + r) * EDIM + c4);
        eS[r][c4+0] = v.x; eS[r][c4+1] = v.y; eS[r][c4+2] = v.z; eS[r][c4+3] = v.w;
    }

    const float* qrow = Qs + ((size_t)b * NN + i) * XDIM;

    for (int nt = 0; nt < 4; ++nt) {
        const int c0 = nt * 64;
        __syncthreads();  // protect kS/wS from previous iteration readers

        // load K-matrix tile: rows j0..j0+63, cols c0..c0+63
        #pragma unroll
        for (int t = tid; t < 64*16; t += 256) {
            int r  = t >> 4;
            int c4 = (t & 15) << 2;
            float4 v = *(const float4*)(Km + ((size_t)b * NN + j0 + r) * XDIM + c0 + c4);
            kS[r][c4+0] = v.x; kS[r][c4+1] = v.y; kS[r][c4+2] = v.z; kS[r][c4+3] = v.w;
        }
        // load wem chunk: 128 x 64
        #pragma unroll
        for (int t = tid; t < 128*16; t += 256) {
            int r  = t >> 4;
            int c4 = (t & 15) << 2;
            float4 v = *(const float4*)(wem + (size_t)r * XDIM + c0 + c4);
            wS[r][c4+0] = v.x; wS[r][c4+1] = v.y; wS[r][c4+2] = v.z; wS[r][c4+3] = v.w;
        }
        __syncthreads();

        float acc1[4][4] = {};
        #pragma unroll 8
        for (int k = 0; k < 128; ++k) {
            float a0 = eS[ty*4+0][k], a1 = eS[ty*4+1][k], a2 = eS[ty*4+2][k], a3 = eS[ty*4+3][k];
            float4 bv = *(const float4*)&wS[k][tx*4];
            acc1[0][0] += a0*bv.x; acc1[0][1] += a0*bv.y; acc1[0][2] += a0*bv.z; acc1[0][3] += a0*bv.w;
            acc1[1][0] += a1*bv.x; acc1[1][1] += a1*bv.y; acc1[1][2] += a1*bv.z; acc1[1][3] += a1*bv.w;
            acc1[2][0] += a2*bv.x; acc1[2][1] += a2*bv.y; acc1[2][2] += a2*bv.z; acc1[2][3] += a2*bv.w;
            acc1[3][0] += a3*bv.x; acc1[3][1] += a3*bv.y; acc1[3][2] += a3*bv.z; acc1[3][3] += a3*bv.w;
        }
        __syncthreads();

        // load wea chunk
        #pragma unroll
        for (int t = tid; t < 128*16; t += 256) {
            int r  = t >> 4;
            int c4 = (t & 15) << 2;
            float4 v = *(const float4*)(wea + (size_t)r * XDIM + c0 + c4);
            wS[r][c4+0] = v.x; wS[r][c4+1] = v.y; wS[r][c4+2] = v.z; wS[r][c4+3] = v.w;
        }
        __syncthreads();

        float acc2[4][4] = {};
        #pragma unroll 8
        for (int k = 0; k < 128; ++k) {
            float a0 = eS[ty*4+0][k], a1 = eS[ty*4+1][k], a2 = eS[ty*4+2][k], a3 = eS[ty*4+3][k];
            float4 bv = *(const float4*)&wS[k][tx*4];
            acc2[0][0] += a0*bv.x; acc2[0][1] += a0*bv.y; acc2[0][2] += a0*bv.z; acc2[0][3] += a0*bv.w;
            acc2[1][0] += a1*bv.x; acc2[1][1] += a1*bv.y; acc2[1][2] += a1*bv.z; acc2[1][3] += a1*bv.w;
            acc2[2][0] += a2*bv.x; acc2[2][1] += a2*bv.y; acc2[2][2] += a2*bv.z; acc2[2][3] += a2*bv.w;
            acc2[3][0] += a3*bv.x; acc2[3][1] += a3*bv.y; acc2[3][2] += a3*bv.z; acc2[3][3] += a3*bv.w;
        }

        // epilogue: Y = q*k*(E1+1) + E2
        float qv[4], bm[4], ba[4];
        #pragma unroll
        for (int n = 0; n < 4; ++n) {
            int c = c0 + tx*4 + n;
            qv[n] = qrow[c];
            bm[n] = bem[c];
            ba[n] = bea[c];
        }
        #pragma unroll
        for (int m = 0; m < 4; ++m) {
            int r = ty*4 + m;
            float k0v = kS[r][tx*4+0];
            float k1v = kS[r][tx*4+1];
            float k2v = kS[r][tx*4+2];
            float k3v = kS[r][tx*4+3];
            float4 o;
            o.x = qv[0]*k0v*(acc1[m][0] + bm[0] + 1.f) + acc2[m][0] + ba[0];
            o.y = qv[1]*k1v*(acc1[m][1] + bm[1] + 1.f) + acc2[m][1] + ba[1];
            o.z = qv[2]*k2v*(acc1[m][2] + bm[2] + 1.f) + acc2[m][2] + ba[2];
            o.w = qv[3]*k3v*(acc1[m][3] + bm[3] + 1.f) + acc2[m][3] + ba[3];
            *(float4*)(Y + (row0 + r) * XDIM + c0 + tx*4) = o;
        }
    }
}

// ---------------- residual + layernorm: out = LN(A + B) * g + be ----------------
// grid = rows, blockDim = D (128 or 256)
__global__ void ln_kernel(const float* __restrict__ A, const float* __restrict__ Bv,
                          const float* __restrict__ g, const float* __restrict__ be,
                          float* __restrict__ out)
{
    __shared__ float red[8];
    const int D = blockDim.x;
    const size_t base = (size_t)blockIdx.x * D + threadIdx.x;
    const int lane = threadIdx.x & 31;
    const int w    = threadIdx.x >> 5;
    const int nw   = D >> 5;

    float v = A[base] + Bv[base];

    float s = v;
    #pragma unroll
    for (int o = 16; o; o >>= 1) s += __shfl_xor_sync(0xffffffffu, s, o);
    if (lane == 0) red[w] = s;
    __syncthreads();
    float tot = 0.f;
    for (int ww = 0; ww < nw; ++ww) tot += red[ww];
    float mean = tot / (float)D;
    float d = v - mean;
    __syncthreads();

    float s2 = d * d;
    #pragma unroll
    for (int o = 16; o; o >>= 1) s2 += __shfl_xor_sync(0xffffffffu, s2, o);
    if (lane == 0) red[w] = s2;
    __syncthreads();
    float tot2 = 0.f;
    for (int ww = 0; ww < nw; ++ww) tot2 += red[ww];
    float var = tot2 / (float)D;

    out[base] = d * rsqrtf(var + 1e-5f) * g[threadIdx.x] + be[threadIdx.x];
}

// ---------------- launcher ----------------
extern "C" void kernel_launch(void* const* d_in, const int* in_sizes, int n_in,
                              void* d_out, int out_size)
{
    const float* x   = (const float*)d_in[0];
    const float* e   = (const float*)d_in[1];
    const float* wq  = (const float*)d_in[2];
    const float* wk  = (const float*)d_in[3];
    const float* wv  = (const float*)d_in[4];
    const float* wem = (const float*)d_in[5];
    const float* wea = (const float*)d_in[6];
    const float* wxo = (const float*)d_in[7];
    const float* weo = (const float*)d_in[8];
    const float* wx1 = (const float*)d_in[9];
    const float* wx2 = (const float*)d_in[10];
    const float* we1 = (const float*)d_in[11];
    const float* we2 = (const float*)d_in[12];
    const float* bq  = (const float*)d_in[13];
    const float* bk  = (const float*)d_in[14];
    const float* bv  = (const float*)d_in[15];
    const float* bem = (const float*)d_in[16];
    const float* bea = (const float*)d_in[17];
    const float* bxo = (const float*)d_in[18];
    const float* beo = (const float*)d_in[19];
    const float* bx1 = (const float*)d_in[20];
    const float* bx2 = (const float*)d_in[21];
    const float* be1 = (const float*)d_in[22];
    const float* be2 = (const float*)d_in[23];
    const float* gnx = (const float*)d_in[24];
    const float* bnx = (const float*)d_in[25];
    const float* gne = (const float*)d_in[26];
    const float* bne = (const float*)d_in[27];

    float* x_out = (float*)d_out;
    float* e_out = (float*)d_out + (size_t)ROWS_X * XDIM;

    float *Q, *Km, *V, *newX, *hx, *h1x, *h2x, *Y, *newE, *he, *h1e, *h2e;
    cudaGetSymbolAddress((void**)&Q,    g_Q);
    cudaGetSymbolAddress((void**)&Km,   g_Km);
    cudaGetSymbolAddress((void**)&V,    g_V);
    cudaGetSymbolAddress((void**)&newX, g_newX);
    cudaGetSymbolAddress((void**)&hx,   g_hx);
    cudaGetSymbolAddress((void**)&h1x,  g_h1x);
    cudaGetSymbolAddress((void**)&h2x,  g_h2x);
    cudaGetSymbolAddress((void**)&Y,    g_Y);
    cudaGetSymbolAddress((void**)&newE, g_newE);
    cudaGetSymbolAddress((void**)&he,   g_he);
    cudaGetSymbolAddress((void**)&h1e,  g_h1e);
    cudaGetSymbolAddress((void**)&h2e,  g_h2e);

    const int EDGE_SMEM = (64*132 + 128*68 + 64*68) * (int)sizeof(float);  // 86016 B
    cudaFuncSetAttribute(edge_y_kernel, cudaFuncAttributeMaxDynamicSharedMemorySize, EDGE_SMEM);

    dim3 blk(256);
    auto grid_of = [](int M, int N) { return dim3((unsigned)(N/64), (unsigned)(M/64)); };

    // --- node side (tiny) ---
    gemm_kernel<false><<<grid_of(ROWS_X, XDIM), blk>>>(x, wq, bq, Q,  ROWS_X, XDIM, XDIM, INV_SQRT_DF);
    gemm_kernel<false><<<grid_of(ROWS_X, XDIM), blk>>>(x, wk, bk, Km, ROWS_X, XDIM, XDIM, 1.f);
    gemm_kernel<false><<<grid_of(ROWS_X, XDIM), blk>>>(x, wv, bv, V,  ROWS_X, XDIM, XDIM, 1.f);
    // wV == V exactly (softmax sums to 1 over broadcast axis) => newX = V @ wxo + bxo
    gemm_kernel<false><<<grid_of(ROWS_X, XDIM), blk>>>(V, wxo, bxo, newX, ROWS_X, XDIM, XDIM, 1.f);
    ln_kernel<<<ROWS_X, XDIM>>>(x, newX, gnx, bnx, hx);
    gemm_kernel<true ><<<grid_of(ROWS_X, FFX),  blk>>>(hx,  wx1, bx1, h1x, ROWS_X, FFX,  XDIM, 1.f);
    gemm_kernel<false><<<grid_of(ROWS_X, XDIM), blk>>>(h1x, wx2, bx2, h2x, ROWS_X, XDIM, FFX,  1.f);
    ln_kernel<<<ROWS_X, XDIM>>>(x, h2x, gnx, bnx, x_out);

    // --- edge side (dominant) ---
    edge_y_kernel<<<ROWS_E/64, blk, EDGE_SMEM>>>(e, wem, bem, wea, bea, Q, Km, Y);
    gemm_kernel<false><<<grid_of(ROWS_E, EDIM), blk>>>(Y, weo, beo, newE, ROWS_E, EDIM, XDIM, 1.f);
    ln_kernel<<<ROWS_E, EDIM>>>(e, newE, gne, bne, he);
    gemm_kernel<true ><<<grid_of(ROWS_E, FFE),  blk>>>(he,  we1, be1, h1e, ROWS_E, FFE,  EDIM, 1.f);
    gemm_kernel<false><<<grid_of(ROWS_E, EDIM), blk>>>(h1e, we2, be2, h2e, ROWS_E, EDIM, FFE,  1.f);
    ln_kernel<<<ROWS_E, EDIM>>>(e, h2e, gne, bne, e_out);
}

// round 4
// speedup vs baseline: 1.7405x; 1.7405x over previous
#include <cuda_runtime.h>
#include <cuda_bf16.h>
#include <math.h>
#include <stdint.h>

#define BB  8
#define NN  128
#define XD_ 256
#define ED_ 128
#define FFX 1024
#define FFE 512
#define ROWS_X (BB*NN)
#define ROWS_E (BB*NN*NN)
#define INV_SQRT_DF 0.17677669529663687f

#define PITCH     272           // bytes per bf16 tile row (136 bf16)
#define TILE_HALF 34816         // 128 * 272
#define TILE_FULL 69632

// ---------------- scratch ----------------
__device__ float g_Q   [ROWS_X * XD_];
__device__ float g_Km  [ROWS_X * XD_];
__device__ float g_newX[ROWS_X * XD_];
__device__ float g_hx  [ROWS_X * XD_];
__device__ float g_h1x [ROWS_X * FFX];
__device__ float g_h2x [ROWS_X * XD_];
__device__ float g_wvx [XD_ * XD_];
__device__ float g_bvx [XD_];
__device__ float g_zero[FFX];
__device__ float g_Y   [(size_t)ROWS_E * XD_];
__device__ __nv_bfloat16 g_heHi[(size_t)ROWS_E * ED_];
__device__ __nv_bfloat16 g_heLo[(size_t)ROWS_E * ED_];
__device__ __nv_bfloat16 g_h1Hi[(size_t)ROWS_E * FFE];
__device__ __nv_bfloat16 g_h1Lo[(size_t)ROWS_E * FFE];
__device__ __align__(16) char g_wemP[2 * TILE_FULL];
__device__ __align__(16) char g_weaP[2 * TILE_FULL];
__device__ __align__(16) char g_weoP[2 * TILE_FULL];
__device__ __align__(16) char g_we1P[4 * TILE_FULL];
__device__ __align__(16) char g_we2P[4 * TILE_FULL];

// ---------------- helpers ----------------
__device__ __forceinline__ uint32_t smem_u32(const void* p) {
    uint32_t a;
    asm("{ .reg .u64 t; cvta.to.shared.u64 t, %1; cvt.u32.u64 %0, t; }" : "=r"(a) : "l"(p));
    return a;
}

__device__ __forceinline__ void mma16816(float* c, uint32_t a0, uint32_t a1, uint32_t a2,
                                         uint32_t a3, uint32_t b0, uint32_t b1) {
    asm volatile(
        "mma.sync.aligned.m16n8k16.row.col.f32.bf16.bf16.f32 "
        "{%0,%1,%2,%3},{%4,%5,%6,%7},{%8,%9},{%0,%1,%2,%3};"
        : "+f"(c[0]), "+f"(c[1]), "+f"(c[2]), "+f"(c[3])
        : "r"(a0), "r"(a1), "r"(a2), "r"(a3), "r"(b0), "r"(b1));
}

__device__ __forceinline__ void ldsm4(uint32_t& r0, uint32_t& r1, uint32_t& r2, uint32_t& r3,
                                      uint32_t a) {
    asm volatile("ldmatrix.sync.aligned.m8n8.x4.shared.b16 {%0,%1,%2,%3},[%4];"
                 : "=r"(r0), "=r"(r1), "=r"(r2), "=r"(r3) : "r"(a));
}

// A fragment: 32 rows x 16 k
__device__ __forceinline__ void ldA8(uint32_t a[8], uint32_t base, int r0, int k0, int lane) {
    uint32_t addr = base + (uint32_t)(r0 + (lane & 15)) * PITCH
                  + (uint32_t)(k0 + ((lane >> 4) << 3)) * 2;
    ldsm4(a[0], a[1], a[2], a[3], addr);
    ldsm4(a[4], a[5], a[6], a[7], addr + 16 * PITCH);
}

// B fragment: 64 n x 16 k (n-major storage)
__device__ __forceinline__ void ldB16(uint32_t b[16], uint32_t base, int n0, int k0, int lane) {
    uint32_t addr = base + (uint32_t)(n0 + ((lane >> 4) << 3) + (lane & 7)) * PITCH
                  + (uint32_t)(k0 + (((lane >> 3) & 1) << 3)) * 2;
    ldsm4(b[0],  b[1],  b[2],  b[3],  addr);
    ldsm4(b[4],  b[5],  b[6],  b[7],  addr + 16 * PITCH);
    ldsm4(b[8],  b[9],  b[10], b[11], addr + 32 * PITCH);
    ldsm4(b[12], b[13], b[14], b[15], addr + 48 * PITCH);
}

__device__ __forceinline__ void mma_pass(float (&acc)[2][8][4], const uint32_t a[8],
                                         const uint32_t b[16]) {
    #pragma unroll
    for (int mf = 0; mf < 2; mf++)
        #pragma unroll
        for (int nf = 0; nf < 8; nf++)
            mma16816(acc[mf][nf], a[mf*4], a[mf*4+1], a[mf*4+2], a[mf*4+3],
                     b[nf*2], b[nf*2+1]);
}

__device__ __forceinline__ void compute_ktile(float (&acc)[2][8][4], uint32_t aHi, uint32_t aLo,
                                              uint32_t bHi, uint32_t bLo, int wm, int wn, int lane) {
    #pragma unroll 1
    for (int ks = 0; ks < 8; ks++) {
        uint32_t ah[8], al[8], bh[16], bl[16];
        ldA8(ah, aHi, wm * 32, ks * 16, lane);
        ldA8(al, aLo, wm * 32, ks * 16, lane);
        ldB16(bh, bHi, wn * 64, ks * 16, lane);
        ldB16(bl, bLo, wn * 64, ks * 16, lane);
        mma_pass(acc, ah, bh);
        mma_pass(acc, ah, bl);
        mma_pass(acc, al, bh);
    }
}

__device__ __forceinline__ uint32_t pk2(__nv_bfloat16 a, __nv_bfloat16 b) {
    return (uint32_t)__bfloat16_as_ushort(a) | ((uint32_t)__bfloat16_as_ushort(b) << 16);
}
__device__ __forceinline__ void split2(float x, float y, uint32_t& hi, uint32_t& lo) {
    __nv_bfloat16 hx = __float2bfloat16(x), hy = __float2bfloat16(y);
    __nv_bfloat16 lx = __float2bfloat16(x - __bfloat162float(hx));
    __nv_bfloat16 ly = __float2bfloat16(y - __bfloat162float(hy));
    hi = pk2(hx, hy); lo = pk2(lx, ly);
}

__device__ __forceinline__ void stage_a_fp32(char* sm, const float* src, int stride, int tid) {
    #pragma unroll 4
    for (int t = tid; t < 4096; t += 256) {
        int r = t >> 5, c4 = (t & 31) << 2;
        float4 v = *(const float4*)(src + (size_t)r * stride + c4);
        uint32_t h0, l0, h1, l1;
        split2(v.x, v.y, h0, l0);
        split2(v.z, v.w, h1, l1);
        uint32_t off = (uint32_t)r * PITCH + (uint32_t)c4 * 2;
        *(uint2*)(sm + off)             = make_uint2(h0, h1);
        *(uint2*)(sm + TILE_HALF + off) = make_uint2(l0, l1);
    }
}

__device__ __forceinline__ void stage_a_split(char* sm, const __nv_bfloat16* hiS,
                                              const __nv_bfloat16* loS, size_t row0,
                                              int stride, int colOff, int tid) {
    #pragma unroll 4
    for (int t = tid; t < 2048; t += 256) {
        int r = t >> 4, c8 = (t & 15) << 3;
        size_t gi = (row0 + r) * (size_t)stride + colOff + c8;
        uint32_t off = (uint32_t)r * PITCH + (uint32_t)c8 * 2;
        *(uint4*)(sm + off)             = *(const uint4*)(hiS + gi);
        *(uint4*)(sm + TILE_HALF + off) = *(const uint4*)(loS + gi);
    }
}

__device__ __forceinline__ void stage_w(char* dst, const char* src, int tid) {
    const uint4* s = (const uint4*)src;
    uint4* d = (uint4*)dst;
    #pragma unroll 4
    for (int t = tid; t < 4352; t += 256) d[t] = s[t];
}

// ---------------- weight prep ----------------
__global__ void prep_weight(const float* __restrict__ W, int K, int N, char* __restrict__ out) {
    int KC = K >> 7;
    int s = blockIdx.x;
    int kc = s % KC, nc = s / KC;
    char* base = out + (size_t)s * TILE_FULL;
    for (int t = threadIdx.x; t < 16384; t += 256) {
        int n = t >> 7, k = t & 127;
        float v = W[(size_t)(kc * 128 + k) * N + nc * 128 + n];
        __nv_bfloat16 h = __float2bfloat16(v);
        __nv_bfloat16 l = __float2bfloat16(v - __bfloat162float(h));
        uint32_t off = (uint32_t)n * PITCH + (uint32_t)k * 2;
        *(__nv_bfloat16*)(base + off) = h;
        *(__nv_bfloat16*)(base + TILE_HALF + off) = l;
    }
}

__global__ void fold_bias(const float* __restrict__ bv, const float* __restrict__ wxo,
                          const float* __restrict__ bxo, float* __restrict__ bvx) {
    int n = threadIdx.x;
    float s = bxo[n];
    for (int k = 0; k < XD_; ++k) s += bv[k] * wxo[k * XD_ + n];
    bvx[n] = s;
}

// ---------------- edge_y ----------------
#define EY_A   0
#define EY_BM  69632
#define EY_BA  139264
#define EY_Q   208896
#define EY_BEM 209920
#define EY_BEA 210944
#define EY_BYTES 211968

__global__ void __launch_bounds__(256, 1) edge_y_kernel(
    const float* __restrict__ e, const float* __restrict__ Qs, const float* __restrict__ Km,
    const char* __restrict__ wemP, const char* __restrict__ weaP,
    const float* __restrict__ bem, const float* __restrict__ bea,
    float* __restrict__ Y)
{
    extern __shared__ char sm[];
    const int tid = threadIdx.x;
    const int lane = tid & 31, w = tid >> 5;
    const int wm = w & 3, wn = w >> 2;
    const int g = lane >> 2, q = lane & 3;
    const int blk = blockIdx.x;
    const size_t row0 = (size_t)blk * 128;
    const int b = blk >> 7, i = blk & 127;

    uint32_t smB = smem_u32(sm);
    float* qS   = (float*)(sm + EY_Q);
    float* bemS = (float*)(sm + EY_BEM);
    float* beaS = (float*)(sm + EY_BEA);
    float* kmS  = (float*)(sm + EY_BM);   // reused after MMA

    stage_a_fp32(sm + EY_A, e + row0 * ED_, ED_, tid);
    qS[tid]   = Qs[((size_t)(b * NN + i)) * XD_ + tid];
    bemS[tid] = bem[tid];
    beaS[tid] = bea[tid];

    #pragma unroll 1
    for (int nc = 0; nc < 2; nc++) {
        __syncthreads();
        stage_w(sm + EY_BM, wemP + (size_t)nc * TILE_FULL, tid);
        stage_w(sm + EY_BA, weaP + (size_t)nc * TILE_FULL, tid);
        __syncthreads();

        float acc1[2][8][4] = {}, acc2[2][8][4] = {};
        #pragma unroll 1
        for (int ks = 0; ks < 8; ks++) {
            uint32_t ah[8], al[8], bh[16], bl[16];
            ldA8(ah, smB + EY_A,             wm * 32, ks * 16, lane);
            ldA8(al, smB + EY_A + TILE_HALF, wm * 32, ks * 16, lane);
            ldB16(bh, smB + EY_BM,             wn * 64, ks * 16, lane);
            ldB16(bl, smB + EY_BM + TILE_HALF, wn * 64, ks * 16, lane);
            mma_pass(acc1, ah, bh); mma_pass(acc1, ah, bl); mma_pass(acc1, al, bh);
            ldB16(bh, smB + EY_BA,             wn * 64, ks * 16, lane);
            ldB16(bl, smB + EY_BA + TILE_HALF, wn * 64, ks * 16, lane);
            mma_pass(acc2, ah, bh); mma_pass(acc2, ah, bl); mma_pass(acc2, al, bh);
        }
        __syncthreads();
        #pragma unroll 4
        for (int t = tid; t < 4096; t += 256) {
            int r = t >> 5, c4 = (t & 31) << 2;
            float4 v = *(const float4*)(Km + ((size_t)(b * NN + r)) * XD_ + nc * 128 + c4);
            *(float4*)(kmS + r * 132 + c4) = v;
        }
        __syncthreads();

        #pragma unroll
        for (int mf = 0; mf < 2; mf++)
        #pragma unroll
        for (int h = 0; h < 2; h++) {
            int r = wm * 32 + mf * 16 + h * 8 + g;
            #pragma unroll
            for (int nf = 0; nf < 8; nf++) {
                int cl = wn * 64 + nf * 8 + q * 2;
                int cg = nc * 128 + cl;
                float e1a = acc1[mf][nf][h*2+0] + bemS[cg]   + 1.f;
                float e1b = acc1[mf][nf][h*2+1] + bemS[cg+1] + 1.f;
                float e2a = acc2[mf][nf][h*2+0] + beaS[cg];
                float e2b = acc2[mf][nf][h*2+1] + beaS[cg+1];
                float y0 = qS[cg]   * kmS[r*132 + cl]   * e1a + e2a;
                float y1 = qS[cg+1] * kmS[r*132 + cl+1] * e1b + e2b;
                *(float2*)(Y + (row0 + r) * XD_ + cg) = make_float2(y0, y1);
            }
        }
    }
}

// ---------------- newE + LN -> he ----------------
#define NE_A    0
#define NE_B    69632
#define NE_RED  139264
#define NE_BIAS 141312
#define NE_G    141824
#define NE_BB   142336
#define NE_BYTES 142848

__global__ void __launch_bounds__(256, 1) newE_kernel(
    const float* __restrict__ Yv, const float* __restrict__ e,
    const char* __restrict__ weoP, const float* __restrict__ beo,
    const float* __restrict__ gne, const float* __restrict__ bne,
    __nv_bfloat16* __restrict__ heHi, __nv_bfloat16* __restrict__ heLo)
{
    extern __shared__ char sm[];
    const int tid = threadIdx.x;
    const int lane = tid & 31, w = tid >> 5;
    const int wm = w & 3, wn = w >> 2;
    const int g = lane >> 2, q = lane & 3;
    const size_t row0 = (size_t)blockIdx.x * 128;

    uint32_t smB = smem_u32(sm);
    float* red   = (float*)(sm + NE_RED);
    float* red2  = red + 256;
    float* biasS = (float*)(sm + NE_BIAS);
    float* gS    = (float*)(sm + NE_G);
    float* bS    = (float*)(sm + NE_BB);
    if (tid < 128) { biasS[tid] = beo[tid]; gS[tid] = gne[tid]; bS[tid] = bne[tid]; }

    float acc[2][8][4] = {};
    #pragma unroll 1
    for (int kt = 0; kt < 2; kt++) {
        __syncthreads();
        stage_a_fp32(sm + NE_A, Yv + row0 * XD_ + kt * 128, XD_, tid);
        stage_w(sm + NE_B, weoP + (size_t)kt * TILE_FULL, tid);
        __syncthreads();
        compute_ktile(acc, smB + NE_A, smB + NE_A + TILE_HALF,
                      smB + NE_B, smB + NE_B + TILE_HALF, wm, wn, lane);
    }

    #pragma unroll
    for (int mf = 0; mf < 2; mf++)
    #pragma unroll
    for (int h = 0; h < 2; h++) {
        int r = wm * 32 + mf * 16 + h * 8 + g;
        #pragma unroll
        for (int nf = 0; nf < 8; nf++) {
            int cl = wn * 64 + nf * 8 + q * 2;
            float2 ev = *(const float2*)(e + (row0 + r) * ED_ + cl);
            acc[mf][nf][h*2+0] += biasS[cl]   + ev.x;
            acc[mf][nf][h*2+1] += biasS[cl+1] + ev.y;
        }
    }
    float mean[2][2], rstd[2][2];
    #pragma unroll
    for (int mf = 0; mf < 2; mf++)
    #pragma unroll
    for (int h = 0; h < 2; h++) {
        float s = 0.f;
        #pragma unroll
        for (int nf = 0; nf < 8; nf++) s += acc[mf][nf][h*2] + acc[mf][nf][h*2+1];
        s += __shfl_xor_sync(0xffffffffu, s, 1);
        s += __shfl_xor_sync(0xffffffffu, s, 2);
        if (q == 0) red[wn * 128 + wm * 32 + mf * 16 + h * 8 + g] = s;
    }
    __syncthreads();
    #pragma unroll
    for (int mf = 0; mf < 2; mf++)
    #pragma unroll
    for (int h = 0; h < 2; h++) {
        int r = wm * 32 + mf * 16 + h * 8 + g;
        mean[mf][h] = (red[r] + red[128 + r]) * (1.f / 128.f);
        float s = 0.f;
        #pragma unroll
        for (int nf = 0; nf < 8; nf++) {
            float d0 = acc[mf][nf][h*2]   - mean[mf][h];
            float d1 = acc[mf][nf][h*2+1] - mean[mf][h];
            s += d0 * d0 + d1 * d1;
        }
        s += __shfl_xor_sync(0xffffffffu, s, 1);
        s += __shfl_xor_sync(0xffffffffu, s, 2);
        if (q == 0) red2[wn * 128 + r] = s;
    }
    __syncthreads();
    #pragma unroll
    for (int mf = 0; mf < 2; mf++)
    #pragma unroll
    for (int h = 0; h < 2; h++) {
        int r = wm * 32 + mf * 16 + h * 8 + g;
        rstd[mf][h] = rsqrtf((red2[r] + red2[128 + r]) * (1.f / 128.f) + 1e-5f);
        #pragma unroll
        for (int nf = 0; nf < 8; nf++) {
            int cl = wn * 64 + nf * 8 + q * 2;
            float o0 = (acc[mf][nf][h*2]   - mean[mf][h]) * rstd[mf][h] * gS[cl]   + bS[cl];
            float o1 = (acc[mf][nf][h*2+1] - mean[mf][h]) * rstd[mf][h] * gS[cl+1] + bS[cl+1];
            uint32_t hi, lo;
            split2(o0, o1, hi, lo);
            size_t oi = ((row0 + r) * ED_ + cl) * 2;
            *(uint32_t*)((char*)heHi + oi) = hi;
            *(uint32_t*)((char*)heLo + oi) = lo;
        }
    }
}

// ---------------- FF1 ----------------
#define F1_A  0
#define F1_B  69632
#define F1_BE 139264
#define F1_BYTES 141312

__global__ void __launch_bounds__(256, 1) ff1_kernel(
    const __nv_bfloat16* __restrict__ heHi, const __nv_bfloat16* __restrict__ heLo,
    const char* __restrict__ we1P, const float* __restrict__ be1,
    __nv_bfloat16* __restrict__ h1Hi, __nv_bfloat16* __restrict__ h1Lo)
{
    extern __shared__ char sm[];
    const int tid = threadIdx.x;
    const int lane = tid & 31, w = tid >> 5;
    const int wm = w & 3, wn = w >> 2;
    const int g = lane >> 2, q = lane & 3;
    const size_t row0 = (size_t)blockIdx.x * 128;

    uint32_t smB = smem_u32(sm);
    float* beS = (float*)(sm + F1_BE);

    stage_a_split(sm + F1_A, heHi, heLo, row0, ED_, 0, tid);
    for (int t = tid; t < 512; t += 256) beS[t] = be1[t];

    #pragma unroll 1
    for (int nc = 0; nc < 4; nc++) {
        __syncthreads();
        stage_w(sm + F1_B, we1P + (size_t)nc * TILE_FULL, tid);
        __syncthreads();
        float acc[2][8][4] = {};
        compute_ktile(acc, smB + F1_A, smB + F1_A + TILE_HALF,
                      smB + F1_B, smB + F1_B + TILE_HALF, wm, wn, lane);
        #pragma unroll
        for (int mf = 0; mf < 2; mf++)
        #pragma unroll
        for (int h = 0; h < 2; h++) {
            int r = wm * 32 + mf * 16 + h * 8 + g;
            #pragma unroll
            for (int nf = 0; nf < 8; nf++) {
                int cl = wn * 64 + nf * 8 + q * 2;
                int cgl = nc * 128 + cl;
                float o0 = fmaxf(acc[mf][nf][h*2]   + beS[cgl],   0.f);
                float o1 = fmaxf(acc[mf][nf][h*2+1] + beS[cgl+1], 0.f);
                uint32_t hi, lo;
                split2(o0, o1, hi, lo);
                size_t oi = ((row0 + r) * FFE + cgl) * 2;
                *(uint32_t*)((char*)h1Hi + oi) = hi;
                *(uint32_t*)((char*)h1Lo + oi) = lo;
            }
        }
    }
}

// ---------------- FF2 + LN ----------------
__global__ void __launch_bounds__(256, 1) ff2_kernel(
    const __nv_bfloat16* __restrict__ h1Hi, const __nv_bfloat16* __restrict__ h1Lo,
    const float* __restrict__ e,
    const char* __restrict__ we2P, const float* __restrict__ be2,
    const float* __restrict__ gne, const float* __restrict__ bne,
    float* __restrict__ e_out)
{
    extern __shared__ char sm[];
    const int tid = threadIdx.x;
    const int lane = tid & 31, w = tid >> 5;
    const int wm = w & 3, wn = w >> 2;
    const int g = lane >> 2, q = lane & 3;
    const size_t row0 = (size_t)blockIdx.x * 128;

    uint32_t smB = smem_u32(sm);
    float* red   = (float*)(sm + NE_RED);
    float* red2  = red + 256;
    float* biasS = (float*)(sm + NE_BIAS);
    float* gS    = (float*)(sm + NE_G);
    float* bS    = (float*)(sm + NE_BB);
    if (tid < 128) { biasS[tid] = be2[tid]; gS[tid] = gne[tid]; bS[tid] = bne[tid]; }

    float acc[2][8][4] = {};
    #pragma unroll 1
    for (int kt = 0; kt < 4; kt++) {
        __syncthreads();
        stage_a_split(sm + NE_A, h1Hi, h1Lo, row0, FFE, kt * 128, tid);
        stage_w(sm + NE_B, we2P + (size_t)kt * TILE_FULL, tid);
        __syncthreads();
        compute_ktile(acc, smB + NE_A, smB + NE_A + TILE_HALF,
                      smB + NE_B, smB + NE_B + TILE_HALF, wm, wn, lane);
    }

    #pragma unroll
    for (int mf = 0; mf < 2; mf++)
    #pragma unroll
    for (int h = 0; h < 2; h++) {
        int r = wm * 32 + mf * 16 + h * 8 + g;
        #pragma unroll
        for (int nf = 0; nf < 8; nf++) {
            int cl = wn * 64 + nf * 8 + q * 2;
            float2 ev = *(const float2*)(e + (row0 + r) * ED_ + cl);
            acc[mf][nf][h*2+0] += biasS[cl]   + ev.x;
            acc[mf][nf][h*2+1] += biasS[cl+1] + ev.y;
        }
    }
    float mean[2][2], rstd[2][2];
    #pragma unroll
    for (int mf = 0; mf < 2; mf++)
    #pragma unroll
    for (int h = 0; h < 2; h++) {
        float s = 0.f;
        #pragma unroll
        for (int nf = 0; nf < 8; nf++) s += acc[mf][nf][h*2] + acc[mf][nf][h*2+1];
        s += __shfl_xor_sync(0xffffffffu, s, 1);
        s += __shfl_xor_sync(0xffffffffu, s, 2);
        if (q == 0) red[wn * 128 + wm * 32 + mf * 16 + h * 8 + g] = s;
    }
    __syncthreads();
    #pragma unroll
    for (int mf = 0; mf < 2; mf++)
    #pragma unroll
    for (int h = 0; h < 2; h++) {
        int r = wm * 32 + mf * 16 + h * 8 + g;
        mean[mf][h] = (red[r] + red[128 + r]) * (1.f / 128.f);
        float s = 0.f;
        #pragma unroll
        for (int nf = 0; nf < 8; nf++) {
            float d0 = acc[mf][nf][h*2]   - mean[mf][h];
            float d1 = acc[mf][nf][h*2+1] - mean[mf][h];
            s += d0 * d0 + d1 * d1;
        }
        s += __shfl_xor_sync(0xffffffffu, s, 1);
        s += __shfl_xor_sync(0xffffffffu, s, 2);
        if (q == 0) red2[wn * 128 + r] = s;
    }
    __syncthreads();
    #pragma unroll
    for (int mf = 0; mf < 2; mf++)
    #pragma unroll
    for (int h = 0; h < 2; h++) {
        int r = wm * 32 + mf * 16 + h * 8 + g;
        rstd[mf][h] = rsqrtf((red2[r] + red2[128 + r]) * (1.f / 128.f) + 1e-5f);
        #pragma unroll
        for (int nf = 0; nf < 8; nf++) {
            int cl = wn * 64 + nf * 8 + q * 2;
            float o0 = (acc[mf][nf][h*2]   - mean[mf][h]) * rstd[mf][h] * gS[cl]   + bS[cl];
            float o1 = (acc[mf][nf][h*2+1] - mean[mf][h]) * rstd[mf][h] * gS[cl+1] + bS[cl+1];
            *(float2*)(e_out + (row0 + r) * ED_ + cl) = make_float2(o0, o1);
        }
    }
}

// ---------------- node-side SIMT GEMM + LN ----------------
template<bool RELU>
__global__ void __launch_bounds__(256) gemm_kernel(
    const float* __restrict__ A, const float* __restrict__ W,
    const float* __restrict__ bias, float* __restrict__ C,
    int M, int N, int K, float alpha)
{
    __shared__ __align__(16) float aS[64][68];
    __shared__ __align__(16) float wS[64][68];
    const int tid = threadIdx.x;
    const int tx  = tid & 15;
    const int ty  = tid >> 4;
    const size_t row0 = (size_t)blockIdx.y * 64;
    const int    col0 = blockIdx.x * 64;
    float acc[4][4] = {};
    for (int k0 = 0; k0 < K; k0 += 64) {
        #pragma unroll
        for (int t = tid; t < 1024; t += 256) {
            int r = t >> 4, c4 = (t & 15) << 2;
            float4 av = *(const float4*)(A + (row0 + r) * K + k0 + c4);
            aS[r][c4+0]=av.x; aS[r][c4+1]=av.y; aS[r][c4+2]=av.z; aS[r][c4+3]=av.w;
            float4 wv = *(const float4*)(W + (size_t)(k0 + r) * N + col0 + c4);
            wS[r][c4+0]=wv.x; wS[r][c4+1]=wv.y; wS[r][c4+2]=wv.z; wS[r][c4+3]=wv.w;
        }
        __syncthreads();
        #pragma unroll 16
        for (int k = 0; k < 64; ++k) {
            float a0=aS[ty*4+0][k], a1=aS[ty*4+1][k], a2=aS[ty*4+2][k], a3=aS[ty*4+3][k];
            float4 bv = *(const float4*)&wS[k][tx*4];
            acc[0][0]+=a0*bv.x; acc[0][1]+=a0*bv.y; acc[0][2]+=a0*bv.z; acc[0][3]+=a0*bv.w;
            acc[1][0]+=a1*bv.x; acc[1][1]+=a1*bv.y; acc[1][2]+=a1*bv.z; acc[1][3]+=a1*bv.w;
            acc[2][0]+=a2*bv.x; acc[2][1]+=a2*bv.y; acc[2][2]+=a2*bv.z; acc[2][3]+=a2*bv.w;
            acc[3][0]+=a3*bv.x; acc[3][1]+=a3*bv.y; acc[3][2]+=a3*bv.z; acc[3][3]+=a3*bv.w;
        }
        __syncthreads();
    }
    const int c = col0 + tx * 4;
    float b0=bias[c+0], b1=bias[c+1], b2=bias[c+2], b3=bias[c+3];
    #pragma unroll
    for (int m = 0; m < 4; ++m) {
        float4 o;
        o.x = alpha*(acc[m][0]+b0); o.y = alpha*(acc[m][1]+b1);
        o.z = alpha*(acc[m][2]+b2); o.w = alpha*(acc[m][3]+b3);
        if (RELU) { o.x=fmaxf(o.x,0.f); o.y=fmaxf(o.y,0.f); o.z=fmaxf(o.z,0.f); o.w=fmaxf(o.w,0.f); }
        *(float4*)(C + (row0 + ty*4 + m) * N + c) = o;
    }
}

__global__ void ln_kernel(const float* __restrict__ A, const float* __restrict__ Bv,
                          const float* __restrict__ g, const float* __restrict__ be,
                          float* __restrict__ out)
{
    __shared__ float red[8];
    const int D = blockDim.x;
    const size_t base = (size_t)blockIdx.x * D + threadIdx.x;
    const int lane = threadIdx.x & 31;
    const int w    = threadIdx.x >> 5;
    const int nw   = D >> 5;
    float v = A[base] + Bv[base];
    float s = v;
    #pragma unroll
    for (int o = 16; o; o >>= 1) s += __shfl_xor_sync(0xffffffffu, s, o);
    if (lane == 0) red[w] = s;
    __syncthreads();
    float tot = 0.f;
    for (int ww = 0; ww < nw; ++ww) tot += red[ww];
    float mean = tot / (float)D;
    float d = v - mean;
    __syncthreads();
    float s2 = d * d;
    #pragma unroll
    for (int o = 16; o; o >>= 1) s2 += __shfl_xor_sync(0xffffffffu, s2, o);
    if (lane == 0) red[w] = s2;
    __syncthreads();
    float tot2 = 0.f;
    for (int ww = 0; ww < nw; ++ww) tot2 += red[ww];
    float var = tot2 / (float)D;
    out[base] = d * rsqrtf(var + 1e-5f) * g[threadIdx.x] + be[threadIdx.x];
}

// ---------------- launcher ----------------
extern "C" void kernel_launch(void* const* d_in, const int* in_sizes, int n_in,
                              void* d_out, int out_size)
{
    const float* x   = (const float*)d_in[0];
    const float* e   = (const float*)d_in[1];
    const float* wq  = (const float*)d_in[2];
    const float* wk  = (const float*)d_in[3];
    const float* wv  = (const float*)d_in[4];
    const float* wem = (const float*)d_in[5];
    const float* wea = (const float*)d_in[6];
    const float* wxo = (const float*)d_in[7];
    const float* weo = (const float*)d_in[8];
    const float* wx1 = (const float*)d_in[9];
    const float* wx2 = (const float*)d_in[10];
    const float* we1 = (const float*)d_in[11];
    const float* we2 = (const float*)d_in[12];
    const float* bq  = (const float*)d_in[13];
    const float* bk  = (const float*)d_in[14];
    const float* bv  = (const float*)d_in[15];
    const float* bem = (const float*)d_in[16];
    const float* bea = (const float*)d_in[17];
    const float* bxo = (const float*)d_in[18];
    const float* beo = (const float*)d_in[19];
    const float* bx1 = (const float*)d_in[20];
    const float* bx2 = (const float*)d_in[21];
    const float* be1 = (const float*)d_in[22];
    const float* be2 = (const float*)d_in[23];
    const float* gnx = (const float*)d_in[24];
    const float* bnx = (const float*)d_in[25];
    const float* gne = (const float*)d_in[26];
    const float* bne = (const float*)d_in[27];

    float* x_out = (float*)d_out;
    float* e_out = (float*)d_out + (size_t)ROWS_X * XD_;

    float *Q, *Km, *newX, *hx, *h1x, *h2x, *wvx, *bvx, *zero, *Y;
    __nv_bfloat16 *heHi, *heLo, *h1Hi, *h1Lo;
    char *wemP, *weaP, *weoP, *we1P, *we2P;
    cudaGetSymbolAddress((void**)&Q,    g_Q);
    cudaGetSymbolAddress((void**)&Km,   g_Km);
    cudaGetSymbolAddress((void**)&newX, g_newX);
    cudaGetSymbolAddress((void**)&hx,   g_hx);
    cudaGetSymbolAddress((void**)&h1x,  g_h1x);
    cudaGetSymbolAddress((void**)&h2x,  g_h2x);
    cudaGetSymbolAddress((void**)&wvx,  g_wvx);
    cudaGetSymbolAddress((void**)&bvx,  g_bvx);
    cudaGetSymbolAddress((void**)&zero, g_zero);
    cudaGetSymbolAddress((void**)&Y,    g_Y);
    cudaGetSymbolAddress((void**)&heHi, g_heHi);
    cudaGetSymbolAddress((void**)&heLo, g_heLo);
    cudaGetSymbolAddress((void**)&h1Hi, g_h1Hi);
    cudaGetSymbolAddress((void**)&h1Lo, g_h1Lo);
    cudaGetSymbolAddress((void**)&wemP, g_wemP);
    cudaGetSymbolAddress((void**)&weaP, g_weaP);
    cudaGetSymbolAddress((void**)&weoP, g_weoP);
    cudaGetSymbolAddress((void**)&we1P, g_we1P);
    cudaGetSymbolAddress((void**)&we2P, g_we2P);

    cudaFuncSetAttribute(edge_y_kernel, cudaFuncAttributeMaxDynamicSharedMemorySize, EY_BYTES);
    cudaFuncSetAttribute(newE_kernel,   cudaFuncAttributeMaxDynamicSharedMemorySize, NE_BYTES);
    cudaFuncSetAttribute(ff1_kernel,    cudaFuncAttributeMaxDynamicSharedMemorySize, F1_BYTES);
    cudaFuncSetAttribute(ff2_kernel,    cudaFuncAttributeMaxDynamicSharedMemorySize, NE_BYTES);

    dim3 blk(256);
    auto grid_of = [](int M, int N) { return dim3((unsigned)(N/64), (unsigned)(M/64)); };

    prep_weight<<<2, 256>>>(wem, 128, 256, wemP);
    prep_weight<<<2, 256>>>(wea, 128, 256, weaP);
    prep_weight<<<2, 256>>>(weo, 256, 128, weoP);
    prep_weight<<<4, 256>>>(we1, 128, 512, we1P);
    prep_weight<<<4, 256>>>(we2, 512, 128, we2P);

    // node side (softmax collapses: wV == V; fold wv@wxo)
    gemm_kernel<false><<<grid_of(XD_, XD_), blk>>>(wv, wxo, zero, wvx, XD_, XD_, XD_, 1.f);
    fold_bias<<<1, 256>>>(bv, wxo, bxo, bvx);
    gemm_kernel<false><<<grid_of(ROWS_X, XD_), blk>>>(x, wq, bq, Q,  ROWS_X, XD_, XD_, INV_SQRT_DF);
    gemm_kernel<false><<<grid_of(ROWS_X, XD_), blk>>>(x, wk, bk, Km, ROWS_X, XD_, XD_, 1.f);
    gemm_kernel<false><<<grid_of(ROWS_X, XD_), blk>>>(x, wvx, bvx, newX, ROWS_X, XD_, XD_, 1.f);
    ln_kernel<<<ROWS_X, XD_>>>(x, newX, gnx, bnx, hx);
    gemm_kernel<true ><<<grid_of(ROWS_X, FFX), blk>>>(hx,  wx1, bx1, h1x, ROWS_X, FFX, XD_, 1.f);
    gemm_kernel<false><<<grid_of(ROWS_X, XD_), blk>>>(h1x, wx2, bx2, h2x, ROWS_X, XD_, FFX, 1.f);
    ln_kernel<<<ROWS_X, XD_>>>(x, h2x, gnx, bnx, x_out);

    // edge side (tensor cores via mma.sync)
    edge_y_kernel<<<ROWS_E / 128, blk, EY_BYTES>>>(e, Q, Km, wemP, weaP, bem, bea, Y);
    newE_kernel  <<<ROWS_E / 128, blk, NE_BYTES>>>(Y, e, weoP, beo, gne, bne, heHi, heLo);
    ff1_kernel   <<<ROWS_E / 128, blk, F1_BYTES>>>(heHi, heLo, we1P, be1, h1Hi, h1Lo);
    ff2_kernel   <<<ROWS_E / 128, blk, NE_BYTES>>>(h1Hi, h1Lo, e, we2P, be2, gne, bne, e_out);
}

// round 5
// speedup vs baseline: 2.0348x; 1.1691x over previous
#include <cuda_runtime.h>
#include <cuda_bf16.h>
#include <math.h>
#include <stdint.h>

#define BB  8
#define NN  128
#define XD_ 256
#define ED_ 128
#define FFX 1024
#define FFE 512
#define ROWS_X (BB*NN)
#define ROWS_E (BB*NN*NN)
#define INV_SQRT_DF 0.17677669529663687f

#define PITCH     272           // bytes per bf16 tile row (136 bf16)
#define TILE_HALF 34816         // 128 * 272
#define TILE_FULL 69632

// ---------------- scratch ----------------
__device__ float g_Q   [ROWS_X * XD_];
__device__ float g_Km  [ROWS_X * XD_];
__device__ float g_newX[ROWS_X * XD_];
__device__ float g_hx  [ROWS_X * XD_];
__device__ float g_h1x [ROWS_X * FFX];
__device__ float g_h2x [ROWS_X * XD_];
__device__ float g_wvx [XD_ * XD_];
__device__ float g_bvx [XD_];
__device__ float g_zero[FFX];
__device__ __nv_bfloat16 g_heHi[(size_t)ROWS_E * ED_];
__device__ __nv_bfloat16 g_heLo[(size_t)ROWS_E * ED_];
__device__ __align__(16) char g_wemP[2 * TILE_FULL];
__device__ __align__(16) char g_weaP[2 * TILE_FULL];
__device__ __align__(16) char g_weoP[2 * TILE_FULL];
__device__ __align__(16) char g_we1P[4 * TILE_FULL];
__device__ __align__(16) char g_we2P[4 * TILE_FULL];

// ---------------- helpers ----------------
__device__ __forceinline__ uint32_t smem_u32(const void* p) {
    uint32_t a;
    asm("{ .reg .u64 t; cvta.to.shared.u64 t, %1; cvt.u32.u64 %0, t; }" : "=r"(a) : "l"(p));
    return a;
}

__device__ __forceinline__ void mma16816(float* c, uint32_t a0, uint32_t a1, uint32_t a2,
                                         uint32_t a3, uint32_t b0, uint32_t b1) {
    asm volatile(
        "mma.sync.aligned.m16n8k16.row.col.f32.bf16.bf16.f32 "
        "{%0,%1,%2,%3},{%4,%5,%6,%7},{%8,%9},{%0,%1,%2,%3};"
        : "+f"(c[0]), "+f"(c[1]), "+f"(c[2]), "+f"(c[3])
        : "r"(a0), "r"(a1), "r"(a2), "r"(a3), "r"(b0), "r"(b1));
}

__device__ __forceinline__ void ldsm4(uint32_t& r0, uint32_t& r1, uint32_t& r2, uint32_t& r3,
                                      uint32_t a) {
    asm volatile("ldmatrix.sync.aligned.m8n8.x4.shared.b16 {%0,%1,%2,%3},[%4];"
                 : "=r"(r0), "=r"(r1), "=r"(r2), "=r"(r3) : "r"(a));
}

__device__ __forceinline__ void ldA8(uint32_t a[8], uint32_t base, int r0, int k0, int lane) {
    uint32_t addr = base + (uint32_t)(r0 + (lane & 15)) * PITCH
                  + (uint32_t)(k0 + ((lane >> 4) << 3)) * 2;
    ldsm4(a[0], a[1], a[2], a[3], addr);
    ldsm4(a[4], a[5], a[6], a[7], addr + 16 * PITCH);
}

__device__ __forceinline__ void ldB16(uint32_t b[16], uint32_t base, int n0, int k0, int lane) {
    uint32_t addr = base + (uint32_t)(n0 + ((lane >> 4) << 3) + (lane & 7)) * PITCH
                  + (uint32_t)(k0 + (((lane >> 3) & 1) << 3)) * 2;
    ldsm4(b[0],  b[1],  b[2],  b[3],  addr);
    ldsm4(b[4],  b[5],  b[6],  b[7],  addr + 16 * PITCH);
    ldsm4(b[8],  b[9],  b[10], b[11], addr + 32 * PITCH);
    ldsm4(b[12], b[13], b[14], b[15], addr + 48 * PITCH);
}

__device__ __forceinline__ void mma_pass(float (&acc)[2][8][4], const uint32_t a[8],
                                         const uint32_t b[16]) {
    #pragma unroll
    for (int mf = 0; mf < 2; mf++)
        #pragma unroll
        for (int nf = 0; nf < 8; nf++)
            mma16816(acc[mf][nf], a[mf*4], a[mf*4+1], a[mf*4+2], a[mf*4+3],
                     b[nf*2], b[nf*2+1]);
}

__device__ __forceinline__ void compute_ktile(float (&acc)[2][8][4], uint32_t aHi, uint32_t aLo,
                                              uint32_t bHi, uint32_t bLo, int wm, int wn, int lane) {
    #pragma unroll 1
    for (int ks = 0; ks < 8; ks++) {
        uint32_t ah[8], al[8], bh[16], bl[16];
        ldA8(ah, aHi, wm * 32, ks * 16, lane);
        ldA8(al, aLo, wm * 32, ks * 16, lane);
        ldB16(bh, bHi, wn * 64, ks * 16, lane);
        ldB16(bl, bLo, wn * 64, ks * 16, lane);
        mma_pass(acc, ah, bh);
        mma_pass(acc, ah, bl);
        mma_pass(acc, al, bh);
    }
}

__device__ __forceinline__ uint32_t pk2(__nv_bfloat16 a, __nv_bfloat16 b) {
    return (uint32_t)__bfloat16_as_ushort(a) | ((uint32_t)__bfloat16_as_ushort(b) << 16);
}
__device__ __forceinline__ void split2(float x, float y, uint32_t& hi, uint32_t& lo) {
    __nv_bfloat16 hx = __float2bfloat16(x), hy = __float2bfloat16(y);
    __nv_bfloat16 lx = __float2bfloat16(x - __bfloat162float(hx));
    __nv_bfloat16 ly = __float2bfloat16(y - __bfloat162float(hy));
    hi = pk2(hx, hy); lo = pk2(lx, ly);
}
__device__ __forceinline__ float2 unpk2(uint32_t u) {
    __nv_bfloat162 t = *reinterpret_cast<__nv_bfloat162*>(&u);
    return make_float2(__bfloat162float(t.x), __bfloat162float(t.y));
}

__device__ __forceinline__ void stage_a_fp32(char* sm, const float* src, int stride, int tid) {
    #pragma unroll 4
    for (int t = tid; t < 4096; t += 256) {
        int r = t >> 5, c4 = (t & 31) << 2;
        float4 v = *(const float4*)(src + (size_t)r * stride + c4);
        uint32_t h0, l0, h1, l1;
        split2(v.x, v.y, h0, l0);
        split2(v.z, v.w, h1, l1);
        uint32_t off = (uint32_t)r * PITCH + (uint32_t)c4 * 2;
        *(uint2*)(sm + off)             = make_uint2(h0, h1);
        *(uint2*)(sm + TILE_HALF + off) = make_uint2(l0, l1);
    }
}

__device__ __forceinline__ void stage_a_split(char* sm, const __nv_bfloat16* hiS,
                                              const __nv_bfloat16* loS, size_t row0,
                                              int stride, int colOff, int tid) {
    #pragma unroll 4
    for (int t = tid; t < 2048; t += 256) {
        int r = t >> 4, c8 = (t & 15) << 3;
        size_t gi = (row0 + r) * (size_t)stride + colOff + c8;
        uint32_t off = (uint32_t)r * PITCH + (uint32_t)c8 * 2;
        *(uint4*)(sm + off)             = *(const uint4*)(hiS + gi);
        *(uint4*)(sm + TILE_HALF + off) = *(const uint4*)(loS + gi);
    }
}

__device__ __forceinline__ void stage_w(char* dst, const char* src, int tid) {
    const uint4* s = (const uint4*)src;
    uint4* d = (uint4*)dst;
    #pragma unroll 4
    for (int t = tid; t < 4352; t += 256) d[t] = s[t];
}

// ---------------- weight prep ----------------
__global__ void prep_weight(const float* __restrict__ W, int K, int N, char* __restrict__ out) {
    int KC = K >> 7;
    int s = blockIdx.x;
    int kc = s % KC, nc = s / KC;
    char* base = out + (size_t)s * TILE_FULL;
    for (int t = threadIdx.x; t < 16384; t += 256) {
        int n = t >> 7, k = t & 127;
        float v = W[(size_t)(kc * 128 + k) * N + nc * 128 + n];
        __nv_bfloat16 h = __float2bfloat16(v);
        __nv_bfloat16 l = __float2bfloat16(v - __bfloat162float(h));
        uint32_t off = (uint32_t)n * PITCH + (uint32_t)k * 2;
        *(__nv_bfloat16*)(base + off) = h;
        *(__nv_bfloat16*)(base + TILE_HALF + off) = l;
    }
}

__global__ void fold_bias(const float* __restrict__ bv, const float* __restrict__ wxo,
                          const float* __restrict__ bxo, float* __restrict__ bvx) {
    int n = threadIdx.x;
    float s = bxo[n];
    for (int k = 0; k < XD_; ++k) s += bv[k] * wxo[k * XD_ + n];
    bvx[n] = s;
}

// ================ fused edge attention: e -> he (split) ================
#define FA_A   0
#define FA_B   69632
#define FA_C   139264
#define FA_SM  208896
#define FA_BYTES (208896 + 7168)

__global__ void __launch_bounds__(256, 1) edge_attn_kernel(
    const float* __restrict__ e, const float* __restrict__ Qs, const float* __restrict__ Km,
    const char* __restrict__ wemP, const char* __restrict__ weaP, const char* __restrict__ weoP,
    const float* __restrict__ bem, const float* __restrict__ bea, const float* __restrict__ beo,
    const float* __restrict__ gne, const float* __restrict__ bne,
    __nv_bfloat16* __restrict__ heHi, __nv_bfloat16* __restrict__ heLo)
{
    extern __shared__ char sm[];
    const int tid = threadIdx.x;
    const int lane = tid & 31, w = tid >> 5;
    const int wm = w & 3, wn = w >> 2;
    const int g = lane >> 2, q = lane & 3;
    const int blk = blockIdx.x;
    const size_t row0 = (size_t)blk * 128;
    const int b = blk >> 7, i = blk & 127;

    uint32_t smB = smem_u32(sm);
    float* qS   = (float*)(sm + FA_SM);            // 256
    float* bemS = qS + 256;                         // 256
    float* beaS = bemS + 256;                       // 256
    float* beoS = beaS + 256;                       // 128
    float* gneS = beoS + 128;                       // 128
    float* bneS = gneS + 128;                       // 128
    float* red  = bneS + 128;                       // 256
    float* red2 = red + 256;                        // 256
    float* kmS  = (float*)(sm + FA_B);              // Km staged after MMAs

    stage_a_fp32(sm + FA_A, e + row0 * ED_, ED_, tid);
    qS[tid]   = Qs[((size_t)(b * NN + i)) * XD_ + tid];
    bemS[tid] = bem[tid];
    beaS[tid] = bea[tid];
    if (tid < 128) { beoS[tid] = beo[tid]; gneS[tid] = gne[tid]; bneS[tid] = bne[tid]; }

    const uint32_t aHi = smB + FA_A, aLo = smB + FA_A + TILE_HALF;
    const uint32_t bHi = smB + FA_B, bLo = smB + FA_B + TILE_HALF;
    const uint32_t cHi = smB + FA_C, cLo = smB + FA_C + TILE_HALF;

    float accNE[2][8][4] = {};

    #pragma unroll 1
    for (int nc = 0; nc < 2; nc++) {
        // ---- E2 = e @ wea[nc] + bea -> split into C
        __syncthreads();
        stage_w(sm + FA_B, weaP + (size_t)nc * TILE_FULL, tid);
        __syncthreads();
        {
            float acc[2][8][4] = {};
            compute_ktile(acc, aHi, aLo, bHi, bLo, wm, wn, lane);
            #pragma unroll
            for (int mf = 0; mf < 2; mf++)
            #pragma unroll
            for (int h = 0; h < 2; h++) {
                int r = wm * 32 + mf * 16 + h * 8 + g;
                #pragma unroll
                for (int nf = 0; nf < 8; nf++) {
                    int cl = wn * 64 + nf * 8 + q * 2;
                    int cg = nc * 128 + cl;
                    uint32_t hi, lo;
                    split2(acc[mf][nf][h*2] + beaS[cg], acc[mf][nf][h*2+1] + beaS[cg+1], hi, lo);
                    uint32_t off = (uint32_t)r * PITCH + (uint32_t)cl * 2;
                    *(uint32_t*)(sm + FA_C + off)             = hi;
                    *(uint32_t*)(sm + FA_C + TILE_HALF + off) = lo;
                }
            }
        }
        // ---- E1 = e @ wem[nc]
        __syncthreads();
        stage_w(sm + FA_B, wemP + (size_t)nc * TILE_FULL, tid);
        __syncthreads();
        float acc[2][8][4] = {};
        compute_ktile(acc, aHi, aLo, bHi, bLo, wm, wn, lane);
        // ---- stage Km chunk (fp32, pitch 132) into B region
        __syncthreads();
        #pragma unroll 4
        for (int t = tid; t < 4096; t += 256) {
            int r = t >> 5, c4 = (t & 31) << 2;
            float4 v = *(const float4*)(Km + ((size_t)(b * NN + r)) * XD_ + nc * 128 + c4);
            *(float4*)(kmS + r * 132 + c4) = v;
        }
        __syncthreads();
        // ---- Y = q*km*(E1+bem+1) + E2, in-place split back into C
        #pragma unroll
        for (int mf = 0; mf < 2; mf++)
        #pragma unroll
        for (int h = 0; h < 2; h++) {
            int r = wm * 32 + mf * 16 + h * 8 + g;
            #pragma unroll
            for (int nf = 0; nf < 8; nf++) {
                int cl = wn * 64 + nf * 8 + q * 2;
                int cg = nc * 128 + cl;
                uint32_t off = (uint32_t)r * PITCH + (uint32_t)cl * 2;
                float2 e2h = unpk2(*(uint32_t*)(sm + FA_C + off));
                float2 e2l = unpk2(*(uint32_t*)(sm + FA_C + TILE_HALF + off));
                float e1a = acc[mf][nf][h*2]   + bemS[cg]   + 1.f;
                float e1b = acc[mf][nf][h*2+1] + bemS[cg+1] + 1.f;
                float y0 = qS[cg]   * kmS[r*132 + cl]   * e1a + (e2h.x + e2l.x);
                float y1 = qS[cg+1] * kmS[r*132 + cl+1] * e1b + (e2h.y + e2l.y);
                uint32_t hi, lo;
                split2(y0, y1, hi, lo);
                *(uint32_t*)(sm + FA_C + off)             = hi;
                *(uint32_t*)(sm + FA_C + TILE_HALF + off) = lo;
            }
        }
        // ---- newE += Y @ weo[nc]
        __syncthreads();
        stage_w(sm + FA_B, weoP + (size_t)nc * TILE_FULL, tid);
        __syncthreads();
        compute_ktile(accNE, cHi, cLo, bHi, bLo, wm, wn, lane);
    }

    // ---- epilogue: he = LN(e + newE + beo) * gne + bne -> split to gmem
    #pragma unroll
    for (int mf = 0; mf < 2; mf++)
    #pragma unroll
    for (int h = 0; h < 2; h++) {
        int r = wm * 32 + mf * 16 + h * 8 + g;
        #pragma unroll
        for (int nf = 0; nf < 8; nf++) {
            int cl = wn * 64 + nf * 8 + q * 2;
            uint32_t off = (uint32_t)r * PITCH + (uint32_t)cl * 2;
            float2 eh = unpk2(*(uint32_t*)(sm + FA_A + off));
            float2 el = unpk2(*(uint32_t*)(sm + FA_A + TILE_HALF + off));
            accNE[mf][nf][h*2+0] += beoS[cl]   + eh.x + el.x;
            accNE[mf][nf][h*2+1] += beoS[cl+1] + eh.y + el.y;
        }
    }
    float mean[2][2], rstd[2][2];
    #pragma unroll
    for (int mf = 0; mf < 2; mf++)
    #pragma unroll
    for (int h = 0; h < 2; h++) {
        float s = 0.f;
        #pragma unroll
        for (int nf = 0; nf < 8; nf++) s += accNE[mf][nf][h*2] + accNE[mf][nf][h*2+1];
        s += __shfl_xor_sync(0xffffffffu, s, 1);
        s += __shfl_xor_sync(0xffffffffu, s, 2);
        if (q == 0) red[wn * 128 + wm * 32 + mf * 16 + h * 8 + g] = s;
    }
    __syncthreads();
    #pragma unroll
    for (int mf = 0; mf < 2; mf++)
    #pragma unroll
    for (int h = 0; h < 2; h++) {
        int r = wm * 32 + mf * 16 + h * 8 + g;
        mean[mf][h] = (red[r] + red[128 + r]) * (1.f / 128.f);
        float s = 0.f;
        #pragma unroll
        for (int nf = 0; nf < 8; nf++) {
            float d0 = accNE[mf][nf][h*2]   - mean[mf][h];
            float d1 = accNE[mf][nf][h*2+1] - mean[mf][h];
            s += d0 * d0 + d1 * d1;
        }
        s += __shfl_xor_sync(0xffffffffu, s, 1);
        s += __shfl_xor_sync(0xffffffffu, s, 2);
        if (q == 0) red2[wn * 128 + r] = s;
    }
    __syncthreads();
    #pragma unroll
    for (int mf = 0; mf < 2; mf++)
    #pragma unroll
    for (int h = 0; h < 2; h++) {
        int r = wm * 32 + mf * 16 + h * 8 + g;
        rstd[mf][h] = rsqrtf((red2[r] + red2[128 + r]) * (1.f / 128.f) + 1e-5f);
        #pragma unroll
        for (int nf = 0; nf < 8; nf++) {
            int cl = wn * 64 + nf * 8 + q * 2;
            float o0 = (accNE[mf][nf][h*2]   - mean[mf][h]) * rstd[mf][h] * gneS[cl]   + bneS[cl];
            float o1 = (accNE[mf][nf][h*2+1] - mean[mf][h]) * rstd[mf][h] * gneS[cl+1] + bneS[cl+1];
            uint32_t hi, lo;
            split2(o0, o1, hi, lo);
            size_t oi = ((row0 + r) * ED_ + cl) * 2;
            *(uint32_t*)((char*)heHi + oi) = hi;
            *(uint32_t*)((char*)heLo + oi) = lo;
        }
    }
}

// ================ fused edge FF: he -> e_out ================
#define FB_A   0
#define FB_B   69632
#define FB_C   139264
#define FB_SM  208896
#define FB_BYTES (208896 + 6144)

__global__ void __launch_bounds__(256, 1) edge_ff_kernel(
    const __nv_bfloat16* __restrict__ heHi, const __nv_bfloat16* __restrict__ heLo,
    const float* __restrict__ e,
    const char* __restrict__ we1P, const char* __restrict__ we2P,
    const float* __restrict__ be1, const float* __restrict__ be2,
    const float* __restrict__ gne, const float* __restrict__ bne,
    float* __restrict__ e_out)
{
    extern __shared__ char sm[];
    const int tid = threadIdx.x;
    const int lane = tid & 31, w = tid >> 5;
    const int wm = w & 3, wn = w >> 2;
    const int g = lane >> 2, q = lane & 3;
    const size_t row0 = (size_t)blockIdx.x * 128;

    uint32_t smB = smem_u32(sm);
    float* be1S = (float*)(sm + FB_SM);    // 512
    float* be2S = be1S + 512;              // 128
    float* gneS = be2S + 128;              // 128
    float* bneS = gneS + 128;              // 128
    float* red  = bneS + 128;              // 256
    float* red2 = red + 256;               // 256

    stage_a_split(sm + FB_A, heHi, heLo, row0, ED_, 0, tid);
    for (int t = tid; t < 512; t += 256) be1S[t] = be1[t];
    if (tid < 128) { be2S[tid] = be2[tid]; gneS[tid] = gne[tid]; bneS[tid] = bne[tid]; }

    const uint32_t aHi = smB + FB_A, aLo = smB + FB_A + TILE_HALF;
    const uint32_t bHi = smB + FB_B, bLo = smB + FB_B + TILE_HALF;
    const uint32_t cHi = smB + FB_C, cLo = smB + FB_C + TILE_HALF;

    float accH2[2][8][4] = {};

    #pragma unroll 1
    for (int p = 0; p < 4; p++) {
        // h1 chunk = relu(he @ we1[p] + be1[p]) -> split into C
        __syncthreads();
        stage_w(sm + FB_B, we1P + (size_t)p * TILE_FULL, tid);
        __syncthreads();
        float acc[2][8][4] = {};
        compute_ktile(acc, aHi, aLo, bHi, bLo, wm, wn, lane);
        #pragma unroll
        for (int mf = 0; mf < 2; mf++)
        #pragma unroll
        for (int h = 0; h < 2; h++) {
            int r = wm * 32 + mf * 16 + h * 8 + g;
            #pragma unroll
            for (int nf = 0; nf < 8; nf++) {
                int cl = wn * 64 + nf * 8 + q * 2;
                int cgl = p * 128 + cl;
                float o0 = fmaxf(acc[mf][nf][h*2]   + be1S[cgl],   0.f);
                float o1 = fmaxf(acc[mf][nf][h*2+1] + be1S[cgl+1], 0.f);
                uint32_t hi, lo;
                split2(o0, o1, hi, lo);
                uint32_t off = (uint32_t)r * PITCH + (uint32_t)cl * 2;
                *(uint32_t*)(sm + FB_C + off)             = hi;
                *(uint32_t*)(sm + FB_C + TILE_HALF + off) = lo;
            }
        }
        // h2 += chunk @ we2[p]
        __syncthreads();
        stage_w(sm + FB_B, we2P + (size_t)p * TILE_FULL, tid);
        __syncthreads();
        compute_ktile(accH2, cHi, cLo, bHi, bLo, wm, wn, lane);
    }

    // epilogue: e_out = LN(e + h2 + be2) * gne + bne
    #pragma unroll
    for (int mf = 0; mf < 2; mf++)
    #pragma unroll
    for (int h = 0; h < 2; h++) {
        int r = wm * 32 + mf * 16 + h * 8 + g;
        #pragma unroll
        for (int nf = 0; nf < 8; nf++) {
            int cl = wn * 64 + nf * 8 + q * 2;
            float2 ev = *(const float2*)(e + (row0 + r) * ED_ + cl);
            accH2[mf][nf][h*2+0] += be2S[cl]   + ev.x;
            accH2[mf][nf][h*2+1] += be2S[cl+1] + ev.y;
        }
    }
    float mean[2][2], rstd[2][2];
    #pragma unroll
    for (int mf = 0; mf < 2; mf++)
    #pragma unroll
    for (int h = 0; h < 2; h++) {
        float s = 0.f;
        #pragma unroll
        for (int nf = 0; nf < 8; nf++) s += accH2[mf][nf][h*2] + accH2[mf][nf][h*2+1];
        s += __shfl_xor_sync(0xffffffffu, s, 1);
        s += __shfl_xor_sync(0xffffffffu, s, 2);
        if (q == 0) red[wn * 128 + wm * 32 + mf * 16 + h * 8 + g] = s;
    }
    __syncthreads();
    #pragma unroll
    for (int mf = 0; mf < 2; mf++)
    #pragma unroll
    for (int h = 0; h < 2; h++) {
        int r = wm * 32 + mf * 16 + h * 8 + g;
        mean[mf][h] = (red[r] + red[128 + r]) * (1.f / 128.f);
        float s = 0.f;
        #pragma unroll
        for (int nf = 0; nf < 8; nf++) {
            float d0 = accH2[mf][nf][h*2]   - mean[mf][h];
            float d1 = accH2[mf][nf][h*2+1] - mean[mf][h];
            s += d0 * d0 + d1 * d1;
        }
        s += __shfl_xor_sync(0xffffffffu, s, 1);
        s += __shfl_xor_sync(0xffffffffu, s, 2);
        if (q == 0) red2[wn * 128 + r] = s;
    }
    __syncthreads();
    #pragma unroll
    for (int mf = 0; mf < 2; mf++)
    #pragma unroll
    for (int h = 0; h < 2; h++) {
        int r = wm * 32 + mf * 16 + h * 8 + g;
        rstd[mf][h] = rsqrtf((red2[r] + red2[128 + r]) * (1.f / 128.f) + 1e-5f);
        #pragma unroll
        for (int nf = 0; nf < 8; nf++) {
            int cl = wn * 64 + nf * 8 + q * 2;
            float o0 = (accH2[mf][nf][h*2]   - mean[mf][h]) * rstd[mf][h] * gneS[cl]   + bneS[cl];
            float o1 = (accH2[mf][nf][h*2+1] - mean[mf][h]) * rstd[mf][h] * gneS[cl+1] + bneS[cl+1];
            *(float2*)(e_out + (row0 + r) * ED_ + cl) = make_float2(o0, o1);
        }
    }
}

// ---------------- node-side SIMT GEMM + LN ----------------
template<bool RELU>
__global__ void __launch_bounds__(256) gemm_kernel(
    const float* __restrict__ A, const float* __restrict__ W,
    const float* __restrict__ bias, float* __restrict__ C,
    int M, int N, int K, float alpha)
{
    __shared__ __align__(16) float aS[64][68];
    __shared__ __align__(16) float wS[64][68];
    const int tid = threadIdx.x;
    const int tx  = tid & 15;
    const int ty  = tid >> 4;
    const size_t row0 = (size_t)blockIdx.y * 64;
    const int    col0 = blockIdx.x * 64;
    float acc[4][4] = {};
    for (int k0 = 0; k0 < K; k0 += 64) {
        #pragma unroll
        for (int t = tid; t < 1024; t += 256) {
            int r = t >> 4, c4 = (t & 15) << 2;
            float4 av = *(const float4*)(A + (row0 + r) * K + k0 + c4);
            aS[r][c4+0]=av.x; aS[r][c4+1]=av.y; aS[r][c4+2]=av.z; aS[r][c4+3]=av.w;
            float4 wv = *(const float4*)(W + (size_t)(k0 + r) * N + col0 + c4);
            wS[r][c4+0]=wv.x; wS[r][c4+1]=wv.y; wS[r][c4+2]=wv.z; wS[r][c4+3]=wv.w;
        }
        __syncthreads();
        #pragma unroll 16
        for (int k = 0; k < 64; ++k) {
            float a0=aS[ty*4+0][k], a1=aS[ty*4+1][k], a2=aS[ty*4+2][k], a3=aS[ty*4+3][k];
            float4 bv = *(const float4*)&wS[k][tx*4];
            acc[0][0]+=a0*bv.x; acc[0][1]+=a0*bv.y; acc[0][2]+=a0*bv.z; acc[0][3]+=a0*bv.w;
            acc[1][0]+=a1*bv.x; acc[1][1]+=a1*bv.y; acc[1][2]+=a1*bv.z; acc[1][3]+=a1*bv.w;
            acc[2][0]+=a2*bv.x; acc[2][1]+=a2*bv.y; acc[2][2]+=a2*bv.z; acc[2][3]+=a2*bv.w;
            acc[3][0]+=a3*bv.x; acc[3][1]+=a3*bv.y; acc[3][2]+=a3*bv.z; acc[3][3]+=a3*bv.w;
        }
        __syncthreads();
    }
    const int c = col0 + tx * 4;
    float b0=bias[c+0], b1=bias[c+1], b2=bias[c+2], b3=bias[c+3];
    #pragma unroll
    for (int m = 0; m < 4; ++m) {
        float4 o;
        o.x = alpha*(acc[m][0]+b0); o.y = alpha*(acc[m][1]+b1);
        o.z = alpha*(acc[m][2]+b2); o.w = alpha*(acc[m][3]+b3);
        if (RELU) { o.x=fmaxf(o.x,0.f); o.y=fmaxf(o.y,0.f); o.z=fmaxf(o.z,0.f); o.w=fmaxf(o.w,0.f); }
        *(float4*)(C + (row0 + ty*4 + m) * N + c) = o;
    }
}

__global__ void ln_kernel(const float* __restrict__ A, const float* __restrict__ Bv,
                          const float* __restrict__ g, const float* __restrict__ be,
                          float* __restrict__ out)
{
    __shared__ float red[8];
    const int D = blockDim.x;
    const size_t base = (size_t)blockIdx.x * D + threadIdx.x;
    const int lane = threadIdx.x & 31;
    const int w    = threadIdx.x >> 5;
    const int nw   = D >> 5;
    float v = A[base] + Bv[base];
    float s = v;
    #pragma unroll
    for (int o = 16; o; o >>= 1) s += __shfl_xor_sync(0xffffffffu, s, o);
    if (lane == 0) red[w] = s;
    __syncthreads();
    float tot = 0.f;
    for (int ww = 0; ww < nw; ++ww) tot += red[ww];
    float mean = tot / (float)D;
    float d = v - mean;
    __syncthreads();
    float s2 = d * d;
    #pragma unroll
    for (int o = 16; o; o >>= 1) s2 += __shfl_xor_sync(0xffffffffu, s2, o);
    if (lane == 0) red[w] = s2;
    __syncthreads();
    float tot2 = 0.f;
    for (int ww = 0; ww < nw; ++ww) tot2 += red[ww];
    float var = tot2 / (float)D;
    out[base] = d * rsqrtf(var + 1e-5f) * g[threadIdx.x] + be[threadIdx.x];
}

// ---------------- launcher ----------------
extern "C" void kernel_launch(void* const* d_in, const int* in_sizes, int n_in,
                              void* d_out, int out_size)
{
    const float* x   = (const float*)d_in[0];
    const float* e   = (const float*)d_in[1];
    const float* wq  = (const float*)d_in[2];
    const float* wk  = (const float*)d_in[3];
    const float* wv  = (const float*)d_in[4];
    const float* wem = (const float*)d_in[5];
    const float* wea = (const float*)d_in[6];
    const float* wxo = (const float*)d_in[7];
    const float* weo = (const float*)d_in[8];
    const float* wx1 = (const float*)d_in[9];
    const float* wx2 = (const float*)d_in[10];
    const float* we1 = (const float*)d_in[11];
    const float* we2 = (const float*)d_in[12];
    const float* bq  = (const float*)d_in[13];
    const float* bk  = (const float*)d_in[14];
    const float* bv  = (const float*)d_in[15];
    const float* bem = (const float*)d_in[16];
    const float* bea = (const float*)d_in[17];
    const float* bxo = (const float*)d_in[18];
    const float* beo = (const float*)d_in[19];
    const float* bx1 = (const float*)d_in[20];
    const float* bx2 = (const float*)d_in[21];
    const float* be1 = (const float*)d_in[22];
    const float* be2 = (const float*)d_in[23];
    const float* gnx = (const float*)d_in[24];
    const float* bnx = (const float*)d_in[25];
    const float* gne = (const float*)d_in[26];
    const float* bne = (const float*)d_in[27];

    float* x_out = (float*)d_out;
    float* e_out = (float*)d_out + (size_t)ROWS_X * XD_;

    float *Q, *Km, *newX, *hx, *h1x, *h2x, *wvx, *bvx, *zero;
    __nv_bfloat16 *heHi, *heLo;
    char *wemP, *weaP, *weoP, *we1P, *we2P;
    cudaGetSymbolAddress((void**)&Q,    g_Q);
    cudaGetSymbolAddress((void**)&Km,   g_Km);
    cudaGetSymbolAddress((void**)&newX, g_newX);
    cudaGetSymbolAddress((void**)&hx,   g_hx);
    cudaGetSymbolAddress((void**)&h1x,  g_h1x);
    cudaGetSymbolAddress((void**)&h2x,  g_h2x);
    cudaGetSymbolAddress((void**)&wvx,  g_wvx);
    cudaGetSymbolAddress((void**)&bvx,  g_bvx);
    cudaGetSymbolAddress((void**)&zero, g_zero);
    cudaGetSymbolAddress((void**)&heHi, g_heHi);
    cudaGetSymbolAddress((void**)&heLo, g_heLo);
    cudaGetSymbolAddress((void**)&wemP, g_wemP);
    cudaGetSymbolAddress((void**)&weaP, g_weaP);
    cudaGetSymbolAddress((void**)&weoP, g_weoP);
    cudaGetSymbolAddress((void**)&we1P, g_we1P);
    cudaGetSymbolAddress((void**)&we2P, g_we2P);

    cudaFuncSetAttribute(edge_attn_kernel, cudaFuncAttributeMaxDynamicSharedMemorySize, FA_BYTES);
    cudaFuncSetAttribute(edge_ff_kernel,   cudaFuncAttributeMaxDynamicSharedMemorySize, FB_BYTES);

    dim3 blk(256);
    auto grid_of = [](int M, int N) { return dim3((unsigned)(N/64), (unsigned)(M/64)); };

    prep_weight<<<2, 256>>>(wem, 128, 256, wemP);
    prep_weight<<<2, 256>>>(wea, 128, 256, weaP);
    prep_weight<<<2, 256>>>(weo, 256, 128, weoP);
    prep_weight<<<4, 256>>>(we1, 128, 512, we1P);
    prep_weight<<<4, 256>>>(we2, 512, 128, we2P);

    // node side (softmax collapses: wV == V; fold wv@wxo)
    gemm_kernel<false><<<grid_of(XD_, XD_), blk>>>(wv, wxo, zero, wvx, XD_, XD_, XD_, 1.f);
    fold_bias<<<1, 256>>>(bv, wxo, bxo, bvx);
    gemm_kernel<false><<<grid_of(ROWS_X, XD_), blk>>>(x, wq, bq, Q,  ROWS_X, XD_, XD_, INV_SQRT_DF);
    gemm_kernel<false><<<grid_of(ROWS_X, XD_), blk>>>(x, wk, bk, Km, ROWS_X, XD_, XD_, 1.f);
    gemm_kernel<false><<<grid_of(ROWS_X, XD_), blk>>>(x, wvx, bvx, newX, ROWS_X, XD_, XD_, 1.f);
    ln_kernel<<<ROWS_X, XD_>>>(x, newX, gnx, bnx, hx);
    gemm_kernel<true ><<<grid_of(ROWS_X, FFX), blk>>>(hx,  wx1, bx1, h1x, ROWS_X, FFX, XD_, 1.f);
    gemm_kernel<false><<<grid_of(ROWS_X, XD_), blk>>>(h1x, wx2, bx2, h2x, ROWS_X, XD_, FFX, 1.f);
    ln_kernel<<<ROWS_X, XD_>>>(x, h2x, gnx, bnx, x_out);

    // edge side: two fused tensor-core kernels (Y and h1 never touch HBM)
    edge_attn_kernel<<<ROWS_E / 128, blk, FA_BYTES>>>(
        e, Q, Km, wemP, weaP, weoP, bem, bea, beo, gne, bne, heHi, heLo);
    edge_ff_kernel<<<ROWS_E / 128, blk, FB_BYTES>>>(
        heHi, heLo, e, we1P, we2P, be1, be2, gne, bne, e_out);
}

// round 6
// speedup vs baseline: 2.5649x; 1.2605x over previous
#include <cuda_runtime.h>
#include <cuda_bf16.h>
#include <math.h>
#include <stdint.h>

#define BB  8
#define NN  128
#define XD_ 256
#define ED_ 128
#define FFX 1024
#define FFE 512
#define ROWS_X (BB*NN)
#define ROWS_E (BB*NN*NN)
#define INV_SQRT_DF 0.17677669529663687f

#define PITCH     272           // bytes per bf16 tile row (136 bf16)
#define TILE_HALF 34816         // 128 * 272 (one bf16 128x128 tile)
#define TILE_FULL 69632         // hi + lo (weights only)

// ---------------- scratch ----------------
__device__ float g_Q   [ROWS_X * XD_];
__device__ float g_Km  [ROWS_X * XD_];
__device__ float g_newX[ROWS_X * XD_];
__device__ float g_hx  [ROWS_X * XD_];
__device__ float g_h1x [ROWS_X * FFX];
__device__ float g_h2x [ROWS_X * XD_];
__device__ float g_wvx [XD_ * XD_];
__device__ float g_bvx [XD_];
__device__ float g_zero[FFX];
__device__ __nv_bfloat16 g_he[(size_t)ROWS_E * ED_];
__device__ __align__(16) char g_wemP[2 * TILE_FULL];
__device__ __align__(16) char g_weaP[2 * TILE_FULL];
__device__ __align__(16) char g_weoP[2 * TILE_FULL];
__device__ __align__(16) char g_we1P[4 * TILE_FULL];
__device__ __align__(16) char g_we2P[4 * TILE_FULL];

// ---------------- helpers ----------------
__device__ __forceinline__ uint32_t smem_u32(const void* p) {
    uint32_t a;
    asm("{ .reg .u64 t; cvta.to.shared.u64 t, %1; cvt.u32.u64 %0, t; }" : "=r"(a) : "l"(p));
    return a;
}

__device__ __forceinline__ void mma16816(float* c, uint32_t a0, uint32_t a1, uint32_t a2,
                                         uint32_t a3, uint32_t b0, uint32_t b1) {
    asm volatile(
        "mma.sync.aligned.m16n8k16.row.col.f32.bf16.bf16.f32 "
        "{%0,%1,%2,%3},{%4,%5,%6,%7},{%8,%9},{%0,%1,%2,%3};"
        : "+f"(c[0]), "+f"(c[1]), "+f"(c[2]), "+f"(c[3])
        : "r"(a0), "r"(a1), "r"(a2), "r"(a3), "r"(b0), "r"(b1));
}

__device__ __forceinline__ void ldsm4(uint32_t& r0, uint32_t& r1, uint32_t& r2, uint32_t& r3,
                                      uint32_t a) {
    asm volatile("ldmatrix.sync.aligned.m8n8.x4.shared.b16 {%0,%1,%2,%3},[%4];"
                 : "=r"(r0), "=r"(r1), "=r"(r2), "=r"(r3) : "r"(a));
}

__device__ __forceinline__ void ldA8(uint32_t a[8], uint32_t base, int r0, int k0, int lane) {
    uint32_t addr = base + (uint32_t)(r0 + (lane & 15)) * PITCH
                  + (uint32_t)(k0 + ((lane >> 4) << 3)) * 2;
    ldsm4(a[0], a[1], a[2], a[3], addr);
    ldsm4(a[4], a[5], a[6], a[7], addr + 16 * PITCH);
}

__device__ __forceinline__ void ldB16(uint32_t b[16], uint32_t base, int n0, int k0, int lane) {
    uint32_t addr = base + (uint32_t)(n0 + ((lane >> 4) << 3) + (lane & 7)) * PITCH
                  + (uint32_t)(k0 + (((lane >> 3) & 1) << 3)) * 2;
    ldsm4(b[0],  b[1],  b[2],  b[3],  addr);
    ldsm4(b[4],  b[5],  b[6],  b[7],  addr + 16 * PITCH);
    ldsm4(b[8],  b[9],  b[10], b[11], addr + 32 * PITCH);
    ldsm4(b[12], b[13], b[14], b[15], addr + 48 * PITCH);
}

__device__ __forceinline__ void mma_pass(float (&acc)[2][8][4], const uint32_t a[8],
                                         const uint32_t b[16]) {
    #pragma unroll
    for (int mf = 0; mf < 2; mf++)
        #pragma unroll
        for (int nf = 0; nf < 8; nf++)
            mma16816(acc[mf][nf], a[mf*4], a[mf*4+1], a[mf*4+2], a[mf*4+3],
                     b[nf*2], b[nf*2+1]);
}

// 2-pass split: A bf16, B split hi/lo. D = A*Bh + A*Bl
__device__ __forceinline__ void compute_ktile(float (&acc)[2][8][4], uint32_t aB,
                                              uint32_t bHi, uint32_t bLo, int wm, int wn, int lane) {
    #pragma unroll 1
    for (int ks = 0; ks < 8; ks++) {
        uint32_t ah[8], bh[16], bl[16];
        ldA8(ah, aB, wm * 32, ks * 16, lane);
        ldB16(bh, bHi, wn * 64, ks * 16, lane);
        ldB16(bl, bLo, wn * 64, ks * 16, lane);
        mma_pass(acc, ah, bh);
        mma_pass(acc, ah, bl);
    }
}

__device__ __forceinline__ uint32_t pkf2(float x, float y) {
    __nv_bfloat162 t = __floats2bfloat162_rn(x, y);
    return *reinterpret_cast<uint32_t*>(&t);
}
__device__ __forceinline__ float2 unpk2(uint32_t u) {
    __nv_bfloat162 t = *reinterpret_cast<__nv_bfloat162*>(&u);
    return make_float2(__bfloat162float(t.x), __bfloat162float(t.y));
}

// stage 128x128 fp32 -> single bf16 pitched tile
__device__ __forceinline__ void stage_a_fp32(char* sm, const float* src, int stride, int tid) {
    #pragma unroll 4
    for (int t = tid; t < 4096; t += 256) {
        int r = t >> 5, c4 = (t & 31) << 2;
        float4 v = *(const float4*)(src + (size_t)r * stride + c4);
        uint32_t p0 = pkf2(v.x, v.y);
        uint32_t p1 = pkf2(v.z, v.w);
        *(uint2*)(sm + (uint32_t)r * PITCH + (uint32_t)c4 * 2) = make_uint2(p0, p1);
    }
}

// stage 128x128 bf16 gmem tile -> pitched smem
__device__ __forceinline__ void stage_a_bf16(char* sm, const __nv_bfloat16* src, size_t row0,
                                             int stride, int tid) {
    #pragma unroll 4
    for (int t = tid; t < 2048; t += 256) {
        int r = t >> 4, c8 = (t & 15) << 3;
        *(uint4*)(sm + (uint32_t)r * PITCH + (uint32_t)c8 * 2) =
            *(const uint4*)(src + (row0 + r) * (size_t)stride + c8);
    }
}

// copy a prepped weight tile (hi+lo, 69632 B) gmem -> smem
__device__ __forceinline__ void stage_w(char* dst, const char* src, int tid) {
    const uint4* s = (const uint4*)src;
    uint4* d = (uint4*)dst;
    #pragma unroll 4
    for (int t = tid; t < 4352; t += 256) d[t] = s[t];
}

// ---------------- weight prep ----------------
__global__ void prep_weight(const float* __restrict__ W, int K, int N, char* __restrict__ out) {
    int KC = K >> 7;
    int s = blockIdx.x;
    int kc = s % KC, nc = s / KC;
    char* base = out + (size_t)s * TILE_FULL;
    for (int t = threadIdx.x; t < 16384; t += 256) {
        int n = t >> 7, k = t & 127;
        float v = W[(size_t)(kc * 128 + k) * N + nc * 128 + n];
        __nv_bfloat16 h = __float2bfloat16(v);
        __nv_bfloat16 l = __float2bfloat16(v - __bfloat162float(h));
        uint32_t off = (uint32_t)n * PITCH + (uint32_t)k * 2;
        *(__nv_bfloat16*)(base + off) = h;
        *(__nv_bfloat16*)(base + TILE_HALF + off) = l;
    }
}

__global__ void fold_bias(const float* __restrict__ bv, const float* __restrict__ wxo,
                          const float* __restrict__ bxo, float* __restrict__ bvx) {
    int n = threadIdx.x;
    float s = bxo[n];
    for (int k = 0; k < XD_; ++k) s += bv[k] * wxo[k * XD_ + n];
    bvx[n] = s;
}

// ================ fused edge attention: e -> he (bf16) ================
#define FA_A   0
#define FA_B   34816
#define FA_C   104448
#define FA_SM  139264
#define FA_BYTES (139264 + 6656)

__global__ void __launch_bounds__(256, 1) edge_attn_kernel(
    const float* __restrict__ e, const float* __restrict__ Qs, const float* __restrict__ Km,
    const char* __restrict__ wemP, const char* __restrict__ weaP, const char* __restrict__ weoP,
    const float* __restrict__ bem, const float* __restrict__ bea, const float* __restrict__ beo,
    const float* __restrict__ gne, const float* __restrict__ bne,
    __nv_bfloat16* __restrict__ he)
{
    extern __shared__ char sm[];
    const int tid = threadIdx.x;
    const int lane = tid & 31, w = tid >> 5;
    const int wm = w & 3, wn = w >> 2;
    const int g = lane >> 2, q = lane & 3;
    const int blk = blockIdx.x;
    const size_t row0 = (size_t)blk * 128;
    const int b = blk >> 7, i = blk & 127;

    uint32_t smB = smem_u32(sm);
    float* qS   = (float*)(sm + FA_SM);            // 256
    float* bemS = qS + 256;                         // 256
    float* beaS = bemS + 256;                       // 256
    float* beoS = beaS + 256;                       // 128
    float* gneS = beoS + 128;                       // 128
    float* bneS = gneS + 128;                       // 128
    float* red  = bneS + 128;                       // 256
    float* red2 = red + 256;                        // 256
    float* kmS  = (float*)(sm + FA_B);              // Km staged into B region

    stage_a_fp32(sm + FA_A, e + row0 * ED_, ED_, tid);
    qS[tid]   = Qs[((size_t)(b * NN + i)) * XD_ + tid];
    bemS[tid] = bem[tid];
    beaS[tid] = bea[tid];
    if (tid < 128) { beoS[tid] = beo[tid]; gneS[tid] = gne[tid]; bneS[tid] = bne[tid]; }

    const uint32_t aB  = smB + FA_A;
    const uint32_t bHi = smB + FA_B, bLo = smB + FA_B + TILE_HALF;
    const uint32_t cB  = smB + FA_C;

    float accNE[2][8][4] = {};

    #pragma unroll 1
    for (int nc = 0; nc < 2; nc++) {
        // ---- E2 = e @ wea[nc] + bea -> bf16 into C
        __syncthreads();
        stage_w(sm + FA_B, weaP + (size_t)nc * TILE_FULL, tid);
        __syncthreads();
        {
            float acc[2][8][4] = {};
            compute_ktile(acc, aB, bHi, bLo, wm, wn, lane);
            #pragma unroll
            for (int mf = 0; mf < 2; mf++)
            #pragma unroll
            for (int h = 0; h < 2; h++) {
                int r = wm * 32 + mf * 16 + h * 8 + g;
                #pragma unroll
                for (int nf = 0; nf < 8; nf++) {
                    int cl = wn * 64 + nf * 8 + q * 2;
                    int cg = nc * 128 + cl;
                    *(uint32_t*)(sm + FA_C + (uint32_t)r * PITCH + (uint32_t)cl * 2) =
                        pkf2(acc[mf][nf][h*2] + beaS[cg], acc[mf][nf][h*2+1] + beaS[cg+1]);
                }
            }
        }
        // ---- E1 = e @ wem[nc]
        __syncthreads();
        stage_w(sm + FA_B, wemP + (size_t)nc * TILE_FULL, tid);
        __syncthreads();
        float acc[2][8][4] = {};
        compute_ktile(acc, aB, bHi, bLo, wm, wn, lane);
        // ---- stage Km chunk (fp32, pitch 132) into B region
        __syncthreads();
        #pragma unroll 4
        for (int t = tid; t < 4096; t += 256) {
            int r = t >> 5, c4 = (t & 31) << 2;
            float4 v = *(const float4*)(Km + ((size_t)(b * NN + r)) * XD_ + nc * 128 + c4);
            *(float4*)(kmS + r * 132 + c4) = v;
        }
        __syncthreads();
        // ---- Y = q*km*(E1+bem+1) + E2, in-place bf16 into C
        #pragma unroll
        for (int mf = 0; mf < 2; mf++)
        #pragma unroll
        for (int h = 0; h < 2; h++) {
            int r = wm * 32 + mf * 16 + h * 8 + g;
            #pragma unroll
            for (int nf = 0; nf < 8; nf++) {
                int cl = wn * 64 + nf * 8 + q * 2;
                int cg = nc * 128 + cl;
                uint32_t off = (uint32_t)r * PITCH + (uint32_t)cl * 2;
                float2 e2 = unpk2(*(uint32_t*)(sm + FA_C + off));
                float e1a = acc[mf][nf][h*2]   + bemS[cg]   + 1.f;
                float e1b = acc[mf][nf][h*2+1] + bemS[cg+1] + 1.f;
                float y0 = qS[cg]   * kmS[r*132 + cl]   * e1a + e2.x;
                float y1 = qS[cg+1] * kmS[r*132 + cl+1] * e1b + e2.y;
                *(uint32_t*)(sm + FA_C + off) = pkf2(y0, y1);
            }
        }
        // ---- newE += Y @ weo[nc]
        __syncthreads();
        stage_w(sm + FA_B, weoP + (size_t)nc * TILE_FULL, tid);
        __syncthreads();
        compute_ktile(accNE, cB, bHi, bLo, wm, wn, lane);
    }

    // ---- epilogue: he = LN(e + newE + beo) * gne + bne (e re-read fp32)
    #pragma unroll
    for (int mf = 0; mf < 2; mf++)
    #pragma unroll
    for (int h = 0; h < 2; h++) {
        int r = wm * 32 + mf * 16 + h * 8 + g;
        #pragma unroll
        for (int nf = 0; nf < 8; nf++) {
            int cl = wn * 64 + nf * 8 + q * 2;
            float2 ev = *(const float2*)(e + (row0 + r) * ED_ + cl);
            accNE[mf][nf][h*2+0] += beoS[cl]   + ev.x;
            accNE[mf][nf][h*2+1] += beoS[cl+1] + ev.y;
        }
    }
    float mean[2][2], rstd[2][2];
    #pragma unroll
    for (int mf = 0; mf < 2; mf++)
    #pragma unroll
    for (int h = 0; h < 2; h++) {
        float s = 0.f;
        #pragma unroll
        for (int nf = 0; nf < 8; nf++) s += accNE[mf][nf][h*2] + accNE[mf][nf][h*2+1];
        s += __shfl_xor_sync(0xffffffffu, s, 1);
        s += __shfl_xor_sync(0xffffffffu, s, 2);
        if (q == 0) red[wn * 128 + wm * 32 + mf * 16 + h * 8 + g] = s;
    }
    __syncthreads();
    #pragma unroll
    for (int mf = 0; mf < 2; mf++)
    #pragma unroll
    for (int h = 0; h < 2; h++) {
        int r = wm * 32 + mf * 16 + h * 8 + g;
        mean[mf][h] = (red[r] + red[128 + r]) * (1.f / 128.f);
        float s = 0.f;
        #pragma unroll
        for (int nf = 0; nf < 8; nf++) {
            float d0 = accNE[mf][nf][h*2]   - mean[mf][h];
            float d1 = accNE[mf][nf][h*2+1] - mean[mf][h];
            s += d0 * d0 + d1 * d1;
        }
        s += __shfl_xor_sync(0xffffffffu, s, 1);
        s += __shfl_xor_sync(0xffffffffu, s, 2);
        if (q == 0) red2[wn * 128 + r] = s;
    }
    __syncthreads();
    #pragma unroll
    for (int mf = 0; mf < 2; mf++)
    #pragma unroll
    for (int h = 0; h < 2; h++) {
        int r = wm * 32 + mf * 16 + h * 8 + g;
        rstd[mf][h] = rsqrtf((red2[r] + red2[128 + r]) * (1.f / 128.f) + 1e-5f);
        #pragma unroll
        for (int nf = 0; nf < 8; nf++) {
            int cl = wn * 64 + nf * 8 + q * 2;
            float o0 = (accNE[mf][nf][h*2]   - mean[mf][h]) * rstd[mf][h] * gneS[cl]   + bneS[cl];
            float o1 = (accNE[mf][nf][h*2+1] - mean[mf][h]) * rstd[mf][h] * gneS[cl+1] + bneS[cl+1];
            *(uint32_t*)((char*)he + ((row0 + r) * ED_ + cl) * 2) = pkf2(o0, o1);
        }
    }
}

// ================ fused edge FF: he -> e_out ================
#define FB_A   0
#define FB_B   34816
#define FB_C   104448
#define FB_SM  139264
#define FB_BYTES (139264 + 5632)

__global__ void __launch_bounds__(256, 1) edge_ff_kernel(
    const __nv_bfloat16* __restrict__ he, const float* __restrict__ e,
    const char* __restrict__ we1P, const char* __restrict__ we2P,
    const float* __restrict__ be1, const float* __restrict__ be2,
    const float* __restrict__ gne, const float* __restrict__ bne,
    float* __restrict__ e_out)
{
    extern __shared__ char sm[];
    const int tid = threadIdx.x;
    const int lane = tid & 31, w = tid >> 5;
    const int wm = w & 3, wn = w >> 2;
    const int g = lane >> 2, q = lane & 3;
    const size_t row0 = (size_t)blockIdx.x * 128;

    uint32_t smB = smem_u32(sm);
    float* be1S = (float*)(sm + FB_SM);    // 512
    float* be2S = be1S + 512;              // 128
    float* gneS = be2S + 128;              // 128
    float* bneS = gneS + 128;              // 128
    float* red  = bneS + 128;              // 256
    float* red2 = red + 256;               // 256

    stage_a_bf16(sm + FB_A, he, row0, ED_, tid);
    for (int t = tid; t < 512; t += 256) be1S[t] = be1[t];
    if (tid < 128) { be2S[tid] = be2[tid]; gneS[tid] = gne[tid]; bneS[tid] = bne[tid]; }

    const uint32_t aB  = smB + FB_A;
    const uint32_t bHi = smB + FB_B, bLo = smB + FB_B + TILE_HALF;
    const uint32_t cB  = smB + FB_C;

    float accH2[2][8][4] = {};

    #pragma unroll 1
    for (int p = 0; p < 4; p++) {
        // h1 chunk = relu(he @ we1[p] + be1[p]) -> bf16 into C
        __syncthreads();
        stage_w(sm + FB_B, we1P + (size_t)p * TILE_FULL, tid);
        __syncthreads();
        float acc[2][8][4] = {};
        compute_ktile(acc, aB, bHi, bLo, wm, wn, lane);
        #pragma unroll
        for (int mf = 0; mf < 2; mf++)
        #pragma unroll
        for (int h = 0; h < 2; h++) {
            int r = wm * 32 + mf * 16 + h * 8 + g;
            #pragma unroll
            for (int nf = 0; nf < 8; nf++) {
                int cl = wn * 64 + nf * 8 + q * 2;
                int cgl = p * 128 + cl;
                float o0 = fmaxf(acc[mf][nf][h*2]   + be1S[cgl],   0.f);
                float o1 = fmaxf(acc[mf][nf][h*2+1] + be1S[cgl+1], 0.f);
                *(uint32_t*)(sm + FB_C + (uint32_t)r * PITCH + (uint32_t)cl * 2) = pkf2(o0, o1);
            }
        }
        // h2 += chunk @ we2[p]
        __syncthreads();
        stage_w(sm + FB_B, we2P + (size_t)p * TILE_FULL, tid);
        __syncthreads();
        compute_ktile(accH2, cB, bHi, bLo, wm, wn, lane);
    }

    // epilogue: e_out = LN(e + h2 + be2) * gne + bne
    #pragma unroll
    for (int mf = 0; mf < 2; mf++)
    #pragma unroll
    for (int h = 0; h < 2; h++) {
        int r = wm * 32 + mf * 16 + h * 8 + g;
        #pragma unroll
        for (int nf = 0; nf < 8; nf++) {
            int cl = wn * 64 + nf * 8 + q * 2;
            float2 ev = *(const float2*)(e + (row0 + r) * ED_ + cl);
            accH2[mf][nf][h*2+0] += be2S[cl]   + ev.x;
            accH2[mf][nf][h*2+1] += be2S[cl+1] + ev.y;
        }
    }
    float mean[2][2], rstd[2][2];
    #pragma unroll
    for (int mf = 0; mf < 2; mf++)
    #pragma unroll
    for (int h = 0; h < 2; h++) {
        float s = 0.f;
        #pragma unroll
        for (int nf = 0; nf < 8; nf++) s += accH2[mf][nf][h*2] + accH2[mf][nf][h*2+1];
        s += __shfl_xor_sync(0xffffffffu, s, 1);
        s += __shfl_xor_sync(0xffffffffu, s, 2);
        if (q == 0) red[wn * 128 + wm * 32 + mf * 16 + h * 8 + g] = s;
    }
    __syncthreads();
    #pragma unroll
    for (int mf = 0; mf < 2; mf++)
    #pragma unroll
    for (int h = 0; h < 2; h++) {
        int r = wm * 32 + mf * 16 + h * 8 + g;
        mean[mf][h] = (red[r] + red[128 + r]) * (1.f / 128.f);
        float s = 0.f;
        #pragma unroll
        for (int nf = 0; nf < 8; nf++) {
            float d0 = accH2[mf][nf][h*2]   - mean[mf][h];
            float d1 = accH2[mf][nf][h*2+1] - mean[mf][h];
            s += d0 * d0 + d1 * d1;
        }
        s += __shfl_xor_sync(0xffffffffu, s, 1);
        s += __shfl_xor_sync(0xffffffffu, s, 2);
        if (q == 0) red2[wn * 128 + r] = s;
    }
    __syncthreads();
    #pragma unroll
    for (int mf = 0; mf < 2; mf++)
    #pragma unroll
    for (int h = 0; h < 2; h++) {
        int r = wm * 32 + mf * 16 + h * 8 + g;
        rstd[mf][h] = rsqrtf((red2[r] + red2[128 + r]) * (1.f / 128.f) + 1e-5f);
        #pragma unroll
        for (int nf = 0; nf < 8; nf++) {
            int cl = wn * 64 + nf * 8 + q * 2;
            float o0 = (accH2[mf][nf][h*2]   - mean[mf][h]) * rstd[mf][h] * gneS[cl]   + bneS[cl];
            float o1 = (accH2[mf][nf][h*2+1] - mean[mf][h]) * rstd[mf][h] * gneS[cl+1] + bneS[cl+1];
            *(float2*)(e_out + (row0 + r) * ED_ + cl) = make_float2(o0, o1);
        }
    }
}

// ---------------- node-side SIMT GEMM + LN ----------------
template<bool RELU>
__global__ void __launch_bounds__(256) gemm_kernel(
    const float* __restrict__ A, const float* __restrict__ W,
    const float* __restrict__ bias, float* __restrict__ C,
    int M, int N, int K, float alpha)
{
    __shared__ __align__(16) float aS[64][68];
    __shared__ __align__(16) float wS[64][68];
    const int tid = threadIdx.x;
    const int tx  = tid & 15;
    const int ty  = tid >> 4;
    const size_t row0 = (size_t)blockIdx.y * 64;
    const int    col0 = blockIdx.x * 64;
    float acc[4][4] = {};
    for (int k0 = 0; k0 < K; k0 += 64) {
        #pragma unroll
        for (int t = tid; t < 1024; t += 256) {
            int r = t >> 4, c4 = (t & 15) << 2;
            float4 av = *(const float4*)(A + (row0 + r) * K + k0 + c4);
            aS[r][c4+0]=av.x; aS[r][c4+1]=av.y; aS[r][c4+2]=av.z; aS[r][c4+3]=av.w;
            float4 wv = *(const float4*)(W + (size_t)(k0 + r) * N + col0 + c4);
            wS[r][c4+0]=wv.x; wS[r][c4+1]=wv.y; wS[r][c4+2]=wv.z; wS[r][c4+3]=wv.w;
        }
        __syncthreads();
        #pragma unroll 16
        for (int k = 0; k < 64; ++k) {
            float a0=aS[ty*4+0][k], a1=aS[ty*4+1][k], a2=aS[ty*4+2][k], a3=aS[ty*4+3][k];
            float4 bv = *(const float4*)&wS[k][tx*4];
            acc[0][0]+=a0*bv.x; acc[0][1]+=a0*bv.y; acc[0][2]+=a0*bv.z; acc[0][3]+=a0*bv.w;
            acc[1][0]+=a1*bv.x; acc[1][1]+=a1*bv.y; acc[1][2]+=a1*bv.z; acc[1][3]+=a1*bv.w;
            acc[2][0]+=a2*bv.x; acc[2][1]+=a2*bv.y; acc[2][2]+=a2*bv.z; acc[2][3]+=a2*bv.w;
            acc[3][0]+=a3*bv.x; acc[3][1]+=a3*bv.y; acc[3][2]+=a3*bv.z; acc[3][3]+=a3*bv.w;
        }
        __syncthreads();
    }
    const int c = col0 + tx * 4;
    float b0=bias[c+0], b1=bias[c+1], b2=bias[c+2], b3=bias[c+3];
    #pragma unroll
    for (int m = 0; m < 4; ++m) {
        float4 o;
        o.x = alpha*(acc[m][0]+b0); o.y = alpha*(acc[m][1]+b1);
        o.z = alpha*(acc[m][2]+b2); o.w = alpha*(acc[m][3]+b3);
        if (RELU) { o.x=fmaxf(o.x,0.f); o.y=fmaxf(o.y,0.f); o.z=fmaxf(o.z,0.f); o.w=fmaxf(o.w,0.f); }
        *(float4*)(C + (row0 + ty*4 + m) * N + c) = o;
    }
}

__global__ void ln_kernel(const float* __restrict__ A, const float* __restrict__ Bv,
                          const float* __restrict__ g, const float* __restrict__ be,
                          float* __restrict__ out)
{
    __shared__ float red[8];
    const int D = blockDim.x;
    const size_t base = (size_t)blockIdx.x * D + threadIdx.x;
    const int lane = threadIdx.x & 31;
    const int w    = threadIdx.x >> 5;
    const int nw   = D >> 5;
    float v = A[base] + Bv[base];
    float s = v;
    #pragma unroll
    for (int o = 16; o; o >>= 1) s += __shfl_xor_sync(0xffffffffu, s, o);
    if (lane == 0) red[w] = s;
    __syncthreads();
    float tot = 0.f;
    for (int ww = 0; ww < nw; ++ww) tot += red[ww];
    float mean = tot / (float)D;
    float d = v - mean;
    __syncthreads();
    float s2 = d * d;
    #pragma unroll
    for (int o = 16; o; o >>= 1) s2 += __shfl_xor_sync(0xffffffffu, s2, o);
    if (lane == 0) red[w] = s2;
    __syncthreads();
    float tot2 = 0.f;
    for (int ww = 0; ww < nw; ++ww) tot2 += red[ww];
    float var = tot2 / (float)D;
    out[base] = d * rsqrtf(var + 1e-5f) * g[threadIdx.x] + be[threadIdx.x];
}

// ---------------- launcher ----------------
extern "C" void kernel_launch(void* const* d_in, const int* in_sizes, int n_in,
                              void* d_out, int out_size)
{
    const float* x   = (const float*)d_in[0];
    const float* e   = (const float*)d_in[1];
    const float* wq  = (const float*)d_in[2];
    const float* wk  = (const float*)d_in[3];
    const float* wv  = (const float*)d_in[4];
    const float* wem = (const float*)d_in[5];
    const float* wea = (const float*)d_in[6];
    const float* wxo = (const float*)d_in[7];
    const float* weo = (const float*)d_in[8];
    const float* wx1 = (const float*)d_in[9];
    const float* wx2 = (const float*)d_in[10];
    const float* we1 = (const float*)d_in[11];
    const float* we2 = (const float*)d_in[12];
    const float* bq  = (const float*)d_in[13];
    const float* bk  = (const float*)d_in[14];
    const float* bv  = (const float*)d_in[15];
    const float* bem = (const float*)d_in[16];
    const float* bea = (const float*)d_in[17];
    const float* bxo = (const float*)d_in[18];
    const float* beo = (const float*)d_in[19];
    const float* bx1 = (const float*)d_in[20];
    const float* bx2 = (const float*)d_in[21];
    const float* be1 = (const float*)d_in[22];
    const float* be2 = (const float*)d_in[23];
    const float* gnx = (const float*)d_in[24];
    const float* bnx = (const float*)d_in[25];
    const float* gne = (const float*)d_in[26];
    const float* bne = (const float*)d_in[27];

    float* x_out = (float*)d_out;
    float* e_out = (float*)d_out + (size_t)ROWS_X * XD_;

    float *Q, *Km, *newX, *hx, *h1x, *h2x, *wvx, *bvx, *zero;
    __nv_bfloat16 *he;
    char *wemP, *weaP, *weoP, *we1P, *we2P;
    cudaGetSymbolAddress((void**)&Q,    g_Q);
    cudaGetSymbolAddress((void**)&Km,   g_Km);
    cudaGetSymbolAddress((void**)&newX, g_newX);
    cudaGetSymbolAddress((void**)&hx,   g_hx);
    cudaGetSymbolAddress((void**)&h1x,  g_h1x);
    cudaGetSymbolAddress((void**)&h2x,  g_h2x);
    cudaGetSymbolAddress((void**)&wvx,  g_wvx);
    cudaGetSymbolAddress((void**)&bvx,  g_bvx);
    cudaGetSymbolAddress((void**)&zero, g_zero);
    cudaGetSymbolAddress((void**)&he,   g_he);
    cudaGetSymbolAddress((void**)&wemP, g_wemP);
    cudaGetSymbolAddress((void**)&weaP, g_weaP);
    cudaGetSymbolAddress((void**)&weoP, g_weoP);
    cudaGetSymbolAddress((void**)&we1P, g_we1P);
    cudaGetSymbolAddress((void**)&we2P, g_we2P);

    cudaFuncSetAttribute(edge_attn_kernel, cudaFuncAttributeMaxDynamicSharedMemorySize, FA_BYTES);
    cudaFuncSetAttribute(edge_ff_kernel,   cudaFuncAttributeMaxDynamicSharedMemorySize, FB_BYTES);

    dim3 blk(256);
    auto grid_of = [](int M, int N) { return dim3((unsigned)(N/64), (unsigned)(M/64)); };

    prep_weight<<<2, 256>>>(wem, 128, 256, wemP);
    prep_weight<<<2, 256>>>(wea, 128, 256, weaP);
    prep_weight<<<2, 256>>>(weo, 256, 128, weoP);
    prep_weight<<<4, 256>>>(we1, 128, 512, we1P);
    prep_weight<<<4, 256>>>(we2, 512, 128, we2P);

    // node side (softmax collapses: wV == V; fold wv@wxo)
    gemm_kernel<false><<<grid_of(XD_, XD_), blk>>>(wv, wxo, zero, wvx, XD_, XD_, XD_, 1.f);
    fold_bias<<<1, 256>>>(bv, wxo, bxo, bvx);
    gemm_kernel<false><<<grid_of(ROWS_X, XD_), blk>>>(x, wq, bq, Q,  ROWS_X, XD_, XD_, INV_SQRT_DF);
    gemm_kernel<false><<<grid_of(ROWS_X, XD_), blk>>>(x, wk, bk, Km, ROWS_X, XD_, XD_, 1.f);
    gemm_kernel<false><<<grid_of(ROWS_X, XD_), blk>>>(x, wvx, bvx, newX, ROWS_X, XD_, XD_, 1.f);
    ln_kernel<<<ROWS_X, XD_>>>(x, newX, gnx, bnx, hx);
    gemm_kernel<true ><<<grid_of(ROWS_X, FFX), blk>>>(hx,  wx1, bx1, h1x, ROWS_X, FFX, XD_, 1.f);
    gemm_kernel<false><<<grid_of(ROWS_X, XD_), blk>>>(h1x, wx2, bx2, h2x, ROWS_X, XD_, FFX, 1.f);
    ln_kernel<<<ROWS_X, XD_>>>(x, h2x, gnx, bnx, x_out);

    // edge side: two fused tensor-core kernels (2-pass split; Y/h1 never touch HBM)
    edge_attn_kernel<<<ROWS_E / 128, blk, FA_BYTES>>>(
        e, Q, Km, wemP, weaP, weoP, bem, bea, beo, gne, bne, he);
    edge_ff_kernel<<<ROWS_E / 128, blk, FB_BYTES>>>(
        he, e, we1P, we2P, be1, be2, gne, bne, e_out);
}

// round 7
// speedup vs baseline: 3.1064x; 1.2111x over previous
#include <cuda_runtime.h>
#include <cuda_bf16.h>
#include <math.h>
#include <stdint.h>

#define BB  8
#define NN  128
#define XD_ 256
#define ED_ 128
#define FFX 1024
#define FFE 512
#define ROWS_X (BB*NN)
#define ROWS_E (BB*NN*NN)
#define INV_SQRT_DF 0.17677669529663687f

#define PITCH     272           // bytes per bf16 tile row (136 bf16)
#define TILE_HALF 34816         // 128 * 272 (one bf16 128x128 tile)
#define TILE_FULL 69632         // hi + lo (weights only)

// ---------------- scratch ----------------
__device__ float g_Q   [ROWS_X * XD_];
__device__ float g_Km  [ROWS_X * XD_];
__device__ float g_newX[ROWS_X * XD_];
__device__ float g_hx  [ROWS_X * XD_];
__device__ float g_h1x [ROWS_X * FFX];
__device__ float g_h2x [ROWS_X * XD_];
__device__ float g_wvx [XD_ * XD_];
__device__ float g_bvx [XD_];
__device__ float g_zero[FFX];
__device__ __nv_bfloat16 g_he[(size_t)ROWS_E * ED_];
__device__ __align__(16) char g_wemP[2 * TILE_FULL];
__device__ __align__(16) char g_weaP[2 * TILE_FULL];
__device__ __align__(16) char g_weoP[2 * TILE_FULL];
__device__ __align__(16) char g_we1P[4 * TILE_FULL];
__device__ __align__(16) char g_we2P[4 * TILE_FULL];

// ---------------- helpers ----------------
__device__ __forceinline__ uint32_t smem_u32(const void* p) {
    uint32_t a;
    asm("{ .reg .u64 t; cvta.to.shared.u64 t, %1; cvt.u32.u64 %0, t; }" : "=r"(a) : "l"(p));
    return a;
}

#define CPA16(dst, src) asm volatile("cp.async.cg.shared.global [%0], [%1], 16;" :: "r"(dst), "l"(src))
#define CP_COMMIT() asm volatile("cp.async.commit_group;" ::: "memory")
#define CP_WAIT0()  asm volatile("cp.async.wait_group 0;" ::: "memory")

__device__ __forceinline__ void prefetch_w(uint32_t dstS, const char* src, int tid) {
    #pragma unroll 4
    for (int t = tid; t < 4352; t += 256)
        CPA16(dstS + (uint32_t)t * 16, src + (size_t)t * 16);
    CP_COMMIT();
}

__device__ __forceinline__ void mma16816(float* c, uint32_t a0, uint32_t a1, uint32_t a2,
                                         uint32_t a3, uint32_t b0, uint32_t b1) {
    asm volatile(
        "mma.sync.aligned.m16n8k16.row.col.f32.bf16.bf16.f32 "
        "{%0,%1,%2,%3},{%4,%5,%6,%7},{%8,%9},{%0,%1,%2,%3};"
        : "+f"(c[0]), "+f"(c[1]), "+f"(c[2]), "+f"(c[3])
        : "r"(a0), "r"(a1), "r"(a2), "r"(a3), "r"(b0), "r"(b1));
}

__device__ __forceinline__ void ldsm4(uint32_t& r0, uint32_t& r1, uint32_t& r2, uint32_t& r3,
                                      uint32_t a) {
    asm volatile("ldmatrix.sync.aligned.m8n8.x4.shared.b16 {%0,%1,%2,%3},[%4];"
                 : "=r"(r0), "=r"(r1), "=r"(r2), "=r"(r3) : "r"(a));
}

__device__ __forceinline__ void ldA8(uint32_t a[8], uint32_t base, int r0, int k0, int lane) {
    uint32_t addr = base + (uint32_t)(r0 + (lane & 15)) * PITCH
                  + (uint32_t)(k0 + ((lane >> 4) << 3)) * 2;
    ldsm4(a[0], a[1], a[2], a[3], addr);
    ldsm4(a[4], a[5], a[6], a[7], addr + 16 * PITCH);
}

__device__ __forceinline__ void ldB16(uint32_t b[16], uint32_t base, int n0, int k0, int lane) {
    uint32_t addr = base + (uint32_t)(n0 + ((lane >> 4) << 3) + (lane & 7)) * PITCH
                  + (uint32_t)(k0 + (((lane >> 3) & 1) << 3)) * 2;
    ldsm4(b[0],  b[1],  b[2],  b[3],  addr);
    ldsm4(b[4],  b[5],  b[6],  b[7],  addr + 16 * PITCH);
    ldsm4(b[8],  b[9],  b[10], b[11], addr + 32 * PITCH);
    ldsm4(b[12], b[13], b[14], b[15], addr + 48 * PITCH);
}

__device__ __forceinline__ void mma_pass(float (&acc)[2][8][4], const uint32_t a[8],
                                         const uint32_t b[16]) {
    #pragma unroll
    for (int mf = 0; mf < 2; mf++)
        #pragma unroll
        for (int nf = 0; nf < 8; nf++)
            mma16816(acc[mf][nf], a[mf*4], a[mf*4+1], a[mf*4+2], a[mf*4+3],
                     b[nf*2], b[nf*2+1]);
}

// 2-pass split: A bf16, B split hi/lo. D = A*Bh + A*Bl
__device__ __forceinline__ void compute_ktile(float (&acc)[2][8][4], uint32_t aB,
                                              uint32_t bB, int wm, int wn, int lane) {
    #pragma unroll 1
    for (int ks = 0; ks < 8; ks++) {
        uint32_t ah[8], bh[16], bl[16];
        ldA8(ah, aB, wm * 32, ks * 16, lane);
        ldB16(bh, bB,             wn * 64, ks * 16, lane);
        ldB16(bl, bB + TILE_HALF, wn * 64, ks * 16, lane);
        mma_pass(acc, ah, bh);
        mma_pass(acc, ah, bl);
    }
}

__device__ __forceinline__ uint32_t pkf2(float x, float y) {
    __nv_bfloat162 t = __floats2bfloat162_rn(x, y);
    return *reinterpret_cast<uint32_t*>(&t);
}
__device__ __forceinline__ float2 unpk2(uint32_t u) {
    __nv_bfloat162 t = *reinterpret_cast<__nv_bfloat162*>(&u);
    return make_float2(__bfloat162float(t.x), __bfloat162float(t.y));
}

__device__ __forceinline__ void stage_a_fp32(char* sm, const float* src, int stride, int tid) {
    #pragma unroll 4
    for (int t = tid; t < 4096; t += 256) {
        int r = t >> 5, c4 = (t & 31) << 2;
        float4 v = *(const float4*)(src + (size_t)r * stride + c4);
        uint32_t p0 = pkf2(v.x, v.y);
        uint32_t p1 = pkf2(v.z, v.w);
        *(uint2*)(sm + (uint32_t)r * PITCH + (uint32_t)c4 * 2) = make_uint2(p0, p1);
    }
}

__device__ __forceinline__ void stage_a_bf16(char* sm, const __nv_bfloat16* src, size_t row0,
                                             int stride, int tid) {
    #pragma unroll 4
    for (int t = tid; t < 2048; t += 256) {
        int r = t >> 4, c8 = (t & 15) << 3;
        *(uint4*)(sm + (uint32_t)r * PITCH + (uint32_t)c8 * 2) =
            *(const uint4*)(src + (row0 + r) * (size_t)stride + c8);
    }
}

// ---------------- merged weight prep: one block per 128x128 tile, coalesced ----------------
__global__ void prep_all(const float* __restrict__ wem, const float* __restrict__ wea,
                         const float* __restrict__ weo, const float* __restrict__ we1,
                         const float* __restrict__ we2,
                         char* __restrict__ wemP, char* __restrict__ weaP,
                         char* __restrict__ weoP, char* __restrict__ we1P,
                         char* __restrict__ we2P)
{
    extern __shared__ float tl[];   // 128 x 129
    int s = blockIdx.x;
    const float* W; char* out; int K, N, kc, nc;
    if (s < 2)       { W = wem; out = wemP + (size_t)s       * TILE_FULL; K = 128; N = 256; kc = 0;      nc = s;     }
    else if (s < 4)  { W = wea; out = weaP + (size_t)(s - 2) * TILE_FULL; K = 128; N = 256; kc = 0;      nc = s - 2; }
    else if (s < 6)  { W = weo; out = weoP + (size_t)(s - 4) * TILE_FULL; K = 256; N = 128; kc = s - 4;  nc = 0;     }
    else if (s < 10) { W = we1; out = we1P + (size_t)(s - 6) * TILE_FULL; K = 128; N = 512; kc = 0;      nc = s - 6; }
    else             { W = we2; out = we2P + (size_t)(s - 10)* TILE_FULL; K = 512; N = 128; kc = s - 10; nc = 0;     }
    int tid = threadIdx.x;
    for (int t = tid; t < 16384; t += 256) {
        int k = t >> 7, n = t & 127;
        tl[k * 129 + n] = W[(size_t)(kc * 128 + k) * N + nc * 128 + n];
    }
    __syncthreads();
    for (int t = tid; t < 8192; t += 256) {
        int n = t >> 6, k = (t & 63) << 1;
        float v0 = tl[k * 129 + n], v1 = tl[(k + 1) * 129 + n];
        __nv_bfloat16 h0 = __float2bfloat16(v0), h1 = __float2bfloat16(v1);
        float l0 = v0 - __bfloat162float(h0), l1 = v1 - __bfloat162float(h1);
        uint32_t off = (uint32_t)n * PITCH + (uint32_t)k * 2;
        *(uint32_t*)(out + off) =
            (uint32_t)__bfloat16_as_ushort(h0) | ((uint32_t)__bfloat16_as_ushort(h1) << 16);
        *(uint32_t*)(out + TILE_HALF + off) = pkf2(l0, l1);
    }
}

__global__ void fold_bias(const float* __restrict__ bv, const float* __restrict__ wxo,
                          const float* __restrict__ bxo, float* __restrict__ bvx) {
    int n = threadIdx.x;
    float s = bxo[n];
    for (int k = 0; k < XD_; ++k) s += bv[k] * wxo[k * XD_ + n];
    bvx[n] = s;
}

// ================ fused edge attention: e -> he (bf16) ================
#define FA_A   0
#define FA_B0  34816
#define FA_B1  104448
#define FA_C   174080
#define FA_SM  208896
#define FA_BYTES (208896 + 6656)

__global__ void __launch_bounds__(256, 1) edge_attn_kernel(
    const float* __restrict__ e, const float* __restrict__ Qs, const float* __restrict__ Km,
    const char* __restrict__ wemP, const char* __restrict__ weaP, const char* __restrict__ weoP,
    const float* __restrict__ bem, const float* __restrict__ bea, const float* __restrict__ beo,
    const float* __restrict__ gne, const float* __restrict__ bne,
    __nv_bfloat16* __restrict__ he)
{
    extern __shared__ char sm[];
    const int tid = threadIdx.x;
    const int lane = tid & 31, w = tid >> 5;
    const int wm = w & 3, wn = w >> 2;
    const int g = lane >> 2, q = lane & 3;
    const int blk = blockIdx.x;
    const size_t row0 = (size_t)blk * 128;
    const int b = blk >> 7, i = blk & 127;

    uint32_t smB = smem_u32(sm);
    float* qS   = (float*)(sm + FA_SM);            // 256
    float* bemS = qS + 256;                         // 256
    float* beaS = bemS + 256;                       // 256
    float* beoS = beaS + 256;                       // 128
    float* gneS = beoS + 128;                       // 128
    float* bneS = gneS + 128;                       // 128
    float* red  = bneS + 128;                       // 256
    float* red2 = red + 256;                        // 256

    const uint32_t aB = smB + FA_A;
    const uint32_t cB = smB + FA_C;
    const uint32_t Bb[2] = {smB + FA_B0, smB + FA_B1};
    const char* tiles[6] = {weaP, wemP, weoP,
                            weaP + TILE_FULL, wemP + TILE_FULL, weoP + TILE_FULL};

    prefetch_w(Bb[0], tiles[0], tid);               // tile 0 in flight
    stage_a_fp32(sm + FA_A, e + row0 * ED_, ED_, tid);
    qS[tid]   = Qs[((size_t)(b * NN + i)) * XD_ + tid];
    bemS[tid] = bem[tid];
    beaS[tid] = bea[tid];
    if (tid < 128) { beoS[tid] = beo[tid]; gneS[tid] = gne[tid]; bneS[tid] = bne[tid]; }
    CP_WAIT0(); __syncthreads();
    prefetch_w(Bb[1], tiles[1], tid);               // tile 1 in flight

    float accNE[2][8][4] = {};

    #pragma unroll 1
    for (int nc = 0; nc < 2; nc++) {
        const int t0 = nc * 3;
        // ---- tile t0 (wea[nc]) ready in Bb[t0&1]: E2 = e@wea + bea -> bf16 into C
        {
            float acc[2][8][4] = {};
            compute_ktile(acc, aB, Bb[t0 & 1], wm, wn, lane);
            #pragma unroll
            for (int mf = 0; mf < 2; mf++)
            #pragma unroll
            for (int h = 0; h < 2; h++) {
                int r = wm * 32 + mf * 16 + h * 8 + g;
                #pragma unroll
                for (int nf = 0; nf < 8; nf++) {
                    int cl = wn * 64 + nf * 8 + q * 2;
                    int cg = nc * 128 + cl;
                    *(uint32_t*)(sm + FA_C + (uint32_t)r * PITCH + (uint32_t)cl * 2) =
                        pkf2(acc[mf][nf][h*2] + beaS[cg], acc[mf][nf][h*2+1] + beaS[cg+1]);
                }
            }
        }
        CP_WAIT0(); __syncthreads();
        if (t0 + 2 < 6) prefetch_w(Bb[t0 & 1], tiles[t0 + 2], tid);
        // ---- tile t0+1 (wem[nc]): E1 = e@wem; Y epilogue in-place into C
        {
            float acc[2][8][4] = {};
            compute_ktile(acc, aB, Bb[(t0 + 1) & 1], wm, wn, lane);
            #pragma unroll
            for (int mf = 0; mf < 2; mf++)
            #pragma unroll
            for (int h = 0; h < 2; h++) {
                int r = wm * 32 + mf * 16 + h * 8 + g;
                const float* kp = Km + ((size_t)(b * NN + r)) * XD_ + nc * 128;
                #pragma unroll
                for (int nf = 0; nf < 8; nf++) {
                    int cl = wn * 64 + nf * 8 + q * 2;
                    int cg = nc * 128 + cl;
                    uint32_t off = (uint32_t)r * PITCH + (uint32_t)cl * 2;
                    float2 e2 = unpk2(*(uint32_t*)(sm + FA_C + off));
                    float2 km = *(const float2*)(kp + cl);
                    float e1a = acc[mf][nf][h*2]   + bemS[cg]   + 1.f;
                    float e1b = acc[mf][nf][h*2+1] + bemS[cg+1] + 1.f;
                    float y0 = qS[cg]   * km.x * e1a + e2.x;
                    float y1 = qS[cg+1] * km.y * e1b + e2.y;
                    *(uint32_t*)(sm + FA_C + off) = pkf2(y0, y1);
                }
            }
        }
        CP_WAIT0(); __syncthreads();
        if (t0 + 3 < 6) prefetch_w(Bb[(t0 + 1) & 1], tiles[t0 + 3], tid);
        // ---- tile t0+2 (weo[nc]): newE += Y @ weo
        compute_ktile(accNE, cB, Bb[t0 & 1], wm, wn, lane);
        CP_WAIT0(); __syncthreads();
        if (t0 + 4 < 6) prefetch_w(Bb[t0 & 1], tiles[t0 + 4], tid);
    }

    // ---- epilogue: he = LN(e + newE + beo) * gne + bne (e re-read fp32)
    #pragma unroll
    for (int mf = 0; mf < 2; mf++)
    #pragma unroll
    for (int h = 0; h < 2; h++) {
        int r = wm * 32 + mf * 16 + h * 8 + g;
        #pragma unroll
        for (int nf = 0; nf < 8; nf++) {
            int cl = wn * 64 + nf * 8 + q * 2;
            float2 ev = *(const float2*)(e + (row0 + r) * ED_ + cl);
            accNE[mf][nf][h*2+0] += beoS[cl]   + ev.x;
            accNE[mf][nf][h*2+1] += beoS[cl+1] + ev.y;
        }
    }
    float mean[2][2], rstd[2][2];
    #pragma unroll
    for (int mf = 0; mf < 2; mf++)
    #pragma unroll
    for (int h = 0; h < 2; h++) {
        float s = 0.f;
        #pragma unroll
        for (int nf = 0; nf < 8; nf++) s += accNE[mf][nf][h*2] + accNE[mf][nf][h*2+1];
        s += __shfl_xor_sync(0xffffffffu, s, 1);
        s += __shfl_xor_sync(0xffffffffu, s, 2);
        if (q == 0) red[wn * 128 + wm * 32 + mf * 16 + h * 8 + g] = s;
    }
    __syncthreads();
    #pragma unroll
    for (int mf = 0; mf < 2; mf++)
    #pragma unroll
    for (int h = 0; h < 2; h++) {
        int r = wm * 32 + mf * 16 + h * 8 + g;
        mean[mf][h] = (red[r] + red[128 + r]) * (1.f / 128.f);
        float s = 0.f;
        #pragma unroll
        for (int nf = 0; nf < 8; nf++) {
            float d0 = accNE[mf][nf][h*2]   - mean[mf][h];
            float d1 = accNE[mf][nf][h*2+1] - mean[mf][h];
            s += d0 * d0 + d1 * d1;
        }
        s += __shfl_xor_sync(0xffffffffu, s, 1);
        s += __shfl_xor_sync(0xffffffffu, s, 2);
        if (q == 0) red2[wn * 128 + r] = s;
    }
    __syncthreads();
    #pragma unroll
    for (int mf = 0; mf < 2; mf++)
    #pragma unroll
    for (int h = 0; h < 2; h++) {
        int r = wm * 32 + mf * 16 + h * 8 + g;
        rstd[mf][h] = rsqrtf((red2[r] + red2[128 + r]) * (1.f / 128.f) + 1e-5f);
        #pragma unroll
        for (int nf = 0; nf < 8; nf++) {
            int cl = wn * 64 + nf * 8 + q * 2;
            float o0 = (accNE[mf][nf][h*2]   - mean[mf][h]) * rstd[mf][h] * gneS[cl]   + bneS[cl];
            float o1 = (accNE[mf][nf][h*2+1] - mean[mf][h]) * rstd[mf][h] * gneS[cl+1] + bneS[cl+1];
            *(uint32_t*)((char*)he + ((row0 + r) * ED_ + cl) * 2) = pkf2(o0, o1);
        }
    }
}

// ================ fused edge FF: he -> e_out ================
#define FB_A   0
#define FB_B0  34816
#define FB_B1  104448
#define FB_C   174080
#define FB_SM  208896
#define FB_BYTES (208896 + 5632)

__global__ void __launch_bounds__(256, 1) edge_ff_kernel(
    const __nv_bfloat16* __restrict__ he, const float* __restrict__ e,
    const char* __restrict__ we1P, const char* __restrict__ we2P,
    const float* __restrict__ be1, const float* __restrict__ be2,
    const float* __restrict__ gne, const float* __restrict__ bne,
    float* __restrict__ e_out)
{
    extern __shared__ char sm[];
    const int tid = threadIdx.x;
    const int lane = tid & 31, w = tid >> 5;
    const int wm = w & 3, wn = w >> 2;
    const int g = lane >> 2, q = lane & 3;
    const size_t row0 = (size_t)blockIdx.x * 128;

    uint32_t smB = smem_u32(sm);
    float* be1S = (float*)(sm + FB_SM);    // 512
    float* be2S = be1S + 512;              // 128
    float* gneS = be2S + 128;              // 128
    float* bneS = gneS + 128;              // 128
    float* red  = bneS + 128;              // 256
    float* red2 = red + 256;               // 256

    const uint32_t aB = smB + FB_A;
    const uint32_t cB = smB + FB_C;
    const uint32_t Bb[2] = {smB + FB_B0, smB + FB_B1};
    const char* tiles[8] = {we1P,                 we2P,
                            we1P + TILE_FULL,     we2P + TILE_FULL,
                            we1P + 2 * TILE_FULL, we2P + 2 * TILE_FULL,
                            we1P + 3 * TILE_FULL, we2P + 3 * TILE_FULL};

    prefetch_w(Bb[0], tiles[0], tid);
    stage_a_bf16(sm + FB_A, he, row0, ED_, tid);
    for (int t = tid; t < 512; t += 256) be1S[t] = be1[t];
    if (tid < 128) { be2S[tid] = be2[tid]; gneS[tid] = gne[tid]; bneS[tid] = bne[tid]; }
    CP_WAIT0(); __syncthreads();
    prefetch_w(Bb[1], tiles[1], tid);

    float accH2[2][8][4] = {};

    #pragma unroll 1
    for (int p = 0; p < 4; p++) {
        const int i0 = p * 2;
        // ---- tile i0 (we1[p]): h1 = relu(he@we1 + be1) -> bf16 into C
        {
            float acc[2][8][4] = {};
            compute_ktile(acc, aB, Bb[i0 & 1], wm, wn, lane);
            #pragma unroll
            for (int mf = 0; mf < 2; mf++)
            #pragma unroll
            for (int h = 0; h < 2; h++) {
                int r = wm * 32 + mf * 16 + h * 8 + g;
                #pragma unroll
                for (int nf = 0; nf < 8; nf++) {
                    int cl = wn * 64 + nf * 8 + q * 2;
                    int cgl = p * 128 + cl;
                    float o0 = fmaxf(acc[mf][nf][h*2]   + be1S[cgl],   0.f);
                    float o1 = fmaxf(acc[mf][nf][h*2+1] + be1S[cgl+1], 0.f);
                    *(uint32_t*)(sm + FB_C + (uint32_t)r * PITCH + (uint32_t)cl * 2) = pkf2(o0, o1);
                }
            }
        }
        CP_WAIT0(); __syncthreads();
        if (i0 + 2 < 8) prefetch_w(Bb[i0 & 1], tiles[i0 + 2], tid);
        // ---- tile i0+1 (we2[p]): h2 += h1chunk @ we2
        compute_ktile(accH2, cB, Bb[(i0 + 1) & 1], wm, wn, lane);
        CP_WAIT0(); __syncthreads();
        if (i0 + 3 < 8) prefetch_w(Bb[(i0 + 1) & 1], tiles[i0 + 3], tid);
    }

    // epilogue: e_out = LN(e + h2 + be2) * gne + bne
    #pragma unroll
    for (int mf = 0; mf < 2; mf++)
    #pragma unroll
    for (int h = 0; h < 2; h++) {
        int r = wm * 32 + mf * 16 + h * 8 + g;
        #pragma unroll
        for (int nf = 0; nf < 8; nf++) {
            int cl = wn * 64 + nf * 8 + q * 2;
            float2 ev = *(const float2*)(e + (row0 + r) * ED_ + cl);
            accH2[mf][nf][h*2+0] += be2S[cl]   + ev.x;
            accH2[mf][nf][h*2+1] += be2S[cl+1] + ev.y;
        }
    }
    float mean[2][2], rstd[2][2];
    #pragma unroll
    for (int mf = 0; mf < 2; mf++)
    #pragma unroll
    for (int h = 0; h < 2; h++) {
        float s = 0.f;
        #pragma unroll
        for (int nf = 0; nf < 8; nf++) s += accH2[mf][nf][h*2] + accH2[mf][nf][h*2+1];
        s += __shfl_xor_sync(0xffffffffu, s, 1);
        s += __shfl_xor_sync(0xffffffffu, s, 2);
        if (q == 0) red[wn * 128 + wm * 32 + mf * 16 + h * 8 + g] = s;
    }
    __syncthreads();
    #pragma unroll
    for (int mf = 0; mf < 2; mf++)
    #pragma unroll
    for (int h = 0; h < 2; h++) {
        int r = wm * 32 + mf * 16 + h * 8 + g;
        mean[mf][h] = (red[r] + red[128 + r]) * (1.f / 128.f);
        float s = 0.f;
        #pragma unroll
        for (int nf = 0; nf < 8; nf++) {
            float d0 = accH2[mf][nf][h*2]   - mean[mf][h];
            float d1 = accH2[mf][nf][h*2+1] - mean[mf][h];
            s += d0 * d0 + d1 * d1;
        }
        s += __shfl_xor_sync(0xffffffffu, s, 1);
        s += __shfl_xor_sync(0xffffffffu, s, 2);
        if (q == 0) red2[wn * 128 + r] = s;
    }
    __syncthreads();
    #pragma unroll
    for (int mf = 0; mf < 2; mf++)
    #pragma unroll
    for (int h = 0; h < 2; h++) {
        int r = wm * 32 + mf * 16 + h * 8 + g;
        rstd[mf][h] = rsqrtf((red2[r] + red2[128 + r]) * (1.f / 128.f) + 1e-5f);
        #pragma unroll
        for (int nf = 0; nf < 8; nf++) {
            int cl = wn * 64 + nf * 8 + q * 2;
            float o0 = (accH2[mf][nf][h*2]   - mean[mf][h]) * rstd[mf][h] * gneS[cl]   + bneS[cl];
            float o1 = (accH2[mf][nf][h*2+1] - mean[mf][h]) * rstd[mf][h] * gneS[cl+1] + bneS[cl+1];
            *(float2*)(e_out + (row0 + r) * ED_ + cl) = make_float2(o0, o1);
        }
    }
}

// ---------------- node-side SIMT GEMM + LN ----------------
template<bool RELU>
__global__ void __launch_bounds__(256) gemm_kernel(
    const float* __restrict__ A, const float* __restrict__ W,
    const float* __restrict__ bias, float* __restrict__ C,
    int M, int N, int K, float alpha)
{
    __shared__ __align__(16) float aS[64][68];
    __shared__ __align__(16) float wS[64][68];
    const int tid = threadIdx.x;
    const int tx  = tid & 15;
    const int ty  = tid >> 4;
    const size_t row0 = (size_t)blockIdx.y * 64;
    const int    col0 = blockIdx.x * 64;
    float acc[4][4] = {};
    for (int k0 = 0; k0 < K; k0 += 64) {
        #pragma unroll
        for (int t = tid; t < 1024; t += 256) {
            int r = t >> 4, c4 = (t & 15) << 2;
            float4 av = *(const float4*)(A + (row0 + r) * K + k0 + c4);
            aS[r][c4+0]=av.x; aS[r][c4+1]=av.y; aS[r][c4+2]=av.z; aS[r][c4+3]=av.w;
            float4 wv = *(const float4*)(W + (size_t)(k0 + r) * N + col0 + c4);
            wS[r][c4+0]=wv.x; wS[r][c4+1]=wv.y; wS[r][c4+2]=wv.z; wS[r][c4+3]=wv.w;
        }
        __syncthreads();
        #pragma unroll 16
        for (int k = 0; k < 64; ++k) {
            float a0=aS[ty*4+0][k], a1=aS[ty*4+1][k], a2=aS[ty*4+2][k], a3=aS[ty*4+3][k];
            float4 bv = *(const float4*)&wS[k][tx*4];
            acc[0][0]+=a0*bv.x; acc[0][1]+=a0*bv.y; acc[0][2]+=a0*bv.z; acc[0][3]+=a0*bv.w;
            acc[1][0]+=a1*bv.x; acc[1][1]+=a1*bv.y; acc[1][2]+=a1*bv.z; acc[1][3]+=a1*bv.w;
            acc[2][0]+=a2*bv.x; acc[2][1]+=a2*bv.y; acc[2][2]+=a2*bv.z; acc[2][3]+=a2*bv.w;
            acc[3][0]+=a3*bv.x; acc[3][1]+=a3*bv.y; acc[3][2]+=a3*bv.z; acc[3][3]+=a3*bv.w;
        }
        __syncthreads();
    }
    const int c = col0 + tx * 4;
    float b0=bias[c+0], b1=bias[c+1], b2=bias[c+2], b3=bias[c+3];
    #pragma unroll
    for (int m = 0; m < 4; ++m) {
        float4 o;
        o.x = alpha*(acc[m][0]+b0); o.y = alpha*(acc[m][1]+b1);
        o.z = alpha*(acc[m][2]+b2); o.w = alpha*(acc[m][3]+b3);
        if (RELU) { o.x=fmaxf(o.x,0.f); o.y=fmaxf(o.y,0.f); o.z=fmaxf(o.z,0.f); o.w=fmaxf(o.w,0.f); }
        *(float4*)(C + (row0 + ty*4 + m) * N + c) = o;
    }
}

__global__ void ln_kernel(const float* __restrict__ A, const float* __restrict__ Bv,
                          const float* __restrict__ g, const float* __restrict__ be,
                          float* __restrict__ out)
{
    __shared__ float red[8];
    const int D = blockDim.x;
    const size_t base = (size_t)blockIdx.x * D + threadIdx.x;
    const int lane = threadIdx.x & 31;
    const int w    = threadIdx.x >> 5;
    const int nw   = D >> 5;
    float v = A[base] + Bv[base];
    float s = v;
    #pragma unroll
    for (int o = 16; o; o >>= 1) s += __shfl_xor_sync(0xffffffffu, s, o);
    if (lane == 0) red[w] = s;
    __syncthreads();
    float tot = 0.f;
    for (int ww = 0; ww < nw; ++ww) tot += red[ww];
    float mean = tot / (float)D;
    float d = v - mean;
    __syncthreads();
    float s2 = d * d;
    #pragma unroll
    for (int o = 16; o; o >>= 1) s2 += __shfl_xor_sync(0xffffffffu, s2, o);
    if (lane == 0) red[w] = s2;
    __syncthreads();
    float tot2 = 0.f;
    for (int ww = 0; ww < nw; ++ww) tot2 += red[ww];
    float var = tot2 / (float)D;
    out[base] = d * rsqrtf(var + 1e-5f) * g[threadIdx.x] + be[threadIdx.x];
}

// ---------------- launcher ----------------
extern "C" void kernel_launch(void* const* d_in, const int* in_sizes, int n_in,
                              void* d_out, int out_size)
{
    const float* x   = (const float*)d_in[0];
    const float* e   = (const float*)d_in[1];
    const float* wq  = (const float*)d_in[2];
    const float* wk  = (const float*)d_in[3];
    const float* wv  = (const float*)d_in[4];
    const float* wem = (const float*)d_in[5];
    const float* wea = (const float*)d_in[6];
    const float* wxo = (const float*)d_in[7];
    const float* weo = (const float*)d_in[8];
    const float* wx1 = (const float*)d_in[9];
    const float* wx2 = (const float*)d_in[10];
    const float* we1 = (const float*)d_in[11];
    const float* we2 = (const float*)d_in[12];
    const float* bq  = (const float*)d_in[13];
    const float* bk  = (const float*)d_in[14];
    const float* bv  = (const float*)d_in[15];
    const float* bem = (const float*)d_in[16];
    const float* bea = (const float*)d_in[17];
    const float* bxo = (const float*)d_in[18];
    const float* beo = (const float*)d_in[19];
    const float* bx1 = (const float*)d_in[20];
    const float* bx2 = (const float*)d_in[21];
    const float* be1 = (const float*)d_in[22];
    const float* be2 = (const float*)d_in[23];
    const float* gnx = (const float*)d_in[24];
    const float* bnx = (const float*)d_in[25];
    const float* gne = (const float*)d_in[26];
    const float* bne = (const float*)d_in[27];

    float* x_out = (float*)d_out;
    float* e_out = (float*)d_out + (size_t)ROWS_X * XD_;

    float *Q, *Km, *newX, *hx, *h1x, *h2x, *wvx, *bvx, *zero;
    __nv_bfloat16 *he;
    char *wemP, *weaP, *weoP, *we1P, *we2P;
    cudaGetSymbolAddress((void**)&Q,    g_Q);
    cudaGetSymbolAddress((void**)&Km,   g_Km);
    cudaGetSymbolAddress((void**)&newX, g_newX);
    cudaGetSymbolAddress((void**)&hx,   g_hx);
    cudaGetSymbolAddress((void**)&h1x,  g_h1x);
    cudaGetSymbolAddress((void**)&h2x,  g_h2x);
    cudaGetSymbolAddress((void**)&wvx,  g_wvx);
    cudaGetSymbolAddress((void**)&bvx,  g_bvx);
    cudaGetSymbolAddress((void**)&zero, g_zero);
    cudaGetSymbolAddress((void**)&he,   g_he);
    cudaGetSymbolAddress((void**)&wemP, g_wemP);
    cudaGetSymbolAddress((void**)&weaP, g_weaP);
    cudaGetSymbolAddress((void**)&weoP, g_weoP);
    cudaGetSymbolAddress((void**)&we1P, g_we1P);
    cudaGetSymbolAddress((void**)&we2P, g_we2P);

    cudaFuncSetAttribute(edge_attn_kernel, cudaFuncAttributeMaxDynamicSharedMemorySize, FA_BYTES);
    cudaFuncSetAttribute(edge_ff_kernel,   cudaFuncAttributeMaxDynamicSharedMemorySize, FB_BYTES);
    cudaFuncSetAttribute(prep_all,         cudaFuncAttributeMaxDynamicSharedMemorySize, 128 * 129 * 4);

    dim3 blk(256);
    auto grid_of = [](int M, int N) { return dim3((unsigned)(N/64), (unsigned)(M/64)); };

    // single merged weight-prep launch (14 tiles)
    prep_all<<<14, 256, 128 * 129 * 4>>>(wem, wea, weo, we1, we2,
                                         wemP, weaP, weoP, we1P, we2P);

    // node side (softmax collapses: wV == V; fold wv@wxo)
    gemm_kernel<false><<<grid_of(XD_, XD_), blk>>>(wv, wxo, zero, wvx, XD_, XD_, XD_, 1.f);
    fold_bias<<<1, 256>>>(bv, wxo, bxo, bvx);
    gemm_kernel<false><<<grid_of(ROWS_X, XD_), blk>>>(x, wq, bq, Q,  ROWS_X, XD_, XD_, INV_SQRT_DF);
    gemm_kernel<false><<<grid_of(ROWS_X, XD_), blk>>>(x, wk, bk, Km, ROWS_X, XD_, XD_, 1.f);
    gemm_kernel<false><<<grid_of(ROWS_X, XD_), blk>>>(x, wvx, bvx, newX, ROWS_X, XD_, XD_, 1.f);
    ln_kernel<<<ROWS_X, XD_>>>(x, newX, gnx, bnx, hx);
    gemm_kernel<true ><<<grid_of(ROWS_X, FFX), blk>>>(hx,  wx1, bx1, h1x, ROWS_X, FFX, XD_, 1.f);
    gemm_kernel<false><<<grid_of(ROWS_X, XD_), blk>>>(h1x, wx2, bx2, h2x, ROWS_X, XD_, FFX, 1.f);
    ln_kernel<<<ROWS_X, XD_>>>(x, h2x, gnx, bnx, x_out);

    // edge side: fused tensor-core kernels with cp.async double-buffered weights
    edge_attn_kernel<<<ROWS_E / 128, blk, FA_BYTES>>>(
        e, Q, Km, wemP, weaP, weoP, bem, bea, beo, gne, bne, he);
    edge_ff_kernel<<<ROWS_E / 128, blk, FB_BYTES>>>(
        he, e, we1P, we2P, be1, be2, gne, bne, e_out);
}

// round 8
// speedup vs baseline: 3.4252x; 1.1026x over previous
#include <cuda_runtime.h>
#include <cuda_bf16.h>
#include <math.h>
#include <stdint.h>

#define BB  8
#define NN  128
#define XD_ 256
#define ED_ 128
#define FFX 1024
#define FFE 512
#define ROWS_X (BB*NN)
#define ROWS_E (BB*NN*NN)
#define INV_SQRT_DF 0.17677669529663687f

#define PITCH     272           // bytes per bf16 tile row (136 bf16)
#define TILE_HALF 34816         // 128 * 272 (one bf16 128x128 tile)
#define TILE_FULL 69632         // hi + lo (weights only)

// ---------------- scratch ----------------
__device__ float g_Q   [ROWS_X * XD_];
__device__ float g_Km  [ROWS_X * XD_];
__device__ float g_newX[ROWS_X * XD_];
__device__ float g_hx  [ROWS_X * XD_];
__device__ float g_h1x [ROWS_X * FFX];
__device__ float g_h2x [ROWS_X * XD_];
__device__ float g_wvx [XD_ * XD_];
__device__ float g_bvx [XD_];
__device__ float g_zero[FFX];
__device__ __nv_bfloat16 g_he[(size_t)ROWS_E * ED_];
__device__ __align__(16) char g_wemP[2 * TILE_FULL];
__device__ __align__(16) char g_weaP[2 * TILE_FULL];
__device__ __align__(16) char g_weoP[2 * TILE_FULL];
__device__ __align__(16) char g_we1P[4 * TILE_FULL];
__device__ __align__(16) char g_we2P[4 * TILE_FULL];

// ---------------- helpers ----------------
__device__ __forceinline__ uint32_t smem_u32(const void* p) {
    uint32_t a;
    asm("{ .reg .u64 t; cvta.to.shared.u64 t, %1; cvt.u32.u64 %0, t; }" : "=r"(a) : "l"(p));
    return a;
}

#define CPA16(dst, src) asm volatile("cp.async.cg.shared.global [%0], [%1], 16;" :: "r"(dst), "l"(src))
#define CP_COMMIT() asm volatile("cp.async.commit_group;" ::: "memory")
#define CP_WAIT0()  asm volatile("cp.async.wait_group 0;" ::: "memory")

__device__ __forceinline__ void prefetch_w(uint32_t dstS, const char* src, int tid) {
    #pragma unroll 4
    for (int t = tid; t < 4352; t += 256)
        CPA16(dstS + (uint32_t)t * 16, src + (size_t)t * 16);
    CP_COMMIT();
}

__device__ __forceinline__ void mma16816(float* c, uint32_t a0, uint32_t a1, uint32_t a2,
                                         uint32_t a3, uint32_t b0, uint32_t b1) {
    asm volatile(
        "mma.sync.aligned.m16n8k16.row.col.f32.bf16.bf16.f32 "
        "{%0,%1,%2,%3},{%4,%5,%6,%7},{%8,%9},{%0,%1,%2,%3};"
        : "+f"(c[0]), "+f"(c[1]), "+f"(c[2]), "+f"(c[3])
        : "r"(a0), "r"(a1), "r"(a2), "r"(a3), "r"(b0), "r"(b1));
}

__device__ __forceinline__ void ldsm4(uint32_t& r0, uint32_t& r1, uint32_t& r2, uint32_t& r3,
                                      uint32_t a) {
    asm volatile("ldmatrix.sync.aligned.m8n8.x4.shared.b16 {%0,%1,%2,%3},[%4];"
                 : "=r"(r0), "=r"(r1), "=r"(r2), "=r"(r3) : "r"(a));
}

__device__ __forceinline__ void ldA8(uint32_t a[8], uint32_t base, int r0, int k0, int lane) {
    uint32_t addr = base + (uint32_t)(r0 + (lane & 15)) * PITCH
                  + (uint32_t)(k0 + ((lane >> 4) << 3)) * 2;
    ldsm4(a[0], a[1], a[2], a[3], addr);
    ldsm4(a[4], a[5], a[6], a[7], addr + 16 * PITCH);
}

__device__ __forceinline__ void ldB16(uint32_t b[16], uint32_t base, int n0, int k0, int lane) {
    uint32_t addr = base + (uint32_t)(n0 + ((lane >> 4) << 3) + (lane & 7)) * PITCH
                  + (uint32_t)(k0 + (((lane >> 3) & 1) << 3)) * 2;
    ldsm4(b[0],  b[1],  b[2],  b[3],  addr);
    ldsm4(b[4],  b[5],  b[6],  b[7],  addr + 16 * PITCH);
    ldsm4(b[8],  b[9],  b[10], b[11], addr + 32 * PITCH);
    ldsm4(b[12], b[13], b[14], b[15], addr + 48 * PITCH);
}

__device__ __forceinline__ void mma_pass(float (&acc)[2][8][4], const uint32_t a[8],
                                         const uint32_t b[16]) {
    #pragma unroll
    for (int mf = 0; mf < 2; mf++)
        #pragma unroll
        for (int nf = 0; nf < 8; nf++)
            mma16816(acc[mf][nf], a[mf*4], a[mf*4+1], a[mf*4+2], a[mf*4+3],
                     b[nf*2], b[nf*2+1]);
}

// 2-pass split: A bf16, B split hi/lo. D = A*Bh + A*Bl
__device__ __forceinline__ void compute_ktile(float (&acc)[2][8][4], uint32_t aB,
                                              uint32_t bB, int wm, int wn, int lane) {
    #pragma unroll 1
    for (int ks = 0; ks < 8; ks++) {
        uint32_t ah[8], bh[16], bl[16];
        ldA8(ah, aB, wm * 32, ks * 16, lane);
        ldB16(bh, bB,             wn * 64, ks * 16, lane);
        ldB16(bl, bB + TILE_HALF, wn * 64, ks * 16, lane);
        mma_pass(acc, ah, bh);
        mma_pass(acc, ah, bl);
    }
}

__device__ __forceinline__ uint32_t pkf2(float x, float y) {
    __nv_bfloat162 t = __floats2bfloat162_rn(x, y);
    return *reinterpret_cast<uint32_t*>(&t);
}
__device__ __forceinline__ float2 unpk2(uint32_t u) {
    __nv_bfloat162 t = *reinterpret_cast<__nv_bfloat162*>(&u);
    return make_float2(__bfloat162float(t.x), __bfloat162float(t.y));
}

__device__ __forceinline__ void stage_a_fp32(char* sm, const float* src, int stride, int tid) {
    #pragma unroll 4
    for (int t = tid; t < 4096; t += 256) {
        int r = t >> 5, c4 = (t & 31) << 2;
        float4 v = *(const float4*)(src + (size_t)r * stride + c4);
        uint32_t p0 = pkf2(v.x, v.y);
        uint32_t p1 = pkf2(v.z, v.w);
        *(uint2*)(sm + (uint32_t)r * PITCH + (uint32_t)c4 * 2) = make_uint2(p0, p1);
    }
}

__device__ __forceinline__ void stage_a_bf16(char* sm, const __nv_bfloat16* src, size_t row0,
                                             int stride, int tid) {
    #pragma unroll 4
    for (int t = tid; t < 2048; t += 256) {
        int r = t >> 4, c8 = (t & 15) << 3;
        *(uint4*)(sm + (uint32_t)r * PITCH + (uint32_t)c8 * 2) =
            *(const uint4*)(src + (row0 + r) * (size_t)stride + c8);
    }
}

// ---------------- merged weight prep: one block per 128x128 tile, coalesced ----------------
__global__ void prep_all(const float* __restrict__ wem, const float* __restrict__ wea,
                         const float* __restrict__ weo, const float* __restrict__ we1,
                         const float* __restrict__ we2,
                         char* __restrict__ wemP, char* __restrict__ weaP,
                         char* __restrict__ weoP, char* __restrict__ we1P,
                         char* __restrict__ we2P)
{
    extern __shared__ float tl[];   // 128 x 129
    int s = blockIdx.x;
    const float* W; char* out; int K, N, kc, nc;
    if (s < 2)       { W = wem; out = wemP + (size_t)s       * TILE_FULL; K = 128; N = 256; kc = 0;      nc = s;     }
    else if (s < 4)  { W = wea; out = weaP + (size_t)(s - 2) * TILE_FULL; K = 128; N = 256; kc = 0;      nc = s - 2; }
    else if (s < 6)  { W = weo; out = weoP + (size_t)(s - 4) * TILE_FULL; K = 256; N = 128; kc = s - 4;  nc = 0;     }
    else if (s < 10) { W = we1; out = we1P + (size_t)(s - 6) * TILE_FULL; K = 128; N = 512; kc = 0;      nc = s - 6; }
    else             { W = we2; out = we2P + (size_t)(s - 10)* TILE_FULL; K = 512; N = 128; kc = s - 10; nc = 0;     }
    int tid = threadIdx.x;
    for (int t = tid; t < 16384; t += 256) {
        int k = t >> 7, n = t & 127;
        tl[k * 129 + n] = W[(size_t)(kc * 128 + k) * N + nc * 128 + n];
    }
    __syncthreads();
    for (int t = tid; t < 8192; t += 256) {
        int n = t >> 6, k = (t & 63) << 1;
        float v0 = tl[k * 129 + n], v1 = tl[(k + 1) * 129 + n];
        __nv_bfloat16 h0 = __float2bfloat16(v0), h1 = __float2bfloat16(v1);
        float l0 = v0 - __bfloat162float(h0), l1 = v1 - __bfloat162float(h1);
        uint32_t off = (uint32_t)n * PITCH + (uint32_t)k * 2;
        *(uint32_t*)(out + off) =
            (uint32_t)__bfloat16_as_ushort(h0) | ((uint32_t)__bfloat16_as_ushort(h1) << 16);
        *(uint32_t*)(out + TILE_HALF + off) = pkf2(l0, l1);
    }
}

__global__ void fold_bias(const float* __restrict__ bv, const float* __restrict__ wxo,
                          const float* __restrict__ bxo, float* __restrict__ bvx) {
    int n = threadIdx.x;
    float s = bxo[n];
    for (int k = 0; k < XD_; ++k) s += bv[k] * wxo[k * XD_ + n];
    bvx[n] = s;
}

// ================ fused edge attention: e -> he (bf16) ================
#define FA_A   0
#define FA_B0  34816
#define FA_B1  104448
#define FA_C   174080
#define FA_SM  208896
#define FA_BYTES (208896 + 6656)

__global__ void __launch_bounds__(256, 1) edge_attn_kernel(
    const float* __restrict__ e, const float* __restrict__ Qs, const float* __restrict__ Km,
    const char* __restrict__ wemP, const char* __restrict__ weaP, const char* __restrict__ weoP,
    const float* __restrict__ bem, const float* __restrict__ bea, const float* __restrict__ beo,
    const float* __restrict__ gne, const float* __restrict__ bne,
    __nv_bfloat16* __restrict__ he)
{
    extern __shared__ char sm[];
    const int tid = threadIdx.x;
    const int lane = tid & 31, w = tid >> 5;
    const int wm = w & 3, wn = w >> 2;
    const int g = lane >> 2, q = lane & 3;
    const int blk = blockIdx.x;
    const size_t row0 = (size_t)blk * 128;
    const int b = blk >> 7, i = blk & 127;

    uint32_t smB = smem_u32(sm);
    float* qS   = (float*)(sm + FA_SM);            // 256
    float* bemS = qS + 256;                         // 256
    float* beaS = bemS + 256;                       // 256
    float* beoS = beaS + 256;                       // 128
    float* gneS = beoS + 128;                       // 128
    float* bneS = gneS + 128;                       // 128
    float* red  = bneS + 128;                       // 256
    float* red2 = red + 256;                        // 256

    const uint32_t aB = smB + FA_A;
    const uint32_t cB = smB + FA_C;
    const uint32_t Bb[2] = {smB + FA_B0, smB + FA_B1};
    const char* tiles[6] = {weaP, wemP, weoP,
                            weaP + TILE_FULL, wemP + TILE_FULL, weoP + TILE_FULL};

    prefetch_w(Bb[0], tiles[0], tid);               // tile 0 in flight
    stage_a_fp32(sm + FA_A, e + row0 * ED_, ED_, tid);
    qS[tid]   = Qs[((size_t)(b * NN + i)) * XD_ + tid];
    bemS[tid] = bem[tid];
    beaS[tid] = bea[tid];
    if (tid < 128) { beoS[tid] = beo[tid]; gneS[tid] = gne[tid]; bneS[tid] = bne[tid]; }
    CP_WAIT0(); __syncthreads();
    prefetch_w(Bb[1], tiles[1], tid);               // tile 1 in flight

    float accNE[2][8][4] = {};

    #pragma unroll 1
    for (int nc = 0; nc < 2; nc++) {
        const int t0 = nc * 3;
        // ---- tile t0 (wea[nc]) ready in Bb[t0&1]: E2 = e@wea + bea -> bf16 into C
        {
            float acc[2][8][4] = {};
            compute_ktile(acc, aB, Bb[t0 & 1], wm, wn, lane);
            #pragma unroll
            for (int mf = 0; mf < 2; mf++)
            #pragma unroll
            for (int h = 0; h < 2; h++) {
                int r = wm * 32 + mf * 16 + h * 8 + g;
                #pragma unroll
                for (int nf = 0; nf < 8; nf++) {
                    int cl = wn * 64 + nf * 8 + q * 2;
                    int cg = nc * 128 + cl;
                    *(uint32_t*)(sm + FA_C + (uint32_t)r * PITCH + (uint32_t)cl * 2) =
                        pkf2(acc[mf][nf][h*2] + beaS[cg], acc[mf][nf][h*2+1] + beaS[cg+1]);
                }
            }
        }
        CP_WAIT0(); __syncthreads();
        if (t0 + 2 < 6) prefetch_w(Bb[t0 & 1], tiles[t0 + 2], tid);
        // ---- tile t0+1 (wem[nc]): E1 = e@wem; Y epilogue in-place into C
        {
            float acc[2][8][4] = {};
            compute_ktile(acc, aB, Bb[(t0 + 1) & 1], wm, wn, lane);
            #pragma unroll
            for (int mf = 0; mf < 2; mf++)
            #pragma unroll
            for (int h = 0; h < 2; h++) {
                int r = wm * 32 + mf * 16 + h * 8 + g;
                const float* kp = Km + ((size_t)(b * NN + r)) * XD_ + nc * 128;
                #pragma unroll
                for (int nf = 0; nf < 8; nf++) {
                    int cl = wn * 64 + nf * 8 + q * 2;
                    int cg = nc * 128 + cl;
                    uint32_t off = (uint32_t)r * PITCH + (uint32_t)cl * 2;
                    float2 e2 = unpk2(*(uint32_t*)(sm + FA_C + off));
                    float2 km = *(const float2*)(kp + cl);
                    float e1a = acc[mf][nf][h*2]   + bemS[cg]   + 1.f;
                    float e1b = acc[mf][nf][h*2+1] + bemS[cg+1] + 1.f;
                    float y0 = qS[cg]   * km.x * e1a + e2.x;
                    float y1 = qS[cg+1] * km.y * e1b + e2.y;
                    *(uint32_t*)(sm + FA_C + off) = pkf2(y0, y1);
                }
            }
        }
        CP_WAIT0(); __syncthreads();
        if (t0 + 3 < 6) prefetch_w(Bb[(t0 + 1) & 1], tiles[t0 + 3], tid);
        // ---- tile t0+2 (weo[nc]): newE += Y @ weo
        compute_ktile(accNE, cB, Bb[t0 & 1], wm, wn, lane);
        CP_WAIT0(); __syncthreads();
        if (t0 + 4 < 6) prefetch_w(Bb[t0 & 1], tiles[t0 + 4], tid);
    }

    // ---- epilogue: he = LN(e + newE + beo) * gne + bne (e re-read fp32)
    #pragma unroll
    for (int mf = 0; mf < 2; mf++)
    #pragma unroll
    for (int h = 0; h < 2; h++) {
        int r = wm * 32 + mf * 16 + h * 8 + g;
        #pragma unroll
        for (int nf = 0; nf < 8; nf++) {
            int cl = wn * 64 + nf * 8 + q * 2;
            float2 ev = *(const float2*)(e + (row0 + r) * ED_ + cl);
            accNE[mf][nf][h*2+0] += beoS[cl]   + ev.x;
            accNE[mf][nf][h*2+1] += beoS[cl+1] + ev.y;
        }
    }
    float mean[2][2], rstd[2][2];
    #pragma unroll
    for (int mf = 0; mf < 2; mf++)
    #pragma unroll
    for (int h = 0; h < 2; h++) {
        float s = 0.f;
        #pragma unroll
        for (int nf = 0; nf < 8; nf++) s += accNE[mf][nf][h*2] + accNE[mf][nf][h*2+1];
        s += __shfl_xor_sync(0xffffffffu, s, 1);
        s += __shfl_xor_sync(0xffffffffu, s, 2);
        if (q == 0) red[wn * 128 + wm * 32 + mf * 16 + h * 8 + g] = s;
    }
    __syncthreads();
    #pragma unroll
    for (int mf = 0; mf < 2; mf++)
    #pragma unroll
    for (int h = 0; h < 2; h++) {
        int r = wm * 32 + mf * 16 + h * 8 + g;
        mean[mf][h] = (red[r] + red[128 + r]) * (1.f / 128.f);
        float s = 0.f;
        #pragma unroll
        for (int nf = 0; nf < 8; nf++) {
            float d0 = accNE[mf][nf][h*2]   - mean[mf][h];
            float d1 = accNE[mf][nf][h*2+1] - mean[mf][h];
            s += d0 * d0 + d1 * d1;
        }
        s += __shfl_xor_sync(0xffffffffu, s, 1);
        s += __shfl_xor_sync(0xffffffffu, s, 2);
        if (q == 0) red2[wn * 128 + r] = s;
    }
    __syncthreads();
    #pragma unroll
    for (int mf = 0; mf < 2; mf++)
    #pragma unroll
    for (int h = 0; h < 2; h++) {
        int r = wm * 32 + mf * 16 + h * 8 + g;
        rstd[mf][h] = rsqrtf((red2[r] + red2[128 + r]) * (1.f / 128.f) + 1e-5f);
        #pragma unroll
        for (int nf = 0; nf < 8; nf++) {
            int cl = wn * 64 + nf * 8 + q * 2;
            float o0 = (accNE[mf][nf][h*2]   - mean[mf][h]) * rstd[mf][h] * gneS[cl]   + bneS[cl];
            float o1 = (accNE[mf][nf][h*2+1] - mean[mf][h]) * rstd[mf][h] * gneS[cl+1] + bneS[cl+1];
            *(uint32_t*)((char*)he + ((row0 + r) * ED_ + cl) * 2) = pkf2(o0, o1);
        }
    }
}

// ================ fused edge FF: he -> e_out ================
#define FB_A   0
#define FB_B0  34816
#define FB_B1  104448
#define FB_C   174080
#define FB_SM  208896
#define FB_BYTES (208896 + 5632)

__global__ void __launch_bounds__(256, 1) edge_ff_kernel(
    const __nv_bfloat16* __restrict__ he, const float* __restrict__ e,
    const char* __restrict__ we1P, const char* __restrict__ we2P,
    const float* __restrict__ be1, const float* __restrict__ be2,
    const float* __restrict__ gne, const float* __restrict__ bne,
    float* __restrict__ e_out)
{
    extern __shared__ char sm[];
    const int tid = threadIdx.x;
    const int lane = tid & 31, w = tid >> 5;
    const int wm = w & 3, wn = w >> 2;
    const int g = lane >> 2, q = lane & 3;
    const size_t row0 = (size_t)blockIdx.x * 128;

    uint32_t smB = smem_u32(sm);
    float* be1S = (float*)(sm + FB_SM);    // 512
    float* be2S = be1S + 512;              // 128
    float* gneS = be2S + 128;              // 128
    float* bneS = gneS + 128;              // 128
    float* red  = bneS + 128;              // 256
    float* red2 = red + 256;               // 256

    const uint32_t aB = smB + FB_A;
    const uint32_t cB = smB + FB_C;
    const uint32_t Bb[2] = {smB + FB_B0, smB + FB_B1};
    const char* tiles[8] = {we1P,                 we2P,
                            we1P + TILE_FULL,     we2P + TILE_FULL,
                            we1P + 2 * TILE_FULL, we2P + 2 * TILE_FULL,
                            we1P + 3 * TILE_FULL, we2P + 3 * TILE_FULL};

    prefetch_w(Bb[0], tiles[0], tid);
    stage_a_bf16(sm + FB_A, he, row0, ED_, tid);
    for (int t = tid; t < 512; t += 256) be1S[t] = be1[t];
    if (tid < 128) { be2S[tid] = be2[tid]; gneS[tid] = gne[tid]; bneS[tid] = bne[tid]; }
    CP_WAIT0(); __syncthreads();
    prefetch_w(Bb[1], tiles[1], tid);

    float accH2[2][8][4] = {};

    #pragma unroll 1
    for (int p = 0; p < 4; p++) {
        const int i0 = p * 2;
        // ---- tile i0 (we1[p]): h1 = relu(he@we1 + be1) -> bf16 into C
        {
            float acc[2][8][4] = {};
            compute_ktile(acc, aB, Bb[i0 & 1], wm, wn, lane);
            #pragma unroll
            for (int mf = 0; mf < 2; mf++)
            #pragma unroll
            for (int h = 0; h < 2; h++) {
                int r = wm * 32 + mf * 16 + h * 8 + g;
                #pragma unroll
                for (int nf = 0; nf < 8; nf++) {
                    int cl = wn * 64 + nf * 8 + q * 2;
                    int cgl = p * 128 + cl;
                    float o0 = fmaxf(acc[mf][nf][h*2]   + be1S[cgl],   0.f);
                    float o1 = fmaxf(acc[mf][nf][h*2+1] + be1S[cgl+1], 0.f);
                    *(uint32_t*)(sm + FB_C + (uint32_t)r * PITCH + (uint32_t)cl * 2) = pkf2(o0, o1);
                }
            }
        }
        CP_WAIT0(); __syncthreads();
        if (i0 + 2 < 8) prefetch_w(Bb[i0 & 1], tiles[i0 + 2], tid);
        // ---- tile i0+1 (we2[p]): h2 += h1chunk @ we2
        compute_ktile(accH2, cB, Bb[(i0 + 1) & 1], wm, wn, lane);
        CP_WAIT0(); __syncthreads();
        if (i0 + 3 < 8) prefetch_w(Bb[(i0 + 1) & 1], tiles[i0 + 3], tid);
    }

    // epilogue: e_out = LN(e + h2 + be2) * gne + bne
    #pragma unroll
    for (int mf = 0; mf < 2; mf++)
    #pragma unroll
    for (int h = 0; h < 2; h++) {
        int r = wm * 32 + mf * 16 + h * 8 + g;
        #pragma unroll
        for (int nf = 0; nf < 8; nf++) {
            int cl = wn * 64 + nf * 8 + q * 2;
            float2 ev = *(const float2*)(e + (row0 + r) * ED_ + cl);
            accH2[mf][nf][h*2+0] += be2S[cl]   + ev.x;
            accH2[mf][nf][h*2+1] += be2S[cl+1] + ev.y;
        }
    }
    float mean[2][2], rstd[2][2];
    #pragma unroll
    for (int mf = 0; mf < 2; mf++)
    #pragma unroll
    for (int h = 0; h < 2; h++) {
        float s = 0.f;
        #pragma unroll
        for (int nf = 0; nf < 8; nf++) s += accH2[mf][nf][h*2] + accH2[mf][nf][h*2+1];
        s += __shfl_xor_sync(0xffffffffu, s, 1);
        s += __shfl_xor_sync(0xffffffffu, s, 2);
        if (q == 0) red[wn * 128 + wm * 32 + mf * 16 + h * 8 + g] = s;
    }
    __syncthreads();
    #pragma unroll
    for (int mf = 0; mf < 2; mf++)
    #pragma unroll
    for (int h = 0; h < 2; h++) {
        int r = wm * 32 + mf * 16 + h * 8 + g;
        mean[mf][h] = (red[r] + red[128 + r]) * (1.f / 128.f);
        float s = 0.f;
        #pragma unroll
        for (int nf = 0; nf < 8; nf++) {
            float d0 = accH2[mf][nf][h*2]   - mean[mf][h];
            float d1 = accH2[mf][nf][h*2+1] - mean[mf][h];
            s += d0 * d0 + d1 * d1;
        }
        s += __shfl_xor_sync(0xffffffffu, s, 1);
        s += __shfl_xor_sync(0xffffffffu, s, 2);
        if (q == 0) red2[wn * 128 + r] = s;
    }
    __syncthreads();
    #pragma unroll
    for (int mf = 0; mf < 2; mf++)
    #pragma unroll
    for (int h = 0; h < 2; h++) {
        int r = wm * 32 + mf * 16 + h * 8 + g;
        rstd[mf][h] = rsqrtf((red2[r] + red2[128 + r]) * (1.f / 128.f) + 1e-5f);
        #pragma unroll
        for (int nf = 0; nf < 8; nf++) {
            int cl = wn * 64 + nf * 8 + q * 2;
            float o0 = (accH2[mf][nf][h*2]   - mean[mf][h]) * rstd[mf][h] * gneS[cl]   + bneS[cl];
            float o1 = (accH2[mf][nf][h*2+1] - mean[mf][h]) * rstd[mf][h] * gneS[cl+1] + bneS[cl+1];
            *(float2*)(e_out + (row0 + r) * ED_ + cl) = make_float2(o0, o1);
        }
    }
}

// ---------------- node-side SIMT GEMM + LN ----------------
template<bool RELU>
__global__ void __launch_bounds__(256) gemm_kernel(
    const float* __restrict__ A, const float* __restrict__ W,
    const float* __restrict__ bias, float* __restrict__ C,
    int M, int N, int K, float alpha)
{
    __shared__ __align__(16) float aS[64][68];
    __shared__ __align__(16) float wS[64][68];
    const int tid = threadIdx.x;
    const int tx  = tid & 15;
    const int ty  = tid >> 4;
    const size_t row0 = (size_t)blockIdx.y * 64;
    const int    col0 = blockIdx.x * 64;
    float acc[4][4] = {};
    for (int k0 = 0; k0 < K; k0 += 64) {
        #pragma unroll
        for (int t = tid; t < 1024; t += 256) {
            int r = t >> 4, c4 = (t & 15) << 2;
            float4 av = *(const float4*)(A + (row0 + r) * K + k0 + c4);
            aS[r][c4+0]=av.x; aS[r][c4+1]=av.y; aS[r][c4+2]=av.z; aS[r][c4+3]=av.w;
            float4 wv = *(const float4*)(W + (size_t)(k0 + r) * N + col0 + c4);
            wS[r][c4+0]=wv.x; wS[r][c4+1]=wv.y; wS[r][c4+2]=wv.z; wS[r][c4+3]=wv.w;
        }
        __syncthreads();
        #pragma unroll 16
        for (int k = 0; k < 64; ++k) {
            float a0=aS[ty*4+0][k], a1=aS[ty*4+1][k], a2=aS[ty*4+2][k], a3=aS[ty*4+3][k];
            float4 bv = *(const float4*)&wS[k][tx*4];
            acc[0][0]+=a0*bv.x; acc[0][1]+=a0*bv.y; acc[0][2]+=a0*bv.z; acc[0][3]+=a0*bv.w;
            acc[1][0]+=a1*bv.x; acc[1][1]+=a1*bv.y; acc[1][2]+=a1*bv.z; acc[1][3]+=a1*bv.w;
            acc[2][0]+=a2*bv.x; acc[2][1]+=a2*bv.y; acc[2][2]+=a2*bv.z; acc[2][3]+=a2*bv.w;
            acc[3][0]+=a3*bv.x; acc[3][1]+=a3*bv.y; acc[3][2]+=a3*bv.z; acc[3][3]+=a3*bv.w;
        }
        __syncthreads();
    }
    const int c = col0 + tx * 4;
    float b0=bias[c+0], b1=bias[c+1], b2=bias[c+2], b3=bias[c+3];
    #pragma unroll
    for (int m = 0; m < 4; ++m) {
        float4 o;
        o.x = alpha*(acc[m][0]+b0); o.y = alpha*(acc[m][1]+b1);
        o.z = alpha*(acc[m][2]+b2); o.w = alpha*(acc[m][3]+b3);
        if (RELU) { o.x=fmaxf(o.x,0.f); o.y=fmaxf(o.y,0.f); o.z=fmaxf(o.z,0.f); o.w=fmaxf(o.w,0.f); }
        *(float4*)(C + (row0 + ty*4 + m) * N + c) = o;
    }
}

__global__ void ln_kernel(const float* __restrict__ A, const float* __restrict__ Bv,
                          const float* __restrict__ g, const float* __restrict__ be,
                          float* __restrict__ out)
{
    __shared__ float red[8];
    const int D = blockDim.x;
    const size_t base = (size_t)blockIdx.x * D + threadIdx.x;
    const int lane = threadIdx.x & 31;
    const int w    = threadIdx.x >> 5;
    const int nw   = D >> 5;
    float v = A[base] + Bv[base];
    float s = v;
    #pragma unroll
    for (int o = 16; o; o >>= 1) s += __shfl_xor_sync(0xffffffffu, s, o);
    if (lane == 0) red[w] = s;
    __syncthreads();
    float tot = 0.f;
    for (int ww = 0; ww < nw; ++ww) tot += red[ww];
    float mean = tot / (float)D;
    float d = v - mean;
    __syncthreads();
    float s2 = d * d;
    #pragma unroll
    for (int o = 16; o; o >>= 1) s2 += __shfl_xor_sync(0xffffffffu, s2, o);
    if (lane == 0) red[w] = s2;
    __syncthreads();
    float tot2 = 0.f;
    for (int ww = 0; ww < nw; ++ww) tot2 += red[ww];
    float var = tot2 / (float)D;
    out[base] = d * rsqrtf(var + 1e-5f) * g[threadIdx.x] + be[threadIdx.x];
}

// ---------------- launcher ----------------
extern "C" void kernel_launch(void* const* d_in, const int* in_sizes, int n_in,
                              void* d_out, int out_size)
{
    const float* x   = (const float*)d_in[0];
    const float* e   = (const float*)d_in[1];
    const float* wq  = (const float*)d_in[2];
    const float* wk  = (const float*)d_in[3];
    const float* wv  = (const float*)d_in[4];
    const float* wem = (const float*)d_in[5];
    const float* wea = (const float*)d_in[6];
    const float* wxo = (const float*)d_in[7];
    const float* weo = (const float*)d_in[8];
    const float* wx1 = (const float*)d_in[9];
    const float* wx2 = (const float*)d_in[10];
    const float* we1 = (const float*)d_in[11];
    const float* we2 = (const float*)d_in[12];
    const float* bq  = (const float*)d_in[13];
    const float* bk  = (const float*)d_in[14];
    const float* bv  = (const float*)d_in[15];
    const float* bem = (const float*)d_in[16];
    const float* bea = (const float*)d_in[17];
    const float* bxo = (const float*)d_in[18];
    const float* beo = (const float*)d_in[19];
    const float* bx1 = (const float*)d_in[20];
    const float* bx2 = (const float*)d_in[21];
    const float* be1 = (const float*)d_in[22];
    const float* be2 = (const float*)d_in[23];
    const float* gnx = (const float*)d_in[24];
    const float* bnx = (const float*)d_in[25];
    const float* gne = (const float*)d_in[26];
    const float* bne = (const float*)d_in[27];

    float* x_out = (float*)d_out;
    float* e_out = (float*)d_out + (size_t)ROWS_X * XD_;

    float *Q, *Km, *newX, *hx, *h1x, *h2x, *wvx, *bvx, *zero;
    __nv_bfloat16 *he;
    char *wemP, *weaP, *weoP, *we1P, *we2P;
    cudaGetSymbolAddress((void**)&Q,    g_Q);
    cudaGetSymbolAddress((void**)&Km,   g_Km);
    cudaGetSymbolAddress((void**)&newX, g_newX);
    cudaGetSymbolAddress((void**)&hx,   g_hx);
    cudaGetSymbolAddress((void**)&h1x,  g_h1x);
    cudaGetSymbolAddress((void**)&h2x,  g_h2x);
    cudaGetSymbolAddress((void**)&wvx,  g_wvx);
    cudaGetSymbolAddress((void**)&bvx,  g_bvx);
    cudaGetSymbolAddress((void**)&zero, g_zero);
    cudaGetSymbolAddress((void**)&he,   g_he);
    cudaGetSymbolAddress((void**)&wemP, g_wemP);
    cudaGetSymbolAddress((void**)&weaP, g_weaP);
    cudaGetSymbolAddress((void**)&weoP, g_weoP);
    cudaGetSymbolAddress((void**)&we1P, g_we1P);
    cudaGetSymbolAddress((void**)&we2P, g_we2P);

    cudaFuncSetAttribute(edge_attn_kernel, cudaFuncAttributeMaxDynamicSharedMemorySize, FA_BYTES);
    cudaFuncSetAttribute(edge_ff_kernel,   cudaFuncAttributeMaxDynamicSharedMemorySize, FB_BYTES);
    cudaFuncSetAttribute(prep_all,         cudaFuncAttributeMaxDynamicSharedMemorySize, 128 * 129 * 4);

    // one-time side-stream/event setup (host objects only; created on the
    // uncaptured correctness call, reused identically on every call)
    static cudaStream_t sNode = nullptr;
    static cudaEvent_t evFork = nullptr, evJoin = nullptr;
    if (!sNode) {
        cudaStreamCreateWithFlags(&sNode, cudaStreamNonBlocking);
        cudaEventCreateWithFlags(&evFork, cudaEventDisableTiming);
        cudaEventCreateWithFlags(&evJoin, cudaEventDisableTiming);
    }

    dim3 blk(256);
    auto grid_of = [](int M, int N) { return dim3((unsigned)(N/64), (unsigned)(M/64)); };

    // ---- fork: node-side chain runs concurrently on sNode ----
    cudaEventRecord(evFork, 0);
    cudaStreamWaitEvent(sNode, evFork, 0);

    // node side on sNode (softmax collapses: wV == V; fold wv@wxo)
    gemm_kernel<false><<<grid_of(XD_, XD_), blk, 0, sNode>>>(wv, wxo, zero, wvx, XD_, XD_, XD_, 1.f);
    fold_bias<<<1, 256, 0, sNode>>>(bv, wxo, bxo, bvx);
    gemm_kernel<false><<<grid_of(ROWS_X, XD_), blk, 0, sNode>>>(x, wvx, bvx, newX, ROWS_X, XD_, XD_, 1.f);
    ln_kernel<<<ROWS_X, XD_, 0, sNode>>>(x, newX, gnx, bnx, hx);
    gemm_kernel<true ><<<grid_of(ROWS_X, FFX), blk, 0, sNode>>>(hx,  wx1, bx1, h1x, ROWS_X, FFX, XD_, 1.f);
    gemm_kernel<false><<<grid_of(ROWS_X, XD_), blk, 0, sNode>>>(h1x, wx2, bx2, h2x, ROWS_X, XD_, FFX, 1.f);
    ln_kernel<<<ROWS_X, XD_, 0, sNode>>>(x, h2x, gnx, bnx, x_out);
    cudaEventRecord(evJoin, sNode);

    // main stream: prep + Q/K + edge pipeline
    prep_all<<<14, 256, 128 * 129 * 4>>>(wem, wea, weo, we1, we2,
                                         wemP, weaP, weoP, we1P, we2P);
    gemm_kernel<false><<<grid_of(ROWS_X, XD_), blk>>>(x, wq, bq, Q,  ROWS_X, XD_, XD_, INV_SQRT_DF);
    gemm_kernel<false><<<grid_of(ROWS_X, XD_), blk>>>(x, wk, bk, Km, ROWS_X, XD_, XD_, 1.f);

    edge_attn_kernel<<<ROWS_E / 128, blk, FA_BYTES>>>(
        e, Q, Km, wemP, weaP, weoP, bem, bea, beo, gne, bne, he);
    edge_ff_kernel<<<ROWS_E / 128, blk, FB_BYTES>>>(
        he, e, we1P, we2P, be1, be2, gne, bne, e_out);

    // ---- join ----
    cudaStreamWaitEvent(0, evJoin, 0);
}

// round 9
// speedup vs baseline: 4.0869x; 1.1932x over previous
#include <cuda_runtime.h>
#include <cuda_bf16.h>
#include <math.h>
#include <stdint.h>

#define BB  8
#define NN  128
#define XD_ 256
#define ED_ 128
#define FFX 1024
#define FFE 512
#define ROWS_X (BB*NN)
#define ROWS_E (BB*NN*NN)
#define INV_SQRT_DF 0.17677669529663687f

#define PITCH   272           // bytes per bf16 tile row (136 bf16)
#define TILE_W  34816         // 128 * 272 (one bf16 128x128 tile)

// ---------------- scratch ----------------
__device__ float g_Q   [ROWS_X * XD_];
__device__ float g_Km  [ROWS_X * XD_];
__device__ float g_newX[ROWS_X * XD_];
__device__ float g_hx  [ROWS_X * XD_];
__device__ float g_h1x [ROWS_X * FFX];
__device__ float g_h2x [ROWS_X * XD_];
__device__ float g_wvx [XD_ * XD_];
__device__ float g_bvx [XD_];
__device__ float g_zero[FFX];
__device__ __nv_bfloat16 g_he[(size_t)ROWS_E * ED_];
__device__ __align__(16) char g_wemP[2 * TILE_W];
__device__ __align__(16) char g_weaP[2 * TILE_W];
__device__ __align__(16) char g_weoP[2 * TILE_W];
__device__ __align__(16) char g_we1P[4 * TILE_W];
__device__ __align__(16) char g_we2P[4 * TILE_W];

// ---------------- helpers ----------------
__device__ __forceinline__ uint32_t smem_u32(const void* p) {
    uint32_t a;
    asm("{ .reg .u64 t; cvta.to.shared.u64 t, %1; cvt.u32.u64 %0, t; }" : "=r"(a) : "l"(p));
    return a;
}

#define CPA16(dst, src) asm volatile("cp.async.cg.shared.global [%0], [%1], 16;" :: "r"(dst), "l"(src))
#define CP_COMMIT() asm volatile("cp.async.commit_group;" ::: "memory")
#define CP_WAIT0()  asm volatile("cp.async.wait_group 0;" ::: "memory")

__device__ __forceinline__ void prefetch_w(uint32_t dstS, const char* src, int tid) {
    #pragma unroll 4
    for (int t = tid; t < 2176; t += 256)
        CPA16(dstS + (uint32_t)t * 16, src + (size_t)t * 16);
    CP_COMMIT();
}

__device__ __forceinline__ void mma16816(float* c, uint32_t a0, uint32_t a1, uint32_t a2,
                                         uint32_t a3, uint32_t b0, uint32_t b1) {
    asm volatile(
        "mma.sync.aligned.m16n8k16.row.col.f32.bf16.bf16.f32 "
        "{%0,%1,%2,%3},{%4,%5,%6,%7},{%8,%9},{%0,%1,%2,%3};"
        : "+f"(c[0]), "+f"(c[1]), "+f"(c[2]), "+f"(c[3])
        : "r"(a0), "r"(a1), "r"(a2), "r"(a3), "r"(b0), "r"(b1));
}

__device__ __forceinline__ void ldsm4(uint32_t& r0, uint32_t& r1, uint32_t& r2, uint32_t& r3,
                                      uint32_t a) {
    asm volatile("ldmatrix.sync.aligned.m8n8.x4.shared.b16 {%0,%1,%2,%3},[%4];"
                 : "=r"(r0), "=r"(r1), "=r"(r2), "=r"(r3) : "r"(a));
}

__device__ __forceinline__ void ldA8(uint32_t a[8], uint32_t base, int r0, int k0, int lane) {
    uint32_t addr = base + (uint32_t)(r0 + (lane & 15)) * PITCH
                  + (uint32_t)(k0 + ((lane >> 4) << 3)) * 2;
    ldsm4(a[0], a[1], a[2], a[3], addr);
    ldsm4(a[4], a[5], a[6], a[7], addr + 16 * PITCH);
}

__device__ __forceinline__ void ldB16(uint32_t b[16], uint32_t base, int n0, int k0, int lane) {
    uint32_t addr = base + (uint32_t)(n0 + ((lane >> 4) << 3) + (lane & 7)) * PITCH
                  + (uint32_t)(k0 + (((lane >> 3) & 1) << 3)) * 2;
    ldsm4(b[0],  b[1],  b[2],  b[3],  addr);
    ldsm4(b[4],  b[5],  b[6],  b[7],  addr + 16 * PITCH);
    ldsm4(b[8],  b[9],  b[10], b[11], addr + 32 * PITCH);
    ldsm4(b[12], b[13], b[14], b[15], addr + 48 * PITCH);
}

__device__ __forceinline__ void mma_pass(float (&acc)[2][8][4], const uint32_t a[8],
                                         const uint32_t b[16]) {
    #pragma unroll
    for (int mf = 0; mf < 2; mf++)
        #pragma unroll
        for (int nf = 0; nf < 8; nf++)
            mma16816(acc[mf][nf], a[mf*4], a[mf*4+1], a[mf*4+2], a[mf*4+3],
                     b[nf*2], b[nf*2+1]);
}

// 1-pass bf16 GEMM tile (K=128)
__device__ __forceinline__ void compute_ktile(float (&acc)[2][8][4], uint32_t aB,
                                              uint32_t bB, int wm, int wn, int lane) {
    #pragma unroll 1
    for (int ks = 0; ks < 8; ks++) {
        uint32_t ah[8], bh[16];
        ldA8(ah, aB, wm * 32, ks * 16, lane);
        ldB16(bh, bB, wn * 64, ks * 16, lane);
        mma_pass(acc, ah, bh);
    }
}

__device__ __forceinline__ uint32_t pkf2(float x, float y) {
    __nv_bfloat162 t = __floats2bfloat162_rn(x, y);
    return *reinterpret_cast<uint32_t*>(&t);
}
__device__ __forceinline__ float2 unpk2(uint32_t u) {
    __nv_bfloat162 t = *reinterpret_cast<__nv_bfloat162*>(&u);
    return make_float2(__bfloat162float(t.x), __bfloat162float(t.y));
}

__device__ __forceinline__ void stage_a_fp32(char* sm, const float* src, int stride, int tid) {
    #pragma unroll 4
    for (int t = tid; t < 4096; t += 256) {
        int r = t >> 5, c4 = (t & 31) << 2;
        float4 v = *(const float4*)(src + (size_t)r * stride + c4);
        uint32_t p0 = pkf2(v.x, v.y);
        uint32_t p1 = pkf2(v.z, v.w);
        *(uint2*)(sm + (uint32_t)r * PITCH + (uint32_t)c4 * 2) = make_uint2(p0, p1);
    }
}

__device__ __forceinline__ void stage_a_bf16(char* sm, const __nv_bfloat16* src, size_t row0,
                                             int stride, int tid) {
    #pragma unroll 4
    for (int t = tid; t < 2048; t += 256) {
        int r = t >> 4, c8 = (t & 15) << 3;
        *(uint4*)(sm + (uint32_t)r * PITCH + (uint32_t)c8 * 2) =
            *(const uint4*)(src + (row0 + r) * (size_t)stride + c8);
    }
}

// ---------------- merged weight prep: one block per 128x128 tile, coalesced ----------------
__global__ void prep_all(const float* __restrict__ wem, const float* __restrict__ wea,
                         const float* __restrict__ weo, const float* __restrict__ we1,
                         const float* __restrict__ we2,
                         char* __restrict__ wemP, char* __restrict__ weaP,
                         char* __restrict__ weoP, char* __restrict__ we1P,
                         char* __restrict__ we2P)
{
    extern __shared__ float tl[];   // 128 x 129
    int s = blockIdx.x;
    const float* W; char* out; int K, N, kc, nc;
    if (s < 2)       { W = wem; out = wemP + (size_t)s       * TILE_W; K = 128; N = 256; kc = 0;      nc = s;     }
    else if (s < 4)  { W = wea; out = weaP + (size_t)(s - 2) * TILE_W; K = 128; N = 256; kc = 0;      nc = s - 2; }
    else if (s < 6)  { W = weo; out = weoP + (size_t)(s - 4) * TILE_W; K = 256; N = 128; kc = s - 4;  nc = 0;     }
    else if (s < 10) { W = we1; out = we1P + (size_t)(s - 6) * TILE_W; K = 128; N = 512; kc = 0;      nc = s - 6; }
    else             { W = we2; out = we2P + (size_t)(s - 10)* TILE_W; K = 512; N = 128; kc = s - 10; nc = 0;     }
    int tid = threadIdx.x;
    for (int t = tid; t < 16384; t += 256) {
        int k = t >> 7, n = t & 127;
        tl[k * 129 + n] = W[(size_t)(kc * 128 + k) * N + nc * 128 + n];
    }
    __syncthreads();
    for (int t = tid; t < 8192; t += 256) {
        int n = t >> 6, k = (t & 63) << 1;
        float v0 = tl[k * 129 + n], v1 = tl[(k + 1) * 129 + n];
        *(uint32_t*)(out + (uint32_t)n * PITCH + (uint32_t)k * 2) = pkf2(v0, v1);
    }
}

__global__ void fold_bias(const float* __restrict__ bv, const float* __restrict__ wxo,
                          const float* __restrict__ bxo, float* __restrict__ bvx) {
    int n = threadIdx.x;
    float s = bxo[n];
    for (int k = 0; k < XD_; ++k) s += bv[k] * wxo[k * XD_ + n];
    bvx[n] = s;
}

// ================ fused edge attention: e -> he (bf16) ================
#define FA_A   0
#define FA_B0  34816
#define FA_B1  69632
#define FA_C   104448
#define FA_SM  139264
#define FA_BYTES (139264 + 6656)

__global__ void __launch_bounds__(256, 1) edge_attn_kernel(
    const float* __restrict__ e, const float* __restrict__ Qs, const float* __restrict__ Km,
    const char* __restrict__ wemP, const char* __restrict__ weaP, const char* __restrict__ weoP,
    const float* __restrict__ bem, const float* __restrict__ bea, const float* __restrict__ beo,
    const float* __restrict__ gne, const float* __restrict__ bne,
    __nv_bfloat16* __restrict__ he)
{
    extern __shared__ char sm[];
    const int tid = threadIdx.x;
    const int lane = tid & 31, w = tid >> 5;
    const int wm = w & 3, wn = w >> 2;
    const int g = lane >> 2, q = lane & 3;
    const int blk = blockIdx.x;
    const size_t row0 = (size_t)blk * 128;
    const int b = blk >> 7, i = blk & 127;

    uint32_t smB = smem_u32(sm);
    float* qS   = (float*)(sm + FA_SM);            // 256
    float* bemS = qS + 256;                         // 256
    float* beaS = bemS + 256;                       // 256
    float* beoS = beaS + 256;                       // 128
    float* gneS = beoS + 128;                       // 128
    float* bneS = gneS + 128;                       // 128
    float* red  = bneS + 128;                       // 256
    float* red2 = red + 256;                        // 256

    const uint32_t aB = smB + FA_A;
    const uint32_t cB = smB + FA_C;
    const uint32_t Bb[2] = {smB + FA_B0, smB + FA_B1};
    const char* tiles[6] = {weaP, wemP, weoP,
                            weaP + TILE_W, wemP + TILE_W, weoP + TILE_W};

    prefetch_w(Bb[0], tiles[0], tid);               // tile 0 in flight
    stage_a_fp32(sm + FA_A, e + row0 * ED_, ED_, tid);
    qS[tid]   = Qs[((size_t)(b * NN + i)) * XD_ + tid];
    bemS[tid] = bem[tid];
    beaS[tid] = bea[tid];
    if (tid < 128) { beoS[tid] = beo[tid]; gneS[tid] = gne[tid]; bneS[tid] = bne[tid]; }
    CP_WAIT0(); __syncthreads();
    prefetch_w(Bb[1], tiles[1], tid);               // tile 1 in flight

    float accNE[2][8][4] = {};

    #pragma unroll 1
    for (int nc = 0; nc < 2; nc++) {
        const int t0 = nc * 3;
        // ---- tile t0 (wea[nc]) ready in Bb[t0&1]: E2 = e@wea + bea -> bf16 into C
        {
            float acc[2][8][4] = {};
            compute_ktile(acc, aB, Bb[t0 & 1], wm, wn, lane);
            #pragma unroll
            for (int mf = 0; mf < 2; mf++)
            #pragma unroll
            for (int h = 0; h < 2; h++) {
                int r = wm * 32 + mf * 16 + h * 8 + g;
                #pragma unroll
                for (int nf = 0; nf < 8; nf++) {
                    int cl = wn * 64 + nf * 8 + q * 2;
                    int cg = nc * 128 + cl;
                    *(uint32_t*)(sm + FA_C + (uint32_t)r * PITCH + (uint32_t)cl * 2) =
                        pkf2(acc[mf][nf][h*2] + beaS[cg], acc[mf][nf][h*2+1] + beaS[cg+1]);
                }
            }
        }
        CP_WAIT0(); __syncthreads();
        if (t0 + 2 < 6) prefetch_w(Bb[t0 & 1], tiles[t0 + 2], tid);
        // ---- tile t0+1 (wem[nc]): E1 = e@wem; Y epilogue in-place into C
        {
            float acc[2][8][4] = {};
            compute_ktile(acc, aB, Bb[(t0 + 1) & 1], wm, wn, lane);
            #pragma unroll
            for (int mf = 0; mf < 2; mf++)
            #pragma unroll
            for (int h = 0; h < 2; h++) {
                int r = wm * 32 + mf * 16 + h * 8 + g;
                const float* kp = Km + ((size_t)(b * NN + r)) * XD_ + nc * 128;
                #pragma unroll
                for (int nf = 0; nf < 8; nf++) {
                    int cl = wn * 64 + nf * 8 + q * 2;
                    int cg = nc * 128 + cl;
                    uint32_t off = (uint32_t)r * PITCH + (uint32_t)cl * 2;
                    float2 e2 = unpk2(*(uint32_t*)(sm + FA_C + off));
                    float2 km = *(const float2*)(kp + cl);
                    float e1a = acc[mf][nf][h*2]   + bemS[cg]   + 1.f;
                    float e1b = acc[mf][nf][h*2+1] + bemS[cg+1] + 1.f;
                    float y0 = qS[cg]   * km.x * e1a + e2.x;
                    float y1 = qS[cg+1] * km.y * e1b + e2.y;
                    *(uint32_t*)(sm + FA_C + off) = pkf2(y0, y1);
                }
            }
        }
        CP_WAIT0(); __syncthreads();
        if (t0 + 3 < 6) prefetch_w(Bb[(t0 + 1) & 1], tiles[t0 + 3], tid);
        // ---- tile t0+2 (weo[nc]): newE += Y @ weo
        compute_ktile(accNE, cB, Bb[t0 & 1], wm, wn, lane);
        CP_WAIT0(); __syncthreads();
        if (t0 + 4 < 6) prefetch_w(Bb[t0 & 1], tiles[t0 + 4], tid);
    }

    // ---- epilogue: he = LN(e + newE + beo) * gne + bne (e re-read fp32)
    #pragma unroll
    for (int mf = 0; mf < 2; mf++)
    #pragma unroll
    for (int h = 0; h < 2; h++) {
        int r = wm * 32 + mf * 16 + h * 8 + g;
        #pragma unroll
        for (int nf = 0; nf < 8; nf++) {
            int cl = wn * 64 + nf * 8 + q * 2;
            float2 ev = *(const float2*)(e + (row0 + r) * ED_ + cl);
            accNE[mf][nf][h*2+0] += beoS[cl]   + ev.x;
            accNE[mf][nf][h*2+1] += beoS[cl+1] + ev.y;
        }
    }
    float mean[2][2], rstd[2][2];
    #pragma unroll
    for (int mf = 0; mf < 2; mf++)
    #pragma unroll
    for (int h = 0; h < 2; h++) {
        float s = 0.f;
        #pragma unroll
        for (int nf = 0; nf < 8; nf++) s += accNE[mf][nf][h*2] + accNE[mf][nf][h*2+1];
        s += __shfl_xor_sync(0xffffffffu, s, 1);
        s += __shfl_xor_sync(0xffffffffu, s, 2);
        if (q == 0) red[wn * 128 + wm * 32 + mf * 16 + h * 8 + g] = s;
    }
    __syncthreads();
    #pragma unroll
    for (int mf = 0; mf < 2; mf++)
    #pragma unroll
    for (int h = 0; h < 2; h++) {
        int r = wm * 32 + mf * 16 + h * 8 + g;
        mean[mf][h] = (red[r] + red[128 + r]) * (1.f / 128.f);
        float s = 0.f;
        #pragma unroll
        for (int nf = 0; nf < 8; nf++) {
            float d0 = accNE[mf][nf][h*2]   - mean[mf][h];
            float d1 = accNE[mf][nf][h*2+1] - mean[mf][h];
            s += d0 * d0 + d1 * d1;
        }
        s += __shfl_xor_sync(0xffffffffu, s, 1);
        s += __shfl_xor_sync(0xffffffffu, s, 2);
        if (q == 0) red2[wn * 128 + r] = s;
    }
    __syncthreads();
    #pragma unroll
    for (int mf = 0; mf < 2; mf++)
    #pragma unroll
    for (int h = 0; h < 2; h++) {
        int r = wm * 32 + mf * 16 + h * 8 + g;
        rstd[mf][h] = rsqrtf((red2[r] + red2[128 + r]) * (1.f / 128.f) + 1e-5f);
        #pragma unroll
        for (int nf = 0; nf < 8; nf++) {
            int cl = wn * 64 + nf * 8 + q * 2;
            float o0 = (accNE[mf][nf][h*2]   - mean[mf][h]) * rstd[mf][h] * gneS[cl]   + bneS[cl];
            float o1 = (accNE[mf][nf][h*2+1] - mean[mf][h]) * rstd[mf][h] * gneS[cl+1] + bneS[cl+1];
            *(uint32_t*)((char*)he + ((row0 + r) * ED_ + cl) * 2) = pkf2(o0, o1);
        }
    }
}

// ================ fused edge FF: he -> e_out ================
#define FB_A   0
#define FB_B0  34816
#define FB_B1  69632
#define FB_C   104448
#define FB_SM  139264
#define FB_BYTES (139264 + 5632)

__global__ void __launch_bounds__(256, 1) edge_ff_kernel(
    const __nv_bfloat16* __restrict__ he, const float* __restrict__ e,
    const char* __restrict__ we1P, const char* __restrict__ we2P,
    const float* __restrict__ be1, const float* __restrict__ be2,
    const float* __restrict__ gne, const float* __restrict__ bne,
    float* __restrict__ e_out)
{
    extern __shared__ char sm[];
    const int tid = threadIdx.x;
    const int lane = tid & 31, w = tid >> 5;
    const int wm = w & 3, wn = w >> 2;
    const int g = lane >> 2, q = lane & 3;
    const size_t row0 = (size_t)blockIdx.x * 128;

    uint32_t smB = smem_u32(sm);
    float* be1S = (float*)(sm + FB_SM);    // 512
    float* be2S = be1S + 512;              // 128
    float* gneS = be2S + 128;              // 128
    float* bneS = gneS + 128;              // 128
    float* red  = bneS + 128;              // 256
    float* red2 = red + 256;               // 256

    const uint32_t aB = smB + FB_A;
    const uint32_t cB = smB + FB_C;
    const uint32_t Bb[2] = {smB + FB_B0, smB + FB_B1};
    const char* tiles[8] = {we1P,             we2P,
                            we1P + TILE_W,     we2P + TILE_W,
                            we1P + 2 * TILE_W, we2P + 2 * TILE_W,
                            we1P + 3 * TILE_W, we2P + 3 * TILE_W};

    prefetch_w(Bb[0], tiles[0], tid);
    stage_a_bf16(sm + FB_A, he, row0, ED_, tid);
    for (int t = tid; t < 512; t += 256) be1S[t] = be1[t];
    if (tid < 128) { be2S[tid] = be2[tid]; gneS[tid] = gne[tid]; bneS[tid] = bne[tid]; }
    CP_WAIT0(); __syncthreads();
    prefetch_w(Bb[1], tiles[1], tid);

    float accH2[2][8][4] = {};

    #pragma unroll 1
    for (int p = 0; p < 4; p++) {
        const int i0 = p * 2;
        // ---- tile i0 (we1[p]): h1 = relu(he@we1 + be1) -> bf16 into C
        {
            float acc[2][8][4] = {};
            compute_ktile(acc, aB, Bb[i0 & 1], wm, wn, lane);
            #pragma unroll
            for (int mf = 0; mf < 2; mf++)
            #pragma unroll
            for (int h = 0; h < 2; h++) {
                int r = wm * 32 + mf * 16 + h * 8 + g;
                #pragma unroll
                for (int nf = 0; nf < 8; nf++) {
                    int cl = wn * 64 + nf * 8 + q * 2;
                    int cgl = p * 128 + cl;
                    float o0 = fmaxf(acc[mf][nf][h*2]   + be1S[cgl],   0.f);
                    float o1 = fmaxf(acc[mf][nf][h*2+1] + be1S[cgl+1], 0.f);
                    *(uint32_t*)(sm + FB_C + (uint32_t)r * PITCH + (uint32_t)cl * 2) = pkf2(o0, o1);
                }
            }
        }
        CP_WAIT0(); __syncthreads();
        if (i0 + 2 < 8) prefetch_w(Bb[i0 & 1], tiles[i0 + 2], tid);
        // ---- tile i0+1 (we2[p]): h2 += h1chunk @ we2
        compute_ktile(accH2, cB, Bb[(i0 + 1) & 1], wm, wn, lane);
        CP_WAIT0(); __syncthreads();
        if (i0 + 3 < 8) prefetch_w(Bb[(i0 + 1) & 1], tiles[i0 + 3], tid);
    }

    // epilogue: e_out = LN(e + h2 + be2) * gne + bne
    #pragma unroll
    for (int mf = 0; mf < 2; mf++)
    #pragma unroll
    for (int h = 0; h < 2; h++) {
        int r = wm * 32 + mf * 16 + h * 8 + g;
        #pragma unroll
        for (int nf = 0; nf < 8; nf++) {
            int cl = wn * 64 + nf * 8 + q * 2;
            float2 ev = *(const float2*)(e + (row0 + r) * ED_ + cl);
            accH2[mf][nf][h*2+0] += be2S[cl]   + ev.x;
            accH2[mf][nf][h*2+1] += be2S[cl+1] + ev.y;
        }
    }
    float mean[2][2], rstd[2][2];
    #pragma unroll
    for (int mf = 0; mf < 2; mf++)
    #pragma unroll
    for (int h = 0; h < 2; h++) {
        float s = 0.f;
        #pragma unroll
        for (int nf = 0; nf < 8; nf++) s += accH2[mf][nf][h*2] + accH2[mf][nf][h*2+1];
        s += __shfl_xor_sync(0xffffffffu, s, 1);
        s += __shfl_xor_sync(0xffffffffu, s, 2);
        if (q == 0) red[wn * 128 + wm * 32 + mf * 16 + h * 8 + g] = s;
    }
    __syncthreads();
    #pragma unroll
    for (int mf = 0; mf < 2; mf++)
    #pragma unroll
    for (int h = 0; h < 2; h++) {
        int r = wm * 32 + mf * 16 + h * 8 + g;
        mean[mf][h] = (red[r] + red[128 + r]) * (1.f / 128.f);
        float s = 0.f;
        #pragma unroll
        for (int nf = 0; nf < 8; nf++) {
            float d0 = accH2[mf][nf][h*2]   - mean[mf][h];
            float d1 = accH2[mf][nf][h*2+1] - mean[mf][h];
            s += d0 * d0 + d1 * d1;
        }
        s += __shfl_xor_sync(0xffffffffu, s, 1);
        s += __shfl_xor_sync(0xffffffffu, s, 2);
        if (q == 0) red2[wn * 128 + r] = s;
    }
    __syncthreads();
    #pragma unroll
    for (int mf = 0; mf < 2; mf++)
    #pragma unroll
    for (int h = 0; h < 2; h++) {
        int r = wm * 32 + mf * 16 + h * 8 + g;
        rstd[mf][h] = rsqrtf((red2[r] + red2[128 + r]) * (1.f / 128.f) + 1e-5f);
        #pragma unroll
        for (int nf = 0; nf < 8; nf++) {
            int cl = wn * 64 + nf * 8 + q * 2;
            float o0 = (accH2[mf][nf][h*2]   - mean[mf][h]) * rstd[mf][h] * gneS[cl]   + bneS[cl];
            float o1 = (accH2[mf][nf][h*2+1] - mean[mf][h]) * rstd[mf][h] * gneS[cl+1] + bneS[cl+1];
            *(float2*)(e_out + (row0 + r) * ED_ + cl) = make_float2(o0, o1);
        }
    }
}

// ---------------- node-side SIMT GEMM + LN ----------------
template<bool RELU>
__global__ void __launch_bounds__(256) gemm_kernel(
    const float* __restrict__ A, const float* __restrict__ W,
    const float* __restrict__ bias, float* __restrict__ C,
    int M, int N, int K, float alpha)
{
    __shared__ __align__(16) float aS[64][68];
    __shared__ __align__(16) float wS[64][68];
    const int tid = threadIdx.x;
    const int tx  = tid & 15;
    const int ty  = tid >> 4;
    const size_t row0 = (size_t)blockIdx.y * 64;
    const int    col0 = blockIdx.x * 64;
    float acc[4][4] = {};
    for (int k0 = 0; k0 < K; k0 += 64) {
        #pragma unroll
        for (int t = tid; t < 1024; t += 256) {
            int r = t >> 4, c4 = (t & 15) << 2;
            float4 av = *(const float4*)(A + (row0 + r) * K + k0 + c4);
            aS[r][c4+0]=av.x; aS[r][c4+1]=av.y; aS[r][c4+2]=av.z; aS[r][c4+3]=av.w;
            float4 wv = *(const float4*)(W + (size_t)(k0 + r) * N + col0 + c4);
            wS[r][c4+0]=wv.x; wS[r][c4+1]=wv.y; wS[r][c4+2]=wv.z; wS[r][c4+3]=wv.w;
        }
        __syncthreads();
        #pragma unroll 16
        for (int k = 0; k < 64; ++k) {
            float a0=aS[ty*4+0][k], a1=aS[ty*4+1][k], a2=aS[ty*4+2][k], a3=aS[ty*4+3][k];
            float4 bv = *(const float4*)&wS[k][tx*4];
            acc[0][0]+=a0*bv.x; acc[0][1]+=a0*bv.y; acc[0][2]+=a0*bv.z; acc[0][3]+=a0*bv.w;
            acc[1][0]+=a1*bv.x; acc[1][1]+=a1*bv.y; acc[1][2]+=a1*bv.z; acc[1][3]+=a1*bv.w;
            acc[2][0]+=a2*bv.x; acc[2][1]+=a2*bv.y; acc[2][2]+=a2*bv.z; acc[2][3]+=a2*bv.w;
            acc[3][0]+=a3*bv.x; acc[3][1]+=a3*bv.y; acc[3][2]+=a3*bv.z; acc[3][3]+=a3*bv.w;
        }
        __syncthreads();
    }
    const int c = col0 + tx * 4;
    float b0=bias[c+0], b1=bias[c+1], b2=bias[c+2], b3=bias[c+3];
    #pragma unroll
    for (int m = 0; m < 4; ++m) {
        float4 o;
        o.x = alpha*(acc[m][0]+b0); o.y = alpha*(acc[m][1]+b1);
        o.z = alpha*(acc[m][2]+b2); o.w = alpha*(acc[m][3]+b3);
        if (RELU) { o.x=fmaxf(o.x,0.f); o.y=fmaxf(o.y,0.f); o.z=fmaxf(o.z,0.f); o.w=fmaxf(o.w,0.f); }
        *(float4*)(C + (row0 + ty*4 + m) * N + c) = o;
    }
}

__global__ void ln_kernel(const float* __restrict__ A, const float* __restrict__ Bv,
                          const float* __restrict__ g, const float* __restrict__ be,
                          float* __restrict__ out)
{
    __shared__ float red[8];
    const int D = blockDim.x;
    const size_t base = (size_t)blockIdx.x * D + threadIdx.x;
    const int lane = threadIdx.x & 31;
    const int w    = threadIdx.x >> 5;
    const int nw   = D >> 5;
    float v = A[base] + Bv[base];
    float s = v;
    #pragma unroll
    for (int o = 16; o; o >>= 1) s += __shfl_xor_sync(0xffffffffu, s, o);
    if (lane == 0) red[w] = s;
    __syncthreads();
    float tot = 0.f;
    for (int ww = 0; ww < nw; ++ww) tot += red[ww];
    float mean = tot / (float)D;
    float d = v - mean;
    __syncthreads();
    float s2 = d * d;
    #pragma unroll
    for (int o = 16; o; o >>= 1) s2 += __shfl_xor_sync(0xffffffffu, s2, o);
    if (lane == 0) red[w] = s2;
    __syncthreads();
    float tot2 = 0.f;
    for (int ww = 0; ww < nw; ++ww) tot2 += red[ww];
    float var = tot2 / (float)D;
    out[base] = d * rsqrtf(var + 1e-5f) * g[threadIdx.x] + be[threadIdx.x];
}

// ---------------- launcher ----------------
extern "C" void kernel_launch(void* const* d_in, const int* in_sizes, int n_in,
                              void* d_out, int out_size)
{
    const float* x   = (const float*)d_in[0];
    const float* e   = (const float*)d_in[1];
    const float* wq  = (const float*)d_in[2];
    const float* wk  = (const float*)d_in[3];
    const float* wv  = (const float*)d_in[4];
    const float* wem = (const float*)d_in[5];
    const float* wea = (const float*)d_in[6];
    const float* wxo = (const float*)d_in[7];
    const float* weo = (const float*)d_in[8];
    const float* wx1 = (const float*)d_in[9];
    const float* wx2 = (const float*)d_in[10];
    const float* we1 = (const float*)d_in[11];
    const float* we2 = (const float*)d_in[12];
    const float* bq  = (const float*)d_in[13];
    const float* bk  = (const float*)d_in[14];
    const float* bv  = (const float*)d_in[15];
    const float* bem = (const float*)d_in[16];
    const float* bea = (const float*)d_in[17];
    const float* bxo = (const float*)d_in[18];
    const float* beo = (const float*)d_in[19];
    const float* bx1 = (const float*)d_in[20];
    const float* bx2 = (const float*)d_in[21];
    const float* be1 = (const float*)d_in[22];
    const float* be2 = (const float*)d_in[23];
    const float* gnx = (const float*)d_in[24];
    const float* bnx = (const float*)d_in[25];
    const float* gne = (const float*)d_in[26];
    const float* bne = (const float*)d_in[27];

    float* x_out = (float*)d_out;
    float* e_out = (float*)d_out + (size_t)ROWS_X * XD_;

    float *Q, *Km, *newX, *hx, *h1x, *h2x, *wvx, *bvx, *zero;
    __nv_bfloat16 *he;
    char *wemP, *weaP, *weoP, *we1P, *we2P;
    cudaGetSymbolAddress((void**)&Q,    g_Q);
    cudaGetSymbolAddress((void**)&Km,   g_Km);
    cudaGetSymbolAddress((void**)&newX, g_newX);
    cudaGetSymbolAddress((void**)&hx,   g_hx);
    cudaGetSymbolAddress((void**)&h1x,  g_h1x);
    cudaGetSymbolAddress((void**)&h2x,  g_h2x);
    cudaGetSymbolAddress((void**)&wvx,  g_wvx);
    cudaGetSymbolAddress((void**)&bvx,  g_bvx);
    cudaGetSymbolAddress((void**)&zero, g_zero);
    cudaGetSymbolAddress((void**)&he,   g_he);
    cudaGetSymbolAddress((void**)&wemP, g_wemP);
    cudaGetSymbolAddress((void**)&weaP, g_weaP);
    cudaGetSymbolAddress((void**)&weoP, g_weoP);
    cudaGetSymbolAddress((void**)&we1P, g_we1P);
    cudaGetSymbolAddress((void**)&we2P, g_we2P);

    cudaFuncSetAttribute(edge_attn_kernel, cudaFuncAttributeMaxDynamicSharedMemorySize, FA_BYTES);
    cudaFuncSetAttribute(edge_ff_kernel,   cudaFuncAttributeMaxDynamicSharedMemorySize, FB_BYTES);
    cudaFuncSetAttribute(prep_all,         cudaFuncAttributeMaxDynamicSharedMemorySize, 128 * 129 * 4);

    // one-time side-stream/event setup (host objects only)
    static cudaStream_t sNode = nullptr;
    static cudaEvent_t evFork = nullptr, evJoin = nullptr;
    if (!sNode) {
        cudaStreamCreateWithFlags(&sNode, cudaStreamNonBlocking);
        cudaEventCreateWithFlags(&evFork, cudaEventDisableTiming);
        cudaEventCreateWithFlags(&evJoin, cudaEventDisableTiming);
    }

    dim3 blk(256);
    auto grid_of = [](int M, int N) { return dim3((unsigned)(N/64), (unsigned)(M/64)); };

    // ---- fork: node-side chain runs concurrently on sNode ----
    cudaEventRecord(evFork, 0);
    cudaStreamWaitEvent(sNode, evFork, 0);

    // node side on sNode (softmax collapses: wV == V; fold wv@wxo)
    gemm_kernel<false><<<grid_of(XD_, XD_), blk, 0, sNode>>>(wv, wxo, zero, wvx, XD_, XD_, XD_, 1.f);
    fold_bias<<<1, 256, 0, sNode>>>(bv, wxo, bxo, bvx);
    gemm_kernel<false><<<grid_of(ROWS_X, XD_), blk, 0, sNode>>>(x, wvx, bvx, newX, ROWS_X, XD_, XD_, 1.f);
    ln_kernel<<<ROWS_X, XD_, 0, sNode>>>(x, newX, gnx, bnx, hx);
    gemm_kernel<true ><<<grid_of(ROWS_X, FFX), blk, 0, sNode>>>(hx,  wx1, bx1, h1x, ROWS_X, FFX, XD_, 1.f);
    gemm_kernel<false><<<grid_of(ROWS_X, XD_), blk, 0, sNode>>>(h1x, wx2, bx2, h2x, ROWS_X, XD_, FFX, 1.f);
    ln_kernel<<<ROWS_X, XD_, 0, sNode>>>(x, h2x, gnx, bnx, x_out);
    cudaEventRecord(evJoin, sNode);

    // main stream: prep + Q/K + edge pipeline
    prep_all<<<14, 256, 128 * 129 * 4>>>(wem, wea, weo, we1, we2,
                                         wemP, weaP, weoP, we1P, we2P);
    gemm_kernel<false><<<grid_of(ROWS_X, XD_), blk>>>(x, wq, bq, Q,  ROWS_X, XD_, XD_, INV_SQRT_DF);
    gemm_kernel<false><<<grid_of(ROWS_X, XD_), blk>>>(x, wk, bk, Km, ROWS_X, XD_, XD_, 1.f);

    edge_attn_kernel<<<ROWS_E / 128, blk, FA_BYTES>>>(
        e, Q, Km, wemP, weaP, weoP, bem, bea, beo, gne, bne, he);
    edge_ff_kernel<<<ROWS_E / 128, blk, FB_BYTES>>>(
        he, e, we1P, we2P, be1, be2, gne, bne, e_out);

    // ---- join ----
    cudaStreamWaitEvent(0, evJoin, 0);
}

// round 10
// speedup vs baseline: 4.5660x; 1.1172x over previous
#include <cuda_runtime.h>
#include <cuda_bf16.h>
#include <math.h>
#include <stdint.h>

#define BB  8
#define NN  128
#define XD_ 256
#define ED_ 128
#define FFX 1024
#define FFE 512
#define ROWS_X (BB*NN)
#define ROWS_E (BB*NN*NN)
#define INV_SQRT_DF 0.17677669529663687f

#define PITCH   272           // bytes per bf16 tile row (136 bf16)
#define TILE_W  34816         // 128 * 272 (one bf16 128x128 tile)

// ---------------- scratch ----------------
__device__ float g_Q   [ROWS_X * XD_];
__device__ float g_Km  [ROWS_X * XD_];
__device__ float g_newX[ROWS_X * XD_];
__device__ float g_hx  [ROWS_X * XD_];
__device__ float g_h1x [ROWS_X * FFX];
__device__ float g_h2x [ROWS_X * XD_];
__device__ float g_wvx [XD_ * XD_];
__device__ float g_bvx [XD_];
__device__ float g_zero[FFX];
__device__ __align__(16) char g_wemP[2 * TILE_W];
__device__ __align__(16) char g_weaP[2 * TILE_W];
__device__ __align__(16) char g_weoP[2 * TILE_W];
__device__ __align__(16) char g_we1P[4 * TILE_W];
__device__ __align__(16) char g_we2P[4 * TILE_W];

// ---------------- helpers ----------------
__device__ __forceinline__ uint32_t smem_u32(const void* p) {
    uint32_t a;
    asm("{ .reg .u64 t; cvta.to.shared.u64 t, %1; cvt.u32.u64 %0, t; }" : "=r"(a) : "l"(p));
    return a;
}

#define CPA16(dst, src) asm volatile("cp.async.cg.shared.global [%0], [%1], 16;" :: "r"(dst), "l"(src))
#define CP_COMMIT() asm volatile("cp.async.commit_group;" ::: "memory")
#define CP_WAIT0()  asm volatile("cp.async.wait_group 0;" ::: "memory")

__device__ __forceinline__ void prefetch_w(uint32_t dstS, const char* src, int tid) {
    #pragma unroll 4
    for (int t = tid; t < 2176; t += 256)
        CPA16(dstS + (uint32_t)t * 16, src + (size_t)t * 16);
    CP_COMMIT();
}

__device__ __forceinline__ void mma16816(float* c, uint32_t a0, uint32_t a1, uint32_t a2,
                                         uint32_t a3, uint32_t b0, uint32_t b1) {
    asm volatile(
        "mma.sync.aligned.m16n8k16.row.col.f32.bf16.bf16.f32 "
        "{%0,%1,%2,%3},{%4,%5,%6,%7},{%8,%9},{%0,%1,%2,%3};"
        : "+f"(c[0]), "+f"(c[1]), "+f"(c[2]), "+f"(c[3])
        : "r"(a0), "r"(a1), "r"(a2), "r"(a3), "r"(b0), "r"(b1));
}

__device__ __forceinline__ void ldsm4(uint32_t& r0, uint32_t& r1, uint32_t& r2, uint32_t& r3,
                                      uint32_t a) {
    asm volatile("ldmatrix.sync.aligned.m8n8.x4.shared.b16 {%0,%1,%2,%3},[%4];"
                 : "=r"(r0), "=r"(r1), "=r"(r2), "=r"(r3) : "r"(a));
}

__device__ __forceinline__ void ldA8(uint32_t a[8], uint32_t base, int r0, int k0, int lane) {
    uint32_t addr = base + (uint32_t)(r0 + (lane & 15)) * PITCH
                  + (uint32_t)(k0 + ((lane >> 4) << 3)) * 2;
    ldsm4(a[0], a[1], a[2], a[3], addr);
    ldsm4(a[4], a[5], a[6], a[7], addr + 16 * PITCH);
}

__device__ __forceinline__ void ldB16(uint32_t b[16], uint32_t base, int n0, int k0, int lane) {
    uint32_t addr = base + (uint32_t)(n0 + ((lane >> 4) << 3) + (lane & 7)) * PITCH
                  + (uint32_t)(k0 + (((lane >> 3) & 1) << 3)) * 2;
    ldsm4(b[0],  b[1],  b[2],  b[3],  addr);
    ldsm4(b[4],  b[5],  b[6],  b[7],  addr + 16 * PITCH);
    ldsm4(b[8],  b[9],  b[10], b[11], addr + 32 * PITCH);
    ldsm4(b[12], b[13], b[14], b[15], addr + 48 * PITCH);
}

__device__ __forceinline__ void mma_pass(float (&acc)[2][8][4], const uint32_t a[8],
                                         const uint32_t b[16]) {
    #pragma unroll
    for (int mf = 0; mf < 2; mf++)
        #pragma unroll
        for (int nf = 0; nf < 8; nf++)
            mma16816(acc[mf][nf], a[mf*4], a[mf*4+1], a[mf*4+2], a[mf*4+3],
                     b[nf*2], b[nf*2+1]);
}

// 1-pass bf16 GEMM tile (K=128)
__device__ __forceinline__ void compute_ktile(float (&acc)[2][8][4], uint32_t aB,
                                              uint32_t bB, int wm, int wn, int lane) {
    #pragma unroll 2
    for (int ks = 0; ks < 8; ks++) {
        uint32_t ah[8], bh[16];
        ldA8(ah, aB, wm * 32, ks * 16, lane);
        ldB16(bh, bB, wn * 64, ks * 16, lane);
        mma_pass(acc, ah, bh);
    }
}

__device__ __forceinline__ uint32_t pkf2(float x, float y) {
    __nv_bfloat162 t = __floats2bfloat162_rn(x, y);
    return *reinterpret_cast<uint32_t*>(&t);
}
__device__ __forceinline__ float2 unpk2(uint32_t u) {
    __nv_bfloat162 t = *reinterpret_cast<__nv_bfloat162*>(&u);
    return make_float2(__bfloat162float(t.x), __bfloat162float(t.y));
}

__device__ __forceinline__ void stage_a_fp32(char* sm, const float* src, int stride, int tid) {
    #pragma unroll 4
    for (int t = tid; t < 4096; t += 256) {
        int r = t >> 5, c4 = (t & 31) << 2;
        float4 v = *(const float4*)(src + (size_t)r * stride + c4);
        uint32_t p0 = pkf2(v.x, v.y);
        uint32_t p1 = pkf2(v.z, v.w);
        *(uint2*)(sm + (uint32_t)r * PITCH + (uint32_t)c4 * 2) = make_uint2(p0, p1);
    }
}

// ---------------- merged weight prep ----------------
__global__ void prep_all(const float* __restrict__ wem, const float* __restrict__ wea,
                         const float* __restrict__ weo, const float* __restrict__ we1,
                         const float* __restrict__ we2,
                         char* __restrict__ wemP, char* __restrict__ weaP,
                         char* __restrict__ weoP, char* __restrict__ we1P,
                         char* __restrict__ we2P)
{
    extern __shared__ float tl[];   // 128 x 129
    int s = blockIdx.x;
    const float* W; char* out; int K, N, kc, nc;
    if (s < 2)       { W = wem; out = wemP + (size_t)s       * TILE_W; K = 128; N = 256; kc = 0;      nc = s;     }
    else if (s < 4)  { W = wea; out = weaP + (size_t)(s - 2) * TILE_W; K = 128; N = 256; kc = 0;      nc = s - 2; }
    else if (s < 6)  { W = weo; out = weoP + (size_t)(s - 4) * TILE_W; K = 256; N = 128; kc = s - 4;  nc = 0;     }
    else if (s < 10) { W = we1; out = we1P + (size_t)(s - 6) * TILE_W; K = 128; N = 512; kc = 0;      nc = s - 6; }
    else             { W = we2; out = we2P + (size_t)(s - 10)* TILE_W; K = 512; N = 128; kc = s - 10; nc = 0;     }
    int tid = threadIdx.x;
    for (int t = tid; t < 16384; t += 256) {
        int k = t >> 7, n = t & 127;
        tl[k * 129 + n] = W[(size_t)(kc * 128 + k) * N + nc * 128 + n];
    }
    __syncthreads();
    for (int t = tid; t < 8192; t += 256) {
        int n = t >> 6, k = (t & 63) << 1;
        float v0 = tl[k * 129 + n], v1 = tl[(k + 1) * 129 + n];
        *(uint32_t*)(out + (uint32_t)n * PITCH + (uint32_t)k * 2) = pkf2(v0, v1);
    }
}

__global__ void fold_bias(const float* __restrict__ bv, const float* __restrict__ wxo,
                          const float* __restrict__ bxo, float* __restrict__ bvx) {
    int n = threadIdx.x;
    float s = bxo[n];
    for (int k = 0; k < XD_; ++k) s += bv[k] * wxo[k * XD_ + n];
    bvx[n] = s;
}

// ================ fused edge kernel: e -> e_out (attn + FF, one pass) ================
#define R_A   0
#define R_B0  34816
#define R_B1  69632
#define R_C   104448
#define R_SM  139264
#define EF_BYTES (139264 + 9216)

__global__ void __launch_bounds__(256, 1) edge_fused_kernel(
    const float* __restrict__ e, const float* __restrict__ Qs, const float* __restrict__ Km,
    const char* __restrict__ wemP, const char* __restrict__ weaP, const char* __restrict__ weoP,
    const char* __restrict__ we1P, const char* __restrict__ we2P,
    const float* __restrict__ bem, const float* __restrict__ bea, const float* __restrict__ beo,
    const float* __restrict__ be1, const float* __restrict__ be2,
    const float* __restrict__ gne, const float* __restrict__ bne,
    float* __restrict__ e_out)
{
    extern __shared__ char sm[];
    const int tid = threadIdx.x;
    const int lane = tid & 31, w = tid >> 5;
    const int wm = w & 3, wn = w >> 2;
    const int g = lane >> 2, q = lane & 3;
    const int blk = blockIdx.x;
    const size_t row0 = (size_t)blk * 128;
    const int b = blk >> 7, i = blk & 127;

    uint32_t smB = smem_u32(sm);
    float* qS   = (float*)(sm + R_SM);              // 256
    float* bemS = qS + 256;                          // 256
    float* beaS = bemS + 256;                        // 256
    float* beoS = beaS + 256;                        // 128
    float* gneS = beoS + 128;                        // 128
    float* bneS = gneS + 128;                        // 128
    float* be1S = bneS + 128;                        // 512
    float* be2S = be1S + 512;                        // 128
    float* red  = be2S + 128;                        // 256
    float* red2 = red + 256;                         // 256

    const uint32_t aB = smB + R_A;
    const uint32_t cB = smB + R_C;
    const uint32_t Bb[2] = {smB + R_B0, smB + R_B1};
    const char* tiles[14] = {
        weaP, wemP, weoP, weaP + TILE_W, wemP + TILE_W, weoP + TILE_W,
        we1P,              we2P,
        we1P + TILE_W,     we2P + TILE_W,
        we1P + 2 * TILE_W, we2P + 2 * TILE_W,
        we1P + 3 * TILE_W, we2P + 3 * TILE_W};

    prefetch_w(Bb[0], tiles[0], tid);               // tile 0 in flight
    stage_a_fp32(sm + R_A, e + row0 * ED_, ED_, tid);
    qS[tid]   = Qs[((size_t)(b * NN + i)) * XD_ + tid];
    bemS[tid] = bem[tid];
    beaS[tid] = bea[tid];
    if (tid < 128) { beoS[tid] = beo[tid]; gneS[tid] = gne[tid]; bneS[tid] = bne[tid]; }
    if (tid < 128) be2S[tid] = be2[tid];
    for (int t = tid; t < 512; t += 256) be1S[t] = be1[t];
    CP_WAIT0(); __syncthreads();
    prefetch_w(Bb[1], tiles[1], tid);               // tile 1 in flight

    // =================== attention phase ===================
    float accNE[2][8][4] = {};

    #pragma unroll 1
    for (int nc = 0; nc < 2; nc++) {
        const int t0 = nc * 3;
        // ---- tile t0 (wea[nc]): E2 = e@wea + bea -> bf16 into C
        {
            float acc[2][8][4] = {};
            compute_ktile(acc, aB, Bb[t0 & 1], wm, wn, lane);
            #pragma unroll
            for (int mf = 0; mf < 2; mf++)
            #pragma unroll
            for (int h = 0; h < 2; h++) {
                int r = wm * 32 + mf * 16 + h * 8 + g;
                #pragma unroll
                for (int nf = 0; nf < 8; nf++) {
                    int cl = wn * 64 + nf * 8 + q * 2;
                    int cg = nc * 128 + cl;
                    *(uint32_t*)(sm + R_C + (uint32_t)r * PITCH + (uint32_t)cl * 2) =
                        pkf2(acc[mf][nf][h*2] + beaS[cg], acc[mf][nf][h*2+1] + beaS[cg+1]);
                }
            }
        }
        CP_WAIT0(); __syncthreads();
        prefetch_w(Bb[t0 & 1], tiles[t0 + 2], tid);
        // ---- tile t0+1 (wem[nc]): E1 = e@wem; Y epilogue in-place into C
        {
            float acc[2][8][4] = {};
            compute_ktile(acc, aB, Bb[(t0 + 1) & 1], wm, wn, lane);
            #pragma unroll
            for (int mf = 0; mf < 2; mf++)
            #pragma unroll
            for (int h = 0; h < 2; h++) {
                int r = wm * 32 + mf * 16 + h * 8 + g;
                const float* kp = Km + ((size_t)(b * NN + r)) * XD_ + nc * 128;
                #pragma unroll
                for (int nf = 0; nf < 8; nf++) {
                    int cl = wn * 64 + nf * 8 + q * 2;
                    int cg = nc * 128 + cl;
                    uint32_t off = (uint32_t)r * PITCH + (uint32_t)cl * 2;
                    float2 e2 = unpk2(*(uint32_t*)(sm + R_C + off));
                    float2 km = *(const float2*)(kp + cl);
                    float e1a = acc[mf][nf][h*2]   + bemS[cg]   + 1.f;
                    float e1b = acc[mf][nf][h*2+1] + bemS[cg+1] + 1.f;
                    float y0 = qS[cg]   * km.x * e1a + e2.x;
                    float y1 = qS[cg+1] * km.y * e1b + e2.y;
                    *(uint32_t*)(sm + R_C + off) = pkf2(y0, y1);
                }
            }
        }
        CP_WAIT0(); __syncthreads();
        prefetch_w(Bb[(t0 + 1) & 1], tiles[t0 + 3], tid);
        // ---- tile t0+2 (weo[nc]): newE += Y @ weo
        compute_ktile(accNE, cB, Bb[t0 & 1], wm, wn, lane);
        CP_WAIT0(); __syncthreads();
        prefetch_w(Bb[t0 & 1], tiles[t0 + 4], tid);
    }

    // ---- attn epilogue: he = LN(e + newE + beo)*gne + bne -> bf16 INTO A REGION
    #pragma unroll
    for (int mf = 0; mf < 2; mf++)
    #pragma unroll
    for (int h = 0; h < 2; h++) {
        int r = wm * 32 + mf * 16 + h * 8 + g;
        #pragma unroll
        for (int nf = 0; nf < 8; nf++) {
            int cl = wn * 64 + nf * 8 + q * 2;
            float2 ev = *(const float2*)(e + (row0 + r) * ED_ + cl);
            accNE[mf][nf][h*2+0] += beoS[cl]   + ev.x;
            accNE[mf][nf][h*2+1] += beoS[cl+1] + ev.y;
        }
    }
    {
        float mean[2][2], rstd[2][2];
        #pragma unroll
        for (int mf = 0; mf < 2; mf++)
        #pragma unroll
        for (int h = 0; h < 2; h++) {
            float s = 0.f;
            #pragma unroll
            for (int nf = 0; nf < 8; nf++) s += accNE[mf][nf][h*2] + accNE[mf][nf][h*2+1];
            s += __shfl_xor_sync(0xffffffffu, s, 1);
            s += __shfl_xor_sync(0xffffffffu, s, 2);
            if (q == 0) red[wn * 128 + wm * 32 + mf * 16 + h * 8 + g] = s;
        }
        __syncthreads();
        #pragma unroll
        for (int mf = 0; mf < 2; mf++)
        #pragma unroll
        for (int h = 0; h < 2; h++) {
            int r = wm * 32 + mf * 16 + h * 8 + g;
            mean[mf][h] = (red[r] + red[128 + r]) * (1.f / 128.f);
            float s = 0.f;
            #pragma unroll
            for (int nf = 0; nf < 8; nf++) {
                float d0 = accNE[mf][nf][h*2]   - mean[mf][h];
                float d1 = accNE[mf][nf][h*2+1] - mean[mf][h];
                s += d0 * d0 + d1 * d1;
            }
            s += __shfl_xor_sync(0xffffffffu, s, 1);
            s += __shfl_xor_sync(0xffffffffu, s, 2);
            if (q == 0) red2[wn * 128 + r] = s;
        }
        __syncthreads();
        #pragma unroll
        for (int mf = 0; mf < 2; mf++)
        #pragma unroll
        for (int h = 0; h < 2; h++) {
            int r = wm * 32 + mf * 16 + h * 8 + g;
            rstd[mf][h] = rsqrtf((red2[r] + red2[128 + r]) * (1.f / 128.f) + 1e-5f);
            #pragma unroll
            for (int nf = 0; nf < 8; nf++) {
                int cl = wn * 64 + nf * 8 + q * 2;
                float o0 = (accNE[mf][nf][h*2]   - mean[mf][h]) * rstd[mf][h] * gneS[cl]   + bneS[cl];
                float o1 = (accNE[mf][nf][h*2+1] - mean[mf][h]) * rstd[mf][h] * gneS[cl+1] + bneS[cl+1];
                // he -> A region, MMA layout (e-tile is dead now)
                *(uint32_t*)(sm + R_A + (uint32_t)r * PITCH + (uint32_t)cl * 2) = pkf2(o0, o1);
            }
        }
    }
    __syncthreads();   // he visible to all warps before FF ktiles

    // =================== FF phase (A = he, C = h1 chunks) ===================
    float accH2[2][8][4] = {};

    #pragma unroll 1
    for (int p = 0; p < 4; p++) {
        const int i0 = 6 + p * 2;
        // ---- tile i0 (we1[p]): h1 = relu(he@we1 + be1) -> bf16 into C
        {
            float acc[2][8][4] = {};
            compute_ktile(acc, aB, Bb[i0 & 1], wm, wn, lane);
            #pragma unroll
            for (int mf = 0; mf < 2; mf++)
            #pragma unroll
            for (int h = 0; h < 2; h++) {
                int r = wm * 32 + mf * 16 + h * 8 + g;
                #pragma unroll
                for (int nf = 0; nf < 8; nf++) {
                    int cl = wn * 64 + nf * 8 + q * 2;
                    int cgl = p * 128 + cl;
                    float o0 = fmaxf(acc[mf][nf][h*2]   + be1S[cgl],   0.f);
                    float o1 = fmaxf(acc[mf][nf][h*2+1] + be1S[cgl+1], 0.f);
                    *(uint32_t*)(sm + R_C + (uint32_t)r * PITCH + (uint32_t)cl * 2) = pkf2(o0, o1);
                }
            }
        }
        CP_WAIT0(); __syncthreads();
        if (i0 + 2 < 14) prefetch_w(Bb[i0 & 1], tiles[i0 + 2], tid);
        // ---- tile i0+1 (we2[p]): h2 += h1chunk @ we2
        compute_ktile(accH2, cB, Bb[(i0 + 1) & 1], wm, wn, lane);
        CP_WAIT0(); __syncthreads();
        if (i0 + 3 < 14) prefetch_w(Bb[(i0 + 1) & 1], tiles[i0 + 3], tid);
    }

    // ---- FF epilogue: e_out = LN(e + h2 + be2) * gne + bne
    #pragma unroll
    for (int mf = 0; mf < 2; mf++)
    #pragma unroll
    for (int h = 0; h < 2; h++) {
        int r = wm * 32 + mf * 16 + h * 8 + g;
        #pragma unroll
        for (int nf = 0; nf < 8; nf++) {
            int cl = wn * 64 + nf * 8 + q * 2;
            float2 ev = *(const float2*)(e + (row0 + r) * ED_ + cl);
            accH2[mf][nf][h*2+0] += be2S[cl]   + ev.x;
            accH2[mf][nf][h*2+1] += be2S[cl+1] + ev.y;
        }
    }
    float mean[2][2], rstd[2][2];
    #pragma unroll
    for (int mf = 0; mf < 2; mf++)
    #pragma unroll
    for (int h = 0; h < 2; h++) {
        float s = 0.f;
        #pragma unroll
        for (int nf = 0; nf < 8; nf++) s += accH2[mf][nf][h*2] + accH2[mf][nf][h*2+1];
        s += __shfl_xor_sync(0xffffffffu, s, 1);
        s += __shfl_xor_sync(0xffffffffu, s, 2);
        if (q == 0) red[wn * 128 + wm * 32 + mf * 16 + h * 8 + g] = s;
    }
    __syncthreads();
    #pragma unroll
    for (int mf = 0; mf < 2; mf++)
    #pragma unroll
    for (int h = 0; h < 2; h++) {
        int r = wm * 32 + mf * 16 + h * 8 + g;
        mean[mf][h] = (red[r] + red[128 + r]) * (1.f / 128.f);
        float s = 0.f;
        #pragma unroll
        for (int nf = 0; nf < 8; nf++) {
            float d0 = accH2[mf][nf][h*2]   - mean[mf][h];
            float d1 = accH2[mf][nf][h*2+1] - mean[mf][h];
            s += d0 * d0 + d1 * d1;
        }
        s += __shfl_xor_sync(0xffffffffu, s, 1);
        s += __shfl_xor_sync(0xffffffffu, s, 2);
        if (q == 0) red2[wn * 128 + r] = s;
    }
    __syncthreads();
    #pragma unroll
    for (int mf = 0; mf < 2; mf++)
    #pragma unroll
    for (int h = 0; h < 2; h++) {
        int r = wm * 32 + mf * 16 + h * 8 + g;
        rstd[mf][h] = rsqrtf((red2[r] + red2[128 + r]) * (1.f / 128.f) + 1e-5f);
        #pragma unroll
        for (int nf = 0; nf < 8; nf++) {
            int cl = wn * 64 + nf * 8 + q * 2;
            float o0 = (accH2[mf][nf][h*2]   - mean[mf][h]) * rstd[mf][h] * gneS[cl]   + bneS[cl];
            float o1 = (accH2[mf][nf][h*2+1] - mean[mf][h]) * rstd[mf][h] * gneS[cl+1] + bneS[cl+1];
            *(float2*)(e_out + (row0 + r) * ED_ + cl) = make_float2(o0, o1);
        }
    }
}

// ---------------- node-side SIMT GEMM + LN ----------------
template<bool RELU>
__global__ void __launch_bounds__(256) gemm_kernel(
    const float* __restrict__ A, const float* __restrict__ W,
    const float* __restrict__ bias, float* __restrict__ C,
    int M, int N, int K, float alpha)
{
    __shared__ __align__(16) float aS[64][68];
    __shared__ __align__(16) float wS[64][68];
    const int tid = threadIdx.x;
    const int tx  = tid & 15;
    const int ty  = tid >> 4;
    const size_t row0 = (size_t)blockIdx.y * 64;
    const int    col0 = blockIdx.x * 64;
    float acc[4][4] = {};
    for (int k0 = 0; k0 < K; k0 += 64) {
        #pragma unroll
        for (int t = tid; t < 1024; t += 256) {
            int r = t >> 4, c4 = (t & 15) << 2;
            float4 av = *(const float4*)(A + (row0 + r) * K + k0 + c4);
            aS[r][c4+0]=av.x; aS[r][c4+1]=av.y; aS[r][c4+2]=av.z; aS[r][c4+3]=av.w;
            float4 wv = *(const float4*)(W + (size_t)(k0 + r) * N + col0 + c4);
            wS[r][c4+0]=wv.x; wS[r][c4+1]=wv.y; wS[r][c4+2]=wv.z; wS[r][c4+3]=wv.w;
        }
        __syncthreads();
        #pragma unroll 16
        for (int k = 0; k < 64; ++k) {
            float a0=aS[ty*4+0][k], a1=aS[ty*4+1][k], a2=aS[ty*4+2][k], a3=aS[ty*4+3][k];
            float4 bv = *(const float4*)&wS[k][tx*4];
            acc[0][0]+=a0*bv.x; acc[0][1]+=a0*bv.y; acc[0][2]+=a0*bv.z; acc[0][3]+=a0*bv.w;
            acc[1][0]+=a1*bv.x; acc[1][1]+=a1*bv.y; acc[1][2]+=a1*bv.z; acc[1][3]+=a1*bv.w;
            acc[2][0]+=a2*bv.x; acc[2][1]+=a2*bv.y; acc[2][2]+=a2*bv.z; acc[2][3]+=a2*bv.w;
            acc[3][0]+=a3*bv.x; acc[3][1]+=a3*bv.y; acc[3][2]+=a3*bv.z; acc[3][3]+=a3*bv.w;
        }
        __syncthreads();
    }
    const int c = col0 + tx * 4;
    float b0=bias[c+0], b1=bias[c+1], b2=bias[c+2], b3=bias[c+3];
    #pragma unroll
    for (int m = 0; m < 4; ++m) {
        float4 o;
        o.x = alpha*(acc[m][0]+b0); o.y = alpha*(acc[m][1]+b1);
        o.z = alpha*(acc[m][2]+b2); o.w = alpha*(acc[m][3]+b3);
        if (RELU) { o.x=fmaxf(o.x,0.f); o.y=fmaxf(o.y,0.f); o.z=fmaxf(o.z,0.f); o.w=fmaxf(o.w,0.f); }
        *(float4*)(C + (row0 + ty*4 + m) * N + c) = o;
    }
}

__global__ void ln_kernel(const float* __restrict__ A, const float* __restrict__ Bv,
                          const float* __restrict__ g, const float* __restrict__ be,
                          float* __restrict__ out)
{
    __shared__ float red[8];
    const int D = blockDim.x;
    const size_t base = (size_t)blockIdx.x * D + threadIdx.x;
    const int lane = threadIdx.x & 31;
    const int w    = threadIdx.x >> 5;
    const int nw   = D >> 5;
    float v = A[base] + Bv[base];
    float s = v;
    #pragma unroll
    for (int o = 16; o; o >>= 1) s += __shfl_xor_sync(0xffffffffu, s, o);
    if (lane == 0) red[w] = s;
    __syncthreads();
    float tot = 0.f;
    for (int ww = 0; ww < nw; ++ww) tot += red[ww];
    float mean = tot / (float)D;
    float d = v - mean;
    __syncthreads();
    float s2 = d * d;
    #pragma unroll
    for (int o = 16; o; o >>= 1) s2 += __shfl_xor_sync(0xffffffffu, s2, o);
    if (lane == 0) red[w] = s2;
    __syncthreads();
    float tot2 = 0.f;
    for (int ww = 0; ww < nw; ++ww) tot2 += red[ww];
    float var = tot2 / (float)D;
    out[base] = d * rsqrtf(var + 1e-5f) * g[threadIdx.x] + be[threadIdx.x];
}

// ---------------- launcher ----------------
extern "C" void kernel_launch(void* const* d_in, const int* in_sizes, int n_in,
                              void* d_out, int out_size)
{
    const float* x   = (const float*)d_in[0];
    const float* e   = (const float*)d_in[1];
    const float* wq  = (const float*)d_in[2];
    const float* wk  = (const float*)d_in[3];
    const float* wv  = (const float*)d_in[4];
    const float* wem = (const float*)d_in[5];
    const float* wea = (const float*)d_in[6];
    const float* wxo = (const float*)d_in[7];
    const float* weo = (const float*)d_in[8];
    const float* wx1 = (const float*)d_in[9];
    const float* wx2 = (const float*)d_in[10];
    const float* we1 = (const float*)d_in[11];
    const float* we2 = (const float*)d_in[12];
    const float* bq  = (const float*)d_in[13];
    const float* bk  = (const float*)d_in[14];
    const float* bv  = (const float*)d_in[15];
    const float* bem = (const float*)d_in[16];
    const float* bea = (const float*)d_in[17];
    const float* bxo = (const float*)d_in[18];
    const float* beo = (const float*)d_in[19];
    const float* bx1 = (const float*)d_in[20];
    const float* bx2 = (const float*)d_in[21];
    const float* be1 = (const float*)d_in[22];
    const float* be2 = (const float*)d_in[23];
    const float* gnx = (const float*)d_in[24];
    const float* bnx = (const float*)d_in[25];
    const float* gne = (const float*)d_in[26];
    const float* bne = (const float*)d_in[27];

    float* x_out = (float*)d_out;
    float* e_out = (float*)d_out + (size_t)ROWS_X * XD_;

    float *Q, *Km, *newX, *hx, *h1x, *h2x, *wvx, *bvx, *zero;
    char *wemP, *weaP, *weoP, *we1P, *we2P;
    cudaGetSymbolAddress((void**)&Q,    g_Q);
    cudaGetSymbolAddress((void**)&Km,   g_Km);
    cudaGetSymbolAddress((void**)&newX, g_newX);
    cudaGetSymbolAddress((void**)&hx,   g_hx);
    cudaGetSymbolAddress((void**)&h1x,  g_h1x);
    cudaGetSymbolAddress((void**)&h2x,  g_h2x);
    cudaGetSymbolAddress((void**)&wvx,  g_wvx);
    cudaGetSymbolAddress((void**)&bvx,  g_bvx);
    cudaGetSymbolAddress((void**)&zero, g_zero);
    cudaGetSymbolAddress((void**)&wemP, g_wemP);
    cudaGetSymbolAddress((void**)&weaP, g_weaP);
    cudaGetSymbolAddress((void**)&weoP, g_weoP);
    cudaGetSymbolAddress((void**)&we1P, g_we1P);
    cudaGetSymbolAddress((void**)&we2P, g_we2P);

    cudaFuncSetAttribute(edge_fused_kernel, cudaFuncAttributeMaxDynamicSharedMemorySize, EF_BYTES);
    cudaFuncSetAttribute(prep_all,          cudaFuncAttributeMaxDynamicSharedMemorySize, 128 * 129 * 4);

    // one-time side-stream/event setup (host objects only)
    static cudaStream_t sNode = nullptr;
    static cudaEvent_t evFork = nullptr, evJoin = nullptr;
    if (!sNode) {
        cudaStreamCreateWithFlags(&sNode, cudaStreamNonBlocking);
        cudaEventCreateWithFlags(&evFork, cudaEventDisableTiming);
        cudaEventCreateWithFlags(&evJoin, cudaEventDisableTiming);
    }

    dim3 blk(256);
    auto grid_of = [](int M, int N) { return dim3((unsigned)(N/64), (unsigned)(M/64)); };

    // ---- fork: node-side chain runs concurrently on sNode ----
    cudaEventRecord(evFork, 0);
    cudaStreamWaitEvent(sNode, evFork, 0);

    // node side on sNode (softmax collapses: wV == V; fold wv@wxo)
    gemm_kernel<false><<<grid_of(XD_, XD_), blk, 0, sNode>>>(wv, wxo, zero, wvx, XD_, XD_, XD_, 1.f);
    fold_bias<<<1, 256, 0, sNode>>>(bv, wxo, bxo, bvx);
    gemm_kernel<false><<<grid_of(ROWS_X, XD_), blk, 0, sNode>>>(x, wvx, bvx, newX, ROWS_X, XD_, XD_, 1.f);
    ln_kernel<<<ROWS_X, XD_, 0, sNode>>>(x, newX, gnx, bnx, hx);
    gemm_kernel<true ><<<grid_of(ROWS_X, FFX), blk, 0, sNode>>>(hx,  wx1, bx1, h1x, ROWS_X, FFX, XD_, 1.f);
    gemm_kernel<false><<<grid_of(ROWS_X, XD_), blk, 0, sNode>>>(h1x, wx2, bx2, h2x, ROWS_X, XD_, FFX, 1.f);
    ln_kernel<<<ROWS_X, XD_, 0, sNode>>>(x, h2x, gnx, bnx, x_out);
    cudaEventRecord(evJoin, sNode);

    // main stream: prep + Q/K + single fused edge kernel
    prep_all<<<14, 256, 128 * 129 * 4>>>(wem, wea, weo, we1, we2,
                                         wemP, weaP, weoP, we1P, we2P);
    gemm_kernel<false><<<grid_of(ROWS_X, XD_), blk>>>(x, wq, bq, Q,  ROWS_X, XD_, XD_, INV_SQRT_DF);
    gemm_kernel<false><<<grid_of(ROWS_X, XD_), blk>>>(x, wk, bk, Km, ROWS_X, XD_, XD_, 1.f);

    edge_fused_kernel<<<ROWS_E / 128, blk, EF_BYTES>>>(
        e, Q, Km, wemP, weaP, weoP, we1P, we2P,
        bem, bea, beo, be1, be2, gne, bne, e_out);

    // ---- join ----
    cudaStreamWaitEvent(0, evJoin, 0);
}

// round 11
// speedup vs baseline: 4.8429x; 1.0606x over previous
#include <cuda_runtime.h>
#include <cuda_bf16.h>
#include <math.h>
#include <stdint.h>

#define BB  8
#define NN  128
#define XD_ 256
#define ED_ 128
#define FFX 1024
#define FFE 512
#define ROWS_X (BB*NN)
#define ROWS_E (BB*NN*NN)
#define INV_SQRT_DF 0.17677669529663687f

#define PITCH   272           // bytes per bf16 tile row (136 bf16)
#define TILE_W  34816         // 128 * 272 (one bf16 128x128 tile)

// ---------------- scratch ----------------
__device__ float g_Q   [ROWS_X * XD_];
__device__ float g_Km  [ROWS_X * XD_];
__device__ float g_newX[ROWS_X * XD_];
__device__ float g_hx  [ROWS_X * XD_];
__device__ float g_h1x [ROWS_X * FFX];
__device__ float g_h2x [ROWS_X * XD_];
__device__ float g_wvx [XD_ * XD_];
__device__ float g_bvx [XD_];
__device__ float g_zero[FFX];
__device__ float g_w2  [ED_ * ED_];      // wea @ weo (fp32)
__device__ float g_beoF[ED_];            // beo + bea @ weo
__device__ __align__(16) char g_wemP[2 * TILE_W];
__device__ __align__(16) char g_weoP[2 * TILE_W];
__device__ __align__(16) char g_w2P [TILE_W];
__device__ __align__(16) char g_we1P[4 * TILE_W];
__device__ __align__(16) char g_we2P[4 * TILE_W];

// ---------------- helpers ----------------
__device__ __forceinline__ uint32_t smem_u32(const void* p) {
    uint32_t a;
    asm("{ .reg .u64 t; cvta.to.shared.u64 t, %1; cvt.u32.u64 %0, t; }" : "=r"(a) : "l"(p));
    return a;
}

#define CPA16(dst, src) asm volatile("cp.async.cg.shared.global [%0], [%1], 16;" :: "r"(dst), "l"(src))
#define CP_COMMIT() asm volatile("cp.async.commit_group;" ::: "memory")
#define CP_WAIT0()  asm volatile("cp.async.wait_group 0;" ::: "memory")

__device__ __forceinline__ void prefetch_w(uint32_t dstS, const char* src, int tid) {
    #pragma unroll 4
    for (int t = tid; t < 2176; t += 256)
        CPA16(dstS + (uint32_t)t * 16, src + (size_t)t * 16);
    CP_COMMIT();
}

__device__ __forceinline__ void mma16816(float* c, uint32_t a0, uint32_t a1, uint32_t a2,
                                         uint32_t a3, uint32_t b0, uint32_t b1) {
    asm volatile(
        "mma.sync.aligned.m16n8k16.row.col.f32.bf16.bf16.f32 "
        "{%0,%1,%2,%3},{%4,%5,%6,%7},{%8,%9},{%0,%1,%2,%3};"
        : "+f"(c[0]), "+f"(c[1]), "+f"(c[2]), "+f"(c[3])
        : "r"(a0), "r"(a1), "r"(a2), "r"(a3), "r"(b0), "r"(b1));
}

__device__ __forceinline__ void ldsm4(uint32_t& r0, uint32_t& r1, uint32_t& r2, uint32_t& r3,
                                      uint32_t a) {
    asm volatile("ldmatrix.sync.aligned.m8n8.x4.shared.b16 {%0,%1,%2,%3},[%4];"
                 : "=r"(r0), "=r"(r1), "=r"(r2), "=r"(r3) : "r"(a));
}

__device__ __forceinline__ void ldA8(uint32_t a[8], uint32_t base, int r0, int k0, int lane) {
    uint32_t addr = base + (uint32_t)(r0 + (lane & 15)) * PITCH
                  + (uint32_t)(k0 + ((lane >> 4) << 3)) * 2;
    ldsm4(a[0], a[1], a[2], a[3], addr);
    ldsm4(a[4], a[5], a[6], a[7], addr + 16 * PITCH);
}

__device__ __forceinline__ void ldB16(uint32_t b[16], uint32_t base, int n0, int k0, int lane) {
    uint32_t addr = base + (uint32_t)(n0 + ((lane >> 4) << 3) + (lane & 7)) * PITCH
                  + (uint32_t)(k0 + (((lane >> 3) & 1) << 3)) * 2;
    ldsm4(b[0],  b[1],  b[2],  b[3],  addr);
    ldsm4(b[4],  b[5],  b[6],  b[7],  addr + 16 * PITCH);
    ldsm4(b[8],  b[9],  b[10], b[11], addr + 32 * PITCH);
    ldsm4(b[12], b[13], b[14], b[15], addr + 48 * PITCH);
}

__device__ __forceinline__ void mma_pass(float (&acc)[2][8][4], const uint32_t a[8],
                                         const uint32_t b[16]) {
    #pragma unroll
    for (int mf = 0; mf < 2; mf++)
        #pragma unroll
        for (int nf = 0; nf < 8; nf++)
            mma16816(acc[mf][nf], a[mf*4], a[mf*4+1], a[mf*4+2], a[mf*4+3],
                     b[nf*2], b[nf*2+1]);
}

// 1-pass bf16 GEMM tile (K=128)
__device__ __forceinline__ void compute_ktile(float (&acc)[2][8][4], uint32_t aB,
                                              uint32_t bB, int wm, int wn, int lane) {
    #pragma unroll 2
    for (int ks = 0; ks < 8; ks++) {
        uint32_t ah[8], bh[16];
        ldA8(ah, aB, wm * 32, ks * 16, lane);
        ldB16(bh, bB, wn * 64, ks * 16, lane);
        mma_pass(acc, ah, bh);
    }
}

__device__ __forceinline__ uint32_t pkf2(float x, float y) {
    __nv_bfloat162 t = __floats2bfloat162_rn(x, y);
    return *reinterpret_cast<uint32_t*>(&t);
}

__device__ __forceinline__ void stage_a_fp32(char* sm, const float* src, int stride, int tid) {
    #pragma unroll 4
    for (int t = tid; t < 4096; t += 256) {
        int r = t >> 5, c4 = (t & 31) << 2;
        float4 v = *(const float4*)(src + (size_t)r * stride + c4);
        uint32_t p0 = pkf2(v.x, v.y);
        uint32_t p1 = pkf2(v.z, v.w);
        *(uint2*)(sm + (uint32_t)r * PITCH + (uint32_t)c4 * 2) = make_uint2(p0, p1);
    }
}

// ---------------- merged weight prep: 13 tiles (incl. W2) ----------------
__global__ void prep_all(const float* __restrict__ wem, const float* __restrict__ weo,
                         const float* __restrict__ we1, const float* __restrict__ we2,
                         const float* __restrict__ w2,
                         char* __restrict__ wemP, char* __restrict__ weoP,
                         char* __restrict__ we1P, char* __restrict__ we2P,
                         char* __restrict__ w2P)
{
    extern __shared__ float tl[];   // 128 x 129
    int s = blockIdx.x;
    const float* W; char* out; int N, kc, nc;
    if (s < 2)       { W = wem; out = wemP + (size_t)s       * TILE_W; N = 256; kc = 0;      nc = s;     }
    else if (s < 4)  { W = weo; out = weoP + (size_t)(s - 2) * TILE_W; N = 128; kc = s - 2;  nc = 0;     }
    else if (s < 8)  { W = we1; out = we1P + (size_t)(s - 4) * TILE_W; N = 512; kc = 0;      nc = s - 4; }
    else if (s < 12) { W = we2; out = we2P + (size_t)(s - 8) * TILE_W; N = 128; kc = s - 8;  nc = 0;     }
    else             { W = w2;  out = w2P;                             N = 128; kc = 0;      nc = 0;     }
    int tid = threadIdx.x;
    for (int t = tid; t < 16384; t += 256) {
        int k = t >> 7, n = t & 127;
        tl[k * 129 + n] = W[(size_t)(kc * 128 + k) * N + nc * 128 + n];
    }
    __syncthreads();
    for (int t = tid; t < 8192; t += 256) {
        int n = t >> 6, k = (t & 63) << 1;
        float v0 = tl[k * 129 + n], v1 = tl[(k + 1) * 129 + n];
        *(uint32_t*)(out + (uint32_t)n * PITCH + (uint32_t)k * 2) = pkf2(v0, v1);
    }
}

__global__ void fold_bias(const float* __restrict__ bv, const float* __restrict__ wxo,
                          const float* __restrict__ bxo, float* __restrict__ bvx) {
    int n = threadIdx.x;
    float s = bxo[n];
    for (int k = 0; k < XD_; ++k) s += bv[k] * wxo[k * XD_ + n];
    bvx[n] = s;
}

// beoF[n] = beo[n] + sum_c bea[c] * weo[c][n]   (c: 256, n: 128)
__global__ void fold_beo(const float* __restrict__ bea, const float* __restrict__ weo,
                         const float* __restrict__ beo, float* __restrict__ beoF) {
    int n = threadIdx.x;
    float s = beo[n];
    for (int c = 0; c < XD_; ++c) s += bea[c] * weo[c * ED_ + n];
    beoF[n] = s;
}

// ================ fused edge kernel: e -> e_out (attn + FF, one pass) ================
#define R_A   0
#define R_B0  34816
#define R_B1  69632
#define R_C   104448
#define R_SM  139264
#define EF_BYTES (139264 + 8192)

__global__ void __launch_bounds__(256, 1) edge_fused_kernel(
    const float* __restrict__ e, const float* __restrict__ Qs, const float* __restrict__ Km,
    const char* __restrict__ w2P, const char* __restrict__ wemP, const char* __restrict__ weoP,
    const char* __restrict__ we1P, const char* __restrict__ we2P,
    const float* __restrict__ bem, const float* __restrict__ beoF,
    const float* __restrict__ be1, const float* __restrict__ be2,
    const float* __restrict__ gne, const float* __restrict__ bne,
    float* __restrict__ e_out)
{
    extern __shared__ char sm[];
    const int tid = threadIdx.x;
    const int lane = tid & 31, w = tid >> 5;
    const int wm = w & 3, wn = w >> 2;
    const int g = lane >> 2, q = lane & 3;
    const int blk = blockIdx.x;
    const size_t row0 = (size_t)blk * 128;
    const int b = blk >> 7, i = blk & 127;

    uint32_t smB = smem_u32(sm);
    float* qS   = (float*)(sm + R_SM);              // 256
    float* bemS = qS + 256;                          // 256
    float* beoS = bemS + 256;                        // 128 (= beoF)
    float* gneS = beoS + 128;                        // 128
    float* bneS = gneS + 128;                        // 128
    float* be1S = bneS + 128;                        // 512
    float* be2S = be1S + 512;                        // 128
    float* red  = be2S + 128;                        // 256
    float* red2 = red + 256;                         // 256

    const uint32_t aB = smB + R_A;
    const uint32_t cB = smB + R_C;
    const uint32_t Bb[2] = {smB + R_B0, smB + R_B1};
    const char* tiles[13] = {
        w2P, wemP, weoP, wemP + TILE_W, weoP + TILE_W,
        we1P,              we2P,
        we1P + TILE_W,     we2P + TILE_W,
        we1P + 2 * TILE_W, we2P + 2 * TILE_W,
        we1P + 3 * TILE_W, we2P + 3 * TILE_W};

    prefetch_w(Bb[0], tiles[0], tid);               // tile 0 in flight
    stage_a_fp32(sm + R_A, e + row0 * ED_, ED_, tid);
    qS[tid]   = Qs[((size_t)(b * NN + i)) * XD_ + tid];
    bemS[tid] = bem[tid];
    if (tid < 128) { beoS[tid] = beoF[tid]; gneS[tid] = gne[tid]; bneS[tid] = bne[tid]; }
    if (tid < 128) be2S[tid] = be2[tid];
    for (int t = tid; t < 512; t += 256) be1S[t] = be1[t];
    CP_WAIT0(); __syncthreads();
    prefetch_w(Bb[1], tiles[1], tid);               // tile 1 in flight

    // =================== attention phase ===================
    float accNE[2][8][4] = {};

    // ---- phase 0: accNE = e @ W2   (collapsed E2 path)
    compute_ktile(accNE, aB, Bb[0], wm, wn, lane);
    CP_WAIT0(); __syncthreads();
    prefetch_w(Bb[0], tiles[2], tid);

    #pragma unroll 1
    for (int nc = 0; nc < 2; nc++) {
        const int p = 1 + nc * 2;
        // ---- phase p (wem[nc]): E1 = e@wem; Y = q*km*(E1+bem+1) -> bf16 into C
        {
            float acc[2][8][4] = {};
            compute_ktile(acc, aB, Bb[p & 1], wm, wn, lane);
            #pragma unroll
            for (int mf = 0; mf < 2; mf++)
            #pragma unroll
            for (int h = 0; h < 2; h++) {
                int r = wm * 32 + mf * 16 + h * 8 + g;
                const float* kp = Km + ((size_t)(b * NN + r)) * XD_ + nc * 128;
                #pragma unroll
                for (int nf = 0; nf < 8; nf++) {
                    int cl = wn * 64 + nf * 8 + q * 2;
                    int cg = nc * 128 + cl;
                    float2 km = *(const float2*)(kp + cl);
                    float y0 = qS[cg]   * km.x * (acc[mf][nf][h*2]   + bemS[cg]   + 1.f);
                    float y1 = qS[cg+1] * km.y * (acc[mf][nf][h*2+1] + bemS[cg+1] + 1.f);
                    *(uint32_t*)(sm + R_C + (uint32_t)r * PITCH + (uint32_t)cl * 2) = pkf2(y0, y1);
                }
            }
        }
        CP_WAIT0(); __syncthreads();
        prefetch_w(Bb[p & 1], tiles[p + 2], tid);
        // ---- phase p+1 (weo[nc]): accNE += Y @ weo
        compute_ktile(accNE, cB, Bb[(p + 1) & 1], wm, wn, lane);
        CP_WAIT0(); __syncthreads();
        prefetch_w(Bb[(p + 1) & 1], tiles[p + 3], tid);
    }

    // ---- attn epilogue: he = LN(e + accNE + beoF)*gne + bne -> bf16 INTO A REGION
    #pragma unroll
    for (int mf = 0; mf < 2; mf++)
    #pragma unroll
    for (int h = 0; h < 2; h++) {
        int r = wm * 32 + mf * 16 + h * 8 + g;
        #pragma unroll
        for (int nf = 0; nf < 8; nf++) {
            int cl = wn * 64 + nf * 8 + q * 2;
            float2 ev = *(const float2*)(e + (row0 + r) * ED_ + cl);
            accNE[mf][nf][h*2+0] += beoS[cl]   + ev.x;
            accNE[mf][nf][h*2+1] += beoS[cl+1] + ev.y;
        }
    }
    {
        float mean[2][2], rstd[2][2];
        #pragma unroll
        for (int mf = 0; mf < 2; mf++)
        #pragma unroll
        for (int h = 0; h < 2; h++) {
            float s = 0.f;
            #pragma unroll
            for (int nf = 0; nf < 8; nf++) s += accNE[mf][nf][h*2] + accNE[mf][nf][h*2+1];
            s += __shfl_xor_sync(0xffffffffu, s, 1);
            s += __shfl_xor_sync(0xffffffffu, s, 2);
            if (q == 0) red[wn * 128 + wm * 32 + mf * 16 + h * 8 + g] = s;
        }
        __syncthreads();
        #pragma unroll
        for (int mf = 0; mf < 2; mf++)
        #pragma unroll
        for (int h = 0; h < 2; h++) {
            int r = wm * 32 + mf * 16 + h * 8 + g;
            mean[mf][h] = (red[r] + red[128 + r]) * (1.f / 128.f);
            float s = 0.f;
            #pragma unroll
            for (int nf = 0; nf < 8; nf++) {
                float d0 = accNE[mf][nf][h*2]   - mean[mf][h];
                float d1 = accNE[mf][nf][h*2+1] - mean[mf][h];
                s += d0 * d0 + d1 * d1;
            }
            s += __shfl_xor_sync(0xffffffffu, s, 1);
            s += __shfl_xor_sync(0xffffffffu, s, 2);
            if (q == 0) red2[wn * 128 + r] = s;
        }
        __syncthreads();
        #pragma unroll
        for (int mf = 0; mf < 2; mf++)
        #pragma unroll
        for (int h = 0; h < 2; h++) {
            int r = wm * 32 + mf * 16 + h * 8 + g;
            rstd[mf][h] = rsqrtf((red2[r] + red2[128 + r]) * (1.f / 128.f) + 1e-5f);
            #pragma unroll
            for (int nf = 0; nf < 8; nf++) {
                int cl = wn * 64 + nf * 8 + q * 2;
                float o0 = (accNE[mf][nf][h*2]   - mean[mf][h]) * rstd[mf][h] * gneS[cl]   + bneS[cl];
                float o1 = (accNE[mf][nf][h*2+1] - mean[mf][h]) * rstd[mf][h] * gneS[cl+1] + bneS[cl+1];
                // he -> A region, MMA layout (e-tile is dead now)
                *(uint32_t*)(sm + R_A + (uint32_t)r * PITCH + (uint32_t)cl * 2) = pkf2(o0, o1);
            }
        }
    }
    __syncthreads();   // he visible to all warps before FF ktiles

    // =================== FF phase (A = he, C = h1 chunks) ===================
    float accH2[2][8][4] = {};

    #pragma unroll 1
    for (int p = 0; p < 4; p++) {
        const int i0 = 5 + p * 2;
        // ---- tile i0 (we1[p]): h1 = relu(he@we1 + be1) -> bf16 into C
        {
            float acc[2][8][4] = {};
            compute_ktile(acc, aB, Bb[i0 & 1], wm, wn, lane);
            #pragma unroll
            for (int mf = 0; mf < 2; mf++)
            #pragma unroll
            for (int h = 0; h < 2; h++) {
                int r = wm * 32 + mf * 16 + h * 8 + g;
                #pragma unroll
                for (int nf = 0; nf < 8; nf++) {
                    int cl = wn * 64 + nf * 8 + q * 2;
                    int cgl = p * 128 + cl;
                    float o0 = fmaxf(acc[mf][nf][h*2]   + be1S[cgl],   0.f);
                    float o1 = fmaxf(acc[mf][nf][h*2+1] + be1S[cgl+1], 0.f);
                    *(uint32_t*)(sm + R_C + (uint32_t)r * PITCH + (uint32_t)cl * 2) = pkf2(o0, o1);
                }
            }
        }
        CP_WAIT0(); __syncthreads();
        if (i0 + 2 < 13) prefetch_w(Bb[i0 & 1], tiles[i0 + 2], tid);
        // ---- tile i0+1 (we2[p]): h2 += h1chunk @ we2
        compute_ktile(accH2, cB, Bb[(i0 + 1) & 1], wm, wn, lane);
        CP_WAIT0(); __syncthreads();
        if (i0 + 3 < 13) prefetch_w(Bb[(i0 + 1) & 1], tiles[i0 + 3], tid);
    }

    // ---- FF epilogue: e_out = LN(e + h2 + be2) * gne + bne
    #pragma unroll
    for (int mf = 0; mf < 2; mf++)
    #pragma unroll
    for (int h = 0; h < 2; h++) {
        int r = wm * 32 + mf * 16 + h * 8 + g;
        #pragma unroll
        for (int nf = 0; nf < 8; nf++) {
            int cl = wn * 64 + nf * 8 + q * 2;
            float2 ev = *(const float2*)(e + (row0 + r) * ED_ + cl);
            accH2[mf][nf][h*2+0] += be2S[cl]   + ev.x;
            accH2[mf][nf][h*2+1] += be2S[cl+1] + ev.y;
        }
    }
    float mean[2][2], rstd[2][2];
    #pragma unroll
    for (int mf = 0; mf < 2; mf++)
    #pragma unroll
    for (int h = 0; h < 2; h++) {
        float s = 0.f;
        #pragma unroll
        for (int nf = 0; nf < 8; nf++) s += accH2[mf][nf][h*2] + accH2[mf][nf][h*2+1];
        s += __shfl_xor_sync(0xffffffffu, s, 1);
        s += __shfl_xor_sync(0xffffffffu, s, 2);
        if (q == 0) red[wn * 128 + wm * 32 + mf * 16 + h * 8 + g] = s;
    }
    __syncthreads();
    #pragma unroll
    for (int mf = 0; mf < 2; mf++)
    #pragma unroll
    for (int h = 0; h < 2; h++) {
        int r = wm * 32 + mf * 16 + h * 8 + g;
        mean[mf][h] = (red[r] + red[128 + r]) * (1.f / 128.f);
        float s = 0.f;
        #pragma unroll
        for (int nf = 0; nf < 8; nf++) {
            float d0 = accH2[mf][nf][h*2]   - mean[mf][h];
            float d1 = accH2[mf][nf][h*2+1] - mean[mf][h];
            s += d0 * d0 + d1 * d1;
        }
        s += __shfl_xor_sync(0xffffffffu, s, 1);
        s += __shfl_xor_sync(0xffffffffu, s, 2);
        if (q == 0) red2[wn * 128 + r] = s;
    }
    __syncthreads();
    #pragma unroll
    for (int mf = 0; mf < 2; mf++)
    #pragma unroll
    for (int h = 0; h < 2; h++) {
        int r = wm * 32 + mf * 16 + h * 8 + g;
        rstd[mf][h] = rsqrtf((red2[r] + red2[128 + r]) * (1.f / 128.f) + 1e-5f);
        #pragma unroll
        for (int nf = 0; nf < 8; nf++) {
            int cl = wn * 64 + nf * 8 + q * 2;
            float o0 = (accH2[mf][nf][h*2]   - mean[mf][h]) * rstd[mf][h] * gneS[cl]   + bneS[cl];
            float o1 = (accH2[mf][nf][h*2+1] - mean[mf][h]) * rstd[mf][h] * gneS[cl+1] + bneS[cl+1];
            *(float2*)(e_out + (row0 + r) * ED_ + cl) = make_float2(o0, o1);
        }
    }
}

// ---------------- node-side SIMT GEMM + LN ----------------
template<bool RELU>
__global__ void __launch_bounds__(256) gemm_kernel(
    const float* __restrict__ A, const float* __restrict__ W,
    const float* __restrict__ bias, float* __restrict__ C,
    int M, int N, int K, float alpha)
{
    __shared__ __align__(16) float aS[64][68];
    __shared__ __align__(16) float wS[64][68];
    const int tid = threadIdx.x;
    const int tx  = tid & 15;
    const int ty  = tid >> 4;
    const size_t row0 = (size_t)blockIdx.y * 64;
    const int    col0 = blockIdx.x * 64;
    float acc[4][4] = {};
    for (int k0 = 0; k0 < K; k0 += 64) {
        #pragma unroll
        for (int t = tid; t < 1024; t += 256) {
            int r = t >> 4, c4 = (t & 15) << 2;
            float4 av = *(const float4*)(A + (row0 + r) * K + k0 + c4);
            aS[r][c4+0]=av.x; aS[r][c4+1]=av.y; aS[r][c4+2]=av.z; aS[r][c4+3]=av.w;
            float4 wv = *(const float4*)(W + (size_t)(k0 + r) * N + col0 + c4);
            wS[r][c4+0]=wv.x; wS[r][c4+1]=wv.y; wS[r][c4+2]=wv.z; wS[r][c4+3]=wv.w;
        }
        __syncthreads();
        #pragma unroll 16
        for (int k = 0; k < 64; ++k) {
            float a0=aS[ty*4+0][k], a1=aS[ty*4+1][k], a2=aS[ty*4+2][k], a3=aS[ty*4+3][k];
            float4 bv = *(const float4*)&wS[k][tx*4];
            acc[0][0]+=a0*bv.x; acc[0][1]+=a0*bv.y; acc[0][2]+=a0*bv.z; acc[0][3]+=a0*bv.w;
            acc[1][0]+=a1*bv.x; acc[1][1]+=a1*bv.y; acc[1][2]+=a1*bv.z; acc[1][3]+=a1*bv.w;
            acc[2][0]+=a2*bv.x; acc[2][1]+=a2*bv.y; acc[2][2]+=a2*bv.z; acc[2][3]+=a2*bv.w;
            acc[3][0]+=a3*bv.x; acc[3][1]+=a3*bv.y; acc[3][2]+=a3*bv.z; acc[3][3]+=a3*bv.w;
        }
        __syncthreads();
    }
    const int c = col0 + tx * 4;
    float b0=bias[c+0], b1=bias[c+1], b2=bias[c+2], b3=bias[c+3];
    #pragma unroll
    for (int m = 0; m < 4; ++m) {
        float4 o;
        o.x = alpha*(acc[m][0]+b0); o.y = alpha*(acc[m][1]+b1);
        o.z = alpha*(acc[m][2]+b2); o.w = alpha*(acc[m][3]+b3);
        if (RELU) { o.x=fmaxf(o.x,0.f); o.y=fmaxf(o.y,0.f); o.z=fmaxf(o.z,0.f); o.w=fmaxf(o.w,0.f); }
        *(float4*)(C + (row0 + ty*4 + m) * N + c) = o;
    }
}

__global__ void ln_kernel(const float* __restrict__ A, const float* __restrict__ Bv,
                          const float* __restrict__ g, const float* __restrict__ be,
                          float* __restrict__ out)
{
    __shared__ float red[8];
    const int D = blockDim.x;
    const size_t base = (size_t)blockIdx.x * D + threadIdx.x;
    const int lane = threadIdx.x & 31;
    const int w    = threadIdx.x >> 5;
    const int nw   = D >> 5;
    float v = A[base] + Bv[base];
    float s = v;
    #pragma unroll
    for (int o = 16; o; o >>= 1) s += __shfl_xor_sync(0xffffffffu, s, o);
    if (lane == 0) red[w] = s;
    __syncthreads();
    float tot = 0.f;
    for (int ww = 0; ww < nw; ++ww) tot += red[ww];
    float mean = tot / (float)D;
    float d = v - mean;
    __syncthreads();
    float s2 = d * d;
    #pragma unroll
    for (int o = 16; o; o >>= 1) s2 += __shfl_xor_sync(0xffffffffu, s2, o);
    if (lane == 0) red[w] = s2;
    __syncthreads();
    float tot2 = 0.f;
    for (int ww = 0; ww < nw; ++ww) tot2 += red[ww];
    float var = tot2 / (float)D;
    out[base] = d * rsqrtf(var + 1e-5f) * g[threadIdx.x] + be[threadIdx.x];
}

// ---------------- launcher ----------------
extern "C" void kernel_launch(void* const* d_in, const int* in_sizes, int n_in,
                              void* d_out, int out_size)
{
    const float* x   = (const float*)d_in[0];
    const float* e   = (const float*)d_in[1];
    const float* wq  = (const float*)d_in[2];
    const float* wk  = (const float*)d_in[3];
    const float* wv  = (const float*)d_in[4];
    const float* wem = (const float*)d_in[5];
    const float* wea = (const float*)d_in[6];
    const float* wxo = (const float*)d_in[7];
    const float* weo = (const float*)d_in[8];
    const float* wx1 = (const float*)d_in[9];
    const float* wx2 = (const float*)d_in[10];
    const float* we1 = (const float*)d_in[11];
    const float* we2 = (const float*)d_in[12];
    const float* bq  = (const float*)d_in[13];
    const float* bk  = (const float*)d_in[14];
    const float* bv  = (const float*)d_in[15];
    const float* bem = (const float*)d_in[16];
    const float* bea = (const float*)d_in[17];
    const float* bxo = (const float*)d_in[18];
    const float* beo = (const float*)d_in[19];
    const float* bx1 = (const float*)d_in[20];
    const float* bx2 = (const float*)d_in[21];
    const float* be1 = (const float*)d_in[22];
    const float* be2 = (const float*)d_in[23];
    const float* gnx = (const float*)d_in[24];
    const float* bnx = (const float*)d_in[25];
    const float* gne = (const float*)d_in[26];
    const float* bne = (const float*)d_in[27];

    float* x_out = (float*)d_out;
    float* e_out = (float*)d_out + (size_t)ROWS_X * XD_;

    float *Q, *Km, *newX, *hx, *h1x, *h2x, *wvx, *bvx, *zero, *w2, *beoF;
    char *wemP, *weoP, *w2P, *we1P, *we2P;
    cudaGetSymbolAddress((void**)&Q,    g_Q);
    cudaGetSymbolAddress((void**)&Km,   g_Km);
    cudaGetSymbolAddress((void**)&newX, g_newX);
    cudaGetSymbolAddress((void**)&hx,   g_hx);
    cudaGetSymbolAddress((void**)&h1x,  g_h1x);
    cudaGetSymbolAddress((void**)&h2x,  g_h2x);
    cudaGetSymbolAddress((void**)&wvx,  g_wvx);
    cudaGetSymbolAddress((void**)&bvx,  g_bvx);
    cudaGetSymbolAddress((void**)&zero, g_zero);
    cudaGetSymbolAddress((void**)&w2,   g_w2);
    cudaGetSymbolAddress((void**)&beoF, g_beoF);
    cudaGetSymbolAddress((void**)&wemP, g_wemP);
    cudaGetSymbolAddress((void**)&weoP, g_weoP);
    cudaGetSymbolAddress((void**)&w2P,  g_w2P);
    cudaGetSymbolAddress((void**)&we1P, g_we1P);
    cudaGetSymbolAddress((void**)&we2P, g_we2P);

    cudaFuncSetAttribute(edge_fused_kernel, cudaFuncAttributeMaxDynamicSharedMemorySize, EF_BYTES);
    cudaFuncSetAttribute(prep_all,          cudaFuncAttributeMaxDynamicSharedMemorySize, 128 * 129 * 4);

    // one-time side-stream/event setup (host objects only)
    static cudaStream_t sNode = nullptr, sQK = nullptr;
    static cudaEvent_t evFork = nullptr, evJoin = nullptr, evQK = nullptr;
    if (!sNode) {
        cudaStreamCreateWithFlags(&sNode, cudaStreamNonBlocking);
        cudaStreamCreateWithFlags(&sQK,   cudaStreamNonBlocking);
        cudaEventCreateWithFlags(&evFork, cudaEventDisableTiming);
        cudaEventCreateWithFlags(&evJoin, cudaEventDisableTiming);
        cudaEventCreateWithFlags(&evQK,   cudaEventDisableTiming);
    }

    dim3 blk(256);
    auto grid_of = [](int M, int N) { return dim3((unsigned)(N/64), (unsigned)(M/64)); };

    // ---- fork ----
    cudaEventRecord(evFork, 0);
    cudaStreamWaitEvent(sNode, evFork, 0);
    cudaStreamWaitEvent(sQK,   evFork, 0);

    // node side on sNode (softmax collapses: wV == V; fold wv@wxo)
    gemm_kernel<false><<<grid_of(XD_, XD_), blk, 0, sNode>>>(wv, wxo, zero, wvx, XD_, XD_, XD_, 1.f);
    fold_bias<<<1, 256, 0, sNode>>>(bv, wxo, bxo, bvx);
    gemm_kernel<false><<<grid_of(ROWS_X, XD_), blk, 0, sNode>>>(x, wvx, bvx, newX, ROWS_X, XD_, XD_, 1.f);
    ln_kernel<<<ROWS_X, XD_, 0, sNode>>>(x, newX, gnx, bnx, hx);
    gemm_kernel<true ><<<grid_of(ROWS_X, FFX), blk, 0, sNode>>>(hx,  wx1, bx1, h1x, ROWS_X, FFX, XD_, 1.f);
    gemm_kernel<false><<<grid_of(ROWS_X, XD_), blk, 0, sNode>>>(h1x, wx2, bx2, h2x, ROWS_X, XD_, FFX, 1.f);
    ln_kernel<<<ROWS_X, XD_, 0, sNode>>>(x, h2x, gnx, bnx, x_out);
    cudaEventRecord(evJoin, sNode);

    // Q/K projections on sQK (independent of prep chain)
    gemm_kernel<false><<<grid_of(ROWS_X, XD_), blk, 0, sQK>>>(x, wq, bq, Q,  ROWS_X, XD_, XD_, INV_SQRT_DF);
    gemm_kernel<false><<<grid_of(ROWS_X, XD_), blk, 0, sQK>>>(x, wk, bk, Km, ROWS_X, XD_, XD_, 1.f);
    cudaEventRecord(evQK, sQK);

    // main stream: W2 = wea@weo, folded bias, prep (13 tiles incl. W2), edge
    gemm_kernel<false><<<grid_of(ED_, ED_), blk>>>(wea, weo, zero, w2, ED_, ED_, XD_, 1.f);
    fold_beo<<<1, 128>>>(bea, weo, beo, beoF);
    prep_all<<<13, 256, 128 * 129 * 4>>>(wem, weo, we1, we2, w2,
                                         wemP, weoP, we1P, we2P, w2P);
    cudaStreamWaitEvent(0, evQK, 0);

    edge_fused_kernel<<<ROWS_E / 128, blk, EF_BYTES>>>(
        e, Q, Km, w2P, wemP, weoP, we1P, we2P,
        bem, beoF, be1, be2, gne, bne, e_out);

    // ---- join ----
    cudaStreamWaitEvent(0, evJoin, 0);
}

// round 12
// speedup vs baseline: 4.9319x; 1.0184x over previous
#include <cuda_runtime.h>
#include <cuda_bf16.h>
#include <math.h>
#include <stdint.h>

#define BB  8
#define NN  128
#define XD_ 256
#define ED_ 128
#define FFX 1024
#define FFE 512
#define ROWS_X (BB*NN)
#define ROWS_E (BB*NN*NN)
#define INV_SQRT_DF 0.17677669529663687f

#define PITCH   272           // bytes per bf16 tile row (136 bf16)
#define TILE_W  34816         // 128 * 272 (one bf16 128x128 tile)

// ---------------- scratch ----------------
__device__ float g_Q   [ROWS_X * XD_];
__device__ float g_Km  [ROWS_X * XD_];
__device__ float g_newX[ROWS_X * XD_];
__device__ float g_hx  [ROWS_X * XD_];
__device__ float g_h1x [ROWS_X * FFX];
__device__ float g_h2x [ROWS_X * XD_];
__device__ float g_wvx [XD_ * XD_];
__device__ float g_bvx [XD_];
__device__ float g_zero[FFX];
__device__ float g_w2  [ED_ * ED_];      // wea @ weo (fp32)
__device__ float g_beoF[ED_];            // beo + bea @ weo
__device__ __align__(16) char g_wemP[2 * TILE_W];
__device__ __align__(16) char g_weoP[2 * TILE_W];
__device__ __align__(16) char g_w2P [TILE_W];
__device__ __align__(16) char g_we1P[4 * TILE_W];
__device__ __align__(16) char g_we2P[4 * TILE_W];

// ---------------- helpers ----------------
__device__ __forceinline__ uint32_t smem_u32(const void* p) {
    uint32_t a;
    asm("{ .reg .u64 t; cvta.to.shared.u64 t, %1; cvt.u32.u64 %0, t; }" : "=r"(a) : "l"(p));
    return a;
}

#define CPA16(dst, src) asm volatile("cp.async.cg.shared.global [%0], [%1], 16;" :: "r"(dst), "l"(src))
#define CP_COMMIT() asm volatile("cp.async.commit_group;" ::: "memory")
#define CP_WAIT0()  asm volatile("cp.async.wait_group 0;" ::: "memory")

__device__ __forceinline__ void prefetch_w(uint32_t dstS, const char* src, int tid) {
    #pragma unroll 4
    for (int t = tid; t < 2176; t += 256)
        CPA16(dstS + (uint32_t)t * 16, src + (size_t)t * 16);
    CP_COMMIT();
}

__device__ __forceinline__ void mma16816(float* c, uint32_t a0, uint32_t a1, uint32_t a2,
                                         uint32_t a3, uint32_t b0, uint32_t b1) {
    asm volatile(
        "mma.sync.aligned.m16n8k16.row.col.f32.bf16.bf16.f32 "
        "{%0,%1,%2,%3},{%4,%5,%6,%7},{%8,%9},{%0,%1,%2,%3};"
        : "+f"(c[0]), "+f"(c[1]), "+f"(c[2]), "+f"(c[3])
        : "r"(a0), "r"(a1), "r"(a2), "r"(a3), "r"(b0), "r"(b1));
}

__device__ __forceinline__ void ldsm4(uint32_t& r0, uint32_t& r1, uint32_t& r2, uint32_t& r3,
                                      uint32_t a) {
    asm volatile("ldmatrix.sync.aligned.m8n8.x4.shared.b16 {%0,%1,%2,%3},[%4];"
                 : "=r"(r0), "=r"(r1), "=r"(r2), "=r"(r3) : "r"(a));
}

__device__ __forceinline__ void ldA8(uint32_t a[8], uint32_t base, int r0, int k0, int lane) {
    uint32_t addr = base + (uint32_t)(r0 + (lane & 15)) * PITCH
                  + (uint32_t)(k0 + ((lane >> 4) << 3)) * 2;
    ldsm4(a[0], a[1], a[2], a[3], addr);
    ldsm4(a[4], a[5], a[6], a[7], addr + 16 * PITCH);
}

__device__ __forceinline__ void ldB16(uint32_t b[16], uint32_t base, int n0, int k0, int lane) {
    uint32_t addr = base + (uint32_t)(n0 + ((lane >> 4) << 3) + (lane & 7)) * PITCH
                  + (uint32_t)(k0 + (((lane >> 3) & 1) << 3)) * 2;
    ldsm4(b[0],  b[1],  b[2],  b[3],  addr);
    ldsm4(b[4],  b[5],  b[6],  b[7],  addr + 16 * PITCH);
    ldsm4(b[8],  b[9],  b[10], b[11], addr + 32 * PITCH);
    ldsm4(b[12], b[13], b[14], b[15], addr + 48 * PITCH);
}

__device__ __forceinline__ void mma_pass(float (&acc)[2][8][4], const uint32_t a[8],
                                         const uint32_t b[16]) {
    #pragma unroll
    for (int mf = 0; mf < 2; mf++)
        #pragma unroll
        for (int nf = 0; nf < 8; nf++)
            mma16816(acc[mf][nf], a[mf*4], a[mf*4+1], a[mf*4+2], a[mf*4+3],
                     b[nf*2], b[nf*2+1]);
}

// 1-pass bf16 GEMM tile (K=128), software-pipelined fragment double-buffer
__device__ __forceinline__ void compute_ktile(float (&acc)[2][8][4], uint32_t aB,
                                              uint32_t bB, int wm, int wn, int lane) {
    uint32_t ah[2][8], bh[2][16];
    ldA8(ah[0], aB, wm * 32, 0, lane);
    ldB16(bh[0], bB, wn * 64, 0, lane);
    #pragma unroll
    for (int ks = 0; ks < 8; ks++) {
        const int cur = ks & 1;
        if (ks < 7) {
            ldA8(ah[cur ^ 1], aB, wm * 32, (ks + 1) * 16, lane);
            ldB16(bh[cur ^ 1], bB, wn * 64, (ks + 1) * 16, lane);
        }
        mma_pass(acc, ah[cur], bh[cur]);
    }
}

__device__ __forceinline__ uint32_t pkf2(float x, float y) {
    __nv_bfloat162 t = __floats2bfloat162_rn(x, y);
    return *reinterpret_cast<uint32_t*>(&t);
}

__device__ __forceinline__ void stage_a_fp32(char* sm, const float* src, int stride, int tid) {
    #pragma unroll 4
    for (int t = tid; t < 4096; t += 256) {
        int r = t >> 5, c4 = (t & 31) << 2;
        float4 v = *(const float4*)(src + (size_t)r * stride + c4);
        uint32_t p0 = pkf2(v.x, v.y);
        uint32_t p1 = pkf2(v.z, v.w);
        *(uint2*)(sm + (uint32_t)r * PITCH + (uint32_t)c4 * 2) = make_uint2(p0, p1);
    }
}

// ---------------- weight prep: one block per 128x128 tile, coalesced ----------------
__device__ __forceinline__ void prep_tile(const float* W, char* out, int N, int kc, int nc,
                                          float* tl, int tid) {
    for (int t = tid; t < 16384; t += 256) {
        int k = t >> 7, n = t & 127;
        tl[k * 129 + n] = W[(size_t)(kc * 128 + k) * N + nc * 128 + n];
    }
    __syncthreads();
    for (int t = tid; t < 8192; t += 256) {
        int n = t >> 6, k = (t & 63) << 1;
        float v0 = tl[k * 129 + n], v1 = tl[(k + 1) * 129 + n];
        *(uint32_t*)(out + (uint32_t)n * PITCH + (uint32_t)k * 2) = pkf2(v0, v1);
    }
}

__global__ void prep_all12(const float* __restrict__ wem, const float* __restrict__ weo,
                           const float* __restrict__ we1, const float* __restrict__ we2,
                           char* __restrict__ wemP, char* __restrict__ weoP,
                           char* __restrict__ we1P, char* __restrict__ we2P)
{
    extern __shared__ float tl[];   // 128 x 129
    int s = blockIdx.x;
    const float* W; char* out; int N, kc, nc;
    if (s < 2)       { W = wem; out = wemP + (size_t)s       * TILE_W; N = 256; kc = 0;     nc = s;     }
    else if (s < 4)  { W = weo; out = weoP + (size_t)(s - 2) * TILE_W; N = 128; kc = s - 2; nc = 0;     }
    else if (s < 8)  { W = we1; out = we1P + (size_t)(s - 4) * TILE_W; N = 512; kc = 0;     nc = s - 4; }
    else             { W = we2; out = we2P + (size_t)(s - 8) * TILE_W; N = 128; kc = s - 8; nc = 0;     }
    prep_tile(W, out, N, kc, nc, tl, threadIdx.x);
}

__global__ void prep_w2(const float* __restrict__ w2, char* __restrict__ w2P) {
    extern __shared__ float tl[];
    prep_tile(w2, w2P, 128, 0, 0, tl, threadIdx.x);
}

__global__ void fold_bias(const float* __restrict__ bv, const float* __restrict__ wxo,
                          const float* __restrict__ bxo, float* __restrict__ bvx) {
    int n = threadIdx.x;
    float s = bxo[n];
    for (int k = 0; k < XD_; ++k) s += bv[k] * wxo[k * XD_ + n];
    bvx[n] = s;
}

// beoF[n] = beo[n] + sum_c bea[c] * weo[c][n]
__global__ void fold_beo(const float* __restrict__ bea, const float* __restrict__ weo,
                         const float* __restrict__ beo, float* __restrict__ beoF) {
    int n = threadIdx.x;
    float s = beo[n];
    for (int c = 0; c < XD_; ++c) s += bea[c] * weo[c * ED_ + n];
    beoF[n] = s;
}

// ================ fused edge kernel: e -> e_out (attn + FF, one pass) ================
#define R_A   0
#define R_B0  34816
#define R_B1  69632
#define R_C   104448
#define R_SM  139264
#define EF_BYTES (139264 + 8192)

__global__ void __launch_bounds__(256, 1) edge_fused_kernel(
    const float* __restrict__ e, const float* __restrict__ Qs, const float* __restrict__ Km,
    const char* __restrict__ w2P, const char* __restrict__ wemP, const char* __restrict__ weoP,
    const char* __restrict__ we1P, const char* __restrict__ we2P,
    const float* __restrict__ bem, const float* __restrict__ beoF,
    const float* __restrict__ be1, const float* __restrict__ be2,
    const float* __restrict__ gne, const float* __restrict__ bne,
    float* __restrict__ e_out)
{
    extern __shared__ char sm[];
    const int tid = threadIdx.x;
    const int lane = tid & 31, w = tid >> 5;
    const int wm = w & 3, wn = w >> 2;
    const int g = lane >> 2, q = lane & 3;
    const int blk = blockIdx.x;
    const size_t row0 = (size_t)blk * 128;
    const int b = blk >> 7, i = blk & 127;

    uint32_t smB = smem_u32(sm);
    float* qS   = (float*)(sm + R_SM);              // 256
    float* bemS = qS + 256;                          // 256
    float* beoS = bemS + 256;                        // 128 (= beoF)
    float* gneS = beoS + 128;                        // 128
    float* bneS = gneS + 128;                        // 128
    float* be1S = bneS + 128;                        // 512
    float* be2S = be1S + 512;                        // 128
    float* red  = be2S + 128;                        // 256
    float* red2 = red + 256;                         // 256

    const uint32_t aB = smB + R_A;
    const uint32_t cB = smB + R_C;
    const uint32_t Bb[2] = {smB + R_B0, smB + R_B1};
    const char* tiles[13] = {
        w2P, wemP, weoP, wemP + TILE_W, weoP + TILE_W,
        we1P,              we2P,
        we1P + TILE_W,     we2P + TILE_W,
        we1P + 2 * TILE_W, we2P + 2 * TILE_W,
        we1P + 3 * TILE_W, we2P + 3 * TILE_W};

    prefetch_w(Bb[0], tiles[0], tid);               // tile 0 in flight
    stage_a_fp32(sm + R_A, e + row0 * ED_, ED_, tid);
    qS[tid]   = Qs[((size_t)(b * NN + i)) * XD_ + tid];
    bemS[tid] = bem[tid];
    if (tid < 128) { beoS[tid] = beoF[tid]; gneS[tid] = gne[tid]; bneS[tid] = bne[tid]; }
    if (tid < 128) be2S[tid] = be2[tid];
    for (int t = tid; t < 512; t += 256) be1S[t] = be1[t];
    CP_WAIT0(); __syncthreads();
    prefetch_w(Bb[1], tiles[1], tid);               // tile 1 in flight

    // =================== attention phase ===================
    float accNE[2][8][4] = {};

    // ---- phase 0: accNE = e @ W2   (collapsed E2 path)
    compute_ktile(accNE, aB, Bb[0], wm, wn, lane);
    CP_WAIT0(); __syncthreads();
    prefetch_w(Bb[0], tiles[2], tid);

    #pragma unroll 1
    for (int nc = 0; nc < 2; nc++) {
        const int p = 1 + nc * 2;
        // ---- phase p (wem[nc]): E1 = e@wem; Y = q*km*(E1+bem+1) -> bf16 into C
        {
            float acc[2][8][4] = {};
            compute_ktile(acc, aB, Bb[p & 1], wm, wn, lane);
            #pragma unroll
            for (int mf = 0; mf < 2; mf++)
            #pragma unroll
            for (int h = 0; h < 2; h++) {
                int r = wm * 32 + mf * 16 + h * 8 + g;
                const float* kp = Km + ((size_t)(b * NN + r)) * XD_ + nc * 128;
                #pragma unroll
                for (int nf = 0; nf < 8; nf++) {
                    int cl = wn * 64 + nf * 8 + q * 2;
                    int cg = nc * 128 + cl;
                    float2 km = *(const float2*)(kp + cl);
                    float y0 = qS[cg]   * km.x * (acc[mf][nf][h*2]   + bemS[cg]   + 1.f);
                    float y1 = qS[cg+1] * km.y * (acc[mf][nf][h*2+1] + bemS[cg+1] + 1.f);
                    *(uint32_t*)(sm + R_C + (uint32_t)r * PITCH + (uint32_t)cl * 2) = pkf2(y0, y1);
                }
            }
        }
        CP_WAIT0(); __syncthreads();
        prefetch_w(Bb[p & 1], tiles[p + 2], tid);
        // ---- phase p+1 (weo[nc]): accNE += Y @ weo
        compute_ktile(accNE, cB, Bb[(p + 1) & 1], wm, wn, lane);
        CP_WAIT0(); __syncthreads();
        prefetch_w(Bb[(p + 1) & 1], tiles[p + 3], tid);
    }

    // ---- attn epilogue: he = LN(e + accNE + beoF)*gne + bne -> bf16 INTO A REGION
    #pragma unroll
    for (int mf = 0; mf < 2; mf++)
    #pragma unroll
    for (int h = 0; h < 2; h++) {
        int r = wm * 32 + mf * 16 + h * 8 + g;
        #pragma unroll
        for (int nf = 0; nf < 8; nf++) {
            int cl = wn * 64 + nf * 8 + q * 2;
            float2 ev = *(const float2*)(e + (row0 + r) * ED_ + cl);
            accNE[mf][nf][h*2+0] += beoS[cl]   + ev.x;
            accNE[mf][nf][h*2+1] += beoS[cl+1] + ev.y;
        }
    }
    {
        float mean[2][2], rstd[2][2];
        #pragma unroll
        for (int mf = 0; mf < 2; mf++)
        #pragma unroll
        for (int h = 0; h < 2; h++) {
            float s = 0.f;
            #pragma unroll
            for (int nf = 0; nf < 8; nf++) s += accNE[mf][nf][h*2] + accNE[mf][nf][h*2+1];
            s += __shfl_xor_sync(0xffffffffu, s, 1);
            s += __shfl_xor_sync(0xffffffffu, s, 2);
            if (q == 0) red[wn * 128 + wm * 32 + mf * 16 + h * 8 + g] = s;
        }
        __syncthreads();
        #pragma unroll
        for (int mf = 0; mf < 2; mf++)
        #pragma unroll
        for (int h = 0; h < 2; h++) {
            int r = wm * 32 + mf * 16 + h * 8 + g;
            mean[mf][h] = (red[r] + red[128 + r]) * (1.f / 128.f);
            float s = 0.f;
            #pragma unroll
            for (int nf = 0; nf < 8; nf++) {
                float d0 = accNE[mf][nf][h*2]   - mean[mf][h];
                float d1 = accNE[mf][nf][h*2+1] - mean[mf][h];
                s += d0 * d0 + d1 * d1;
            }
            s += __shfl_xor_sync(0xffffffffu, s, 1);
            s += __shfl_xor_sync(0xffffffffu, s, 2);
            if (q == 0) red2[wn * 128 + r] = s;
        }
        __syncthreads();
        #pragma unroll
        for (int mf = 0; mf < 2; mf++)
        #pragma unroll
        for (int h = 0; h < 2; h++) {
            int r = wm * 32 + mf * 16 + h * 8 + g;
            rstd[mf][h] = rsqrtf((red2[r] + red2[128 + r]) * (1.f / 128.f) + 1e-5f);
            #pragma unroll
            for (int nf = 0; nf < 8; nf++) {
                int cl = wn * 64 + nf * 8 + q * 2;
                float o0 = (accNE[mf][nf][h*2]   - mean[mf][h]) * rstd[mf][h] * gneS[cl]   + bneS[cl];
                float o1 = (accNE[mf][nf][h*2+1] - mean[mf][h]) * rstd[mf][h] * gneS[cl+1] + bneS[cl+1];
                // he -> A region, MMA layout (e-tile is dead now)
                *(uint32_t*)(sm + R_A + (uint32_t)r * PITCH + (uint32_t)cl * 2) = pkf2(o0, o1);
            }
        }
    }
    __syncthreads();   // he visible to all warps before FF ktiles

    // =================== FF phase (A = he, C = h1 chunks) ===================
    float accH2[2][8][4] = {};

    #pragma unroll 1
    for (int p = 0; p < 4; p++) {
        const int i0 = 5 + p * 2;
        // ---- tile i0 (we1[p]): h1 = relu(he@we1 + be1) -> bf16 into C
        {
            float acc[2][8][4] = {};
            compute_ktile(acc, aB, Bb[i0 & 1], wm, wn, lane);
            #pragma unroll
            for (int mf = 0; mf < 2; mf++)
            #pragma unroll
            for (int h = 0; h < 2; h++) {
                int r = wm * 32 + mf * 16 + h * 8 + g;
                #pragma unroll
                for (int nf = 0; nf < 8; nf++) {
                    int cl = wn * 64 + nf * 8 + q * 2;
                    int cgl = p * 128 + cl;
                    float o0 = fmaxf(acc[mf][nf][h*2]   + be1S[cgl],   0.f);
                    float o1 = fmaxf(acc[mf][nf][h*2+1] + be1S[cgl+1], 0.f);
                    *(uint32_t*)(sm + R_C + (uint32_t)r * PITCH + (uint32_t)cl * 2) = pkf2(o0, o1);
                }
            }
        }
        CP_WAIT0(); __syncthreads();
        if (i0 + 2 < 13) prefetch_w(Bb[i0 & 1], tiles[i0 + 2], tid);
        // ---- tile i0+1 (we2[p]): h2 += h1chunk @ we2
        compute_ktile(accH2, cB, Bb[(i0 + 1) & 1], wm, wn, lane);
        CP_WAIT0(); __syncthreads();
        if (i0 + 3 < 13) prefetch_w(Bb[(i0 + 1) & 1], tiles[i0 + 3], tid);
    }

    // ---- FF epilogue: e_out = LN(e + h2 + be2) * gne + bne
    #pragma unroll
    for (int mf = 0; mf < 2; mf++)
    #pragma unroll
    for (int h = 0; h < 2; h++) {
        int r = wm * 32 + mf * 16 + h * 8 + g;
        #pragma unroll
        for (int nf = 0; nf < 8; nf++) {
            int cl = wn * 64 + nf * 8 + q * 2;
            float2 ev = *(const float2*)(e + (row0 + r) * ED_ + cl);
            accH2[mf][nf][h*2+0] += be2S[cl]   + ev.x;
            accH2[mf][nf][h*2+1] += be2S[cl+1] + ev.y;
        }
    }
    float mean[2][2], rstd[2][2];
    #pragma unroll
    for (int mf = 0; mf < 2; mf++)
    #pragma unroll
    for (int h = 0; h < 2; h++) {
        float s = 0.f;
        #pragma unroll
        for (int nf = 0; nf < 8; nf++) s += accH2[mf][nf][h*2] + accH2[mf][nf][h*2+1];
        s += __shfl_xor_sync(0xffffffffu, s, 1);
        s += __shfl_xor_sync(0xffffffffu, s, 2);
        if (q == 0) red[wn * 128 + wm * 32 + mf * 16 + h * 8 + g] = s;
    }
    __syncthreads();
    #pragma unroll
    for (int mf = 0; mf < 2; mf++)
    #pragma unroll
    for (int h = 0; h < 2; h++) {
        int r = wm * 32 + mf * 16 + h * 8 + g;
        mean[mf][h] = (red[r] + red[128 + r]) * (1.f / 128.f);
        float s = 0.f;
        #pragma unroll
        for (int nf = 0; nf < 8; nf++) {
            float d0 = accH2[mf][nf][h*2]   - mean[mf][h];
            float d1 = accH2[mf][nf][h*2+1] - mean[mf][h];
            s += d0 * d0 + d1 * d1;
        }
        s += __shfl_xor_sync(0xffffffffu, s, 1);
        s += __shfl_xor_sync(0xffffffffu, s, 2);
        if (q == 0) red2[wn * 128 + r] = s;
    }
    __syncthreads();
    #pragma unroll
    for (int mf = 0; mf < 2; mf++)
    #pragma unroll
    for (int h = 0; h < 2; h++) {
        int r = wm * 32 + mf * 16 + h * 8 + g;
        rstd[mf][h] = rsqrtf((red2[r] + red2[128 + r]) * (1.f / 128.f) + 1e-5f);
        #pragma unroll
        for (int nf = 0; nf < 8; nf++) {
            int cl = wn * 64 + nf * 8 + q * 2;
            float o0 = (accH2[mf][nf][h*2]   - mean[mf][h]) * rstd[mf][h] * gneS[cl]   + bneS[cl];
            float o1 = (accH2[mf][nf][h*2+1] - mean[mf][h]) * rstd[mf][h] * gneS[cl+1] + bneS[cl+1];
            *(float2*)(e_out + (row0 + r) * ED_ + cl) = make_float2(o0, o1);
        }
    }
}

// ---------------- node-side SIMT GEMM + LN ----------------
template<bool RELU>
__global__ void __launch_bounds__(256) gemm_kernel(
    const float* __restrict__ A, const float* __restrict__ W,
    const float* __restrict__ bias, float* __restrict__ C,
    int M, int N, int K, float alpha)
{
    __shared__ __align__(16) float aS[64][68];
    __shared__ __align__(16) float wS[64][68];
    const int tid = threadIdx.x;
    const int tx  = tid & 15;
    const int ty  = tid >> 4;
    const size_t row0 = (size_t)blockIdx.y * 64;
    const int    col0 = blockIdx.x * 64;
    float acc[4][4] = {};
    for (int k0 = 0; k0 < K; k0 += 64) {
        #pragma unroll
        for (int t = tid; t < 1024; t += 256) {
            int r = t >> 4, c4 = (t & 15) << 2;
            float4 av = *(const float4*)(A + (row0 + r) * K + k0 + c4);
            aS[r][c4+0]=av.x; aS[r][c4+1]=av.y; aS[r][c4+2]=av.z; aS[r][c4+3]=av.w;
            float4 wv = *(const float4*)(W + (size_t)(k0 + r) * N + col0 + c4);
            wS[r][c4+0]=wv.x; wS[r][c4+1]=wv.y; wS[r][c4+2]=wv.z; wS[r][c4+3]=wv.w;
        }
        __syncthreads();
        #pragma unroll 16
        for (int k = 0; k < 64; ++k) {
            float a0=aS[ty*4+0][k], a1=aS[ty*4+1][k], a2=aS[ty*4+2][k], a3=aS[ty*4+3][k];
            float4 bv = *(const float4*)&wS[k][tx*4];
            acc[0][0]+=a0*bv.x; acc[0][1]+=a0*bv.y; acc[0][2]+=a0*bv.z; acc[0][3]+=a0*bv.w;
            acc[1][0]+=a1*bv.x; acc[1][1]+=a1*bv.y; acc[1][2]+=a1*bv.z; acc[1][3]+=a1*bv.w;
            acc[2][0]+=a2*bv.x; acc[2][1]+=a2*bv.y; acc[2][2]+=a2*bv.z; acc[2][3]+=a2*bv.w;
            acc[3][0]+=a3*bv.x; acc[3][1]+=a3*bv.y; acc[3][2]+=a3*bv.z; acc[3][3]+=a3*bv.w;
        }
        __syncthreads();
    }
    const int c = col0 + tx * 4;
    float b0=bias[c+0], b1=bias[c+1], b2=bias[c+2], b3=bias[c+3];
    #pragma unroll
    for (int m = 0; m < 4; ++m) {
        float4 o;
        o.x = alpha*(acc[m][0]+b0); o.y = alpha*(acc[m][1]+b1);
        o.z = alpha*(acc[m][2]+b2); o.w = alpha*(acc[m][3]+b3);
        if (RELU) { o.x=fmaxf(o.x,0.f); o.y=fmaxf(o.y,0.f); o.z=fmaxf(o.z,0.f); o.w=fmaxf(o.w,0.f); }
        *(float4*)(C + (row0 + ty*4 + m) * N + c) = o;
    }
}

__global__ void ln_kernel(const float* __restrict__ A, const float* __restrict__ Bv,
                          const float* __restrict__ g, const float* __restrict__ be,
                          float* __restrict__ out)
{
    __shared__ float red[8];
    const int D = blockDim.x;
    const size_t base = (size_t)blockIdx.x * D + threadIdx.x;
    const int lane = threadIdx.x & 31;
    const int w    = threadIdx.x >> 5;
    const int nw   = D >> 5;
    float v = A[base] + Bv[base];
    float s = v;
    #pragma unroll
    for (int o = 16; o; o >>= 1) s += __shfl_xor_sync(0xffffffffu, s, o);
    if (lane == 0) red[w] = s;
    __syncthreads();
    float tot = 0.f;
    for (int ww = 0; ww < nw; ++ww) tot += red[ww];
    float mean = tot / (float)D;
    float d = v - mean;
    __syncthreads();
    float s2 = d * d;
    #pragma unroll
    for (int o = 16; o; o >>= 1) s2 += __shfl_xor_sync(0xffffffffu, s2, o);
    if (lane == 0) red[w] = s2;
    __syncthreads();
    float tot2 = 0.f;
    for (int ww = 0; ww < nw; ++ww) tot2 += red[ww];
    float var = tot2 / (float)D;
    out[base] = d * rsqrtf(var + 1e-5f) * g[threadIdx.x] + be[threadIdx.x];
}

// ---------------- launcher ----------------
extern "C" void kernel_launch(void* const* d_in, const int* in_sizes, int n_in,
                              void* d_out, int out_size)
{
    const float* x   = (const float*)d_in[0];
    const float* e   = (const float*)d_in[1];
    const float* wq  = (const float*)d_in[2];
    const float* wk  = (const float*)d_in[3];
    const float* wv  = (const float*)d_in[4];
    const float* wem = (const float*)d_in[5];
    const float* wea = (const float*)d_in[6];
    const float* wxo = (const float*)d_in[7];
    const float* weo = (const float*)d_in[8];
    const float* wx1 = (const float*)d_in[9];
    const float* wx2 = (const float*)d_in[10];
    const float* we1 = (const float*)d_in[11];
    const float* we2 = (const float*)d_in[12];
    const float* bq  = (const float*)d_in[13];
    const float* bk  = (const float*)d_in[14];
    const float* bv  = (const float*)d_in[15];
    const float* bem = (const float*)d_in[16];
    const float* bea = (const float*)d_in[17];
    const float* bxo = (const float*)d_in[18];
    const float* beo = (const float*)d_in[19];
    const float* bx1 = (const float*)d_in[20];
    const float* bx2 = (const float*)d_in[21];
    const float* be1 = (const float*)d_in[22];
    const float* be2 = (const float*)d_in[23];
    const float* gnx = (const float*)d_in[24];
    const float* bnx = (const float*)d_in[25];
    const float* gne = (const float*)d_in[26];
    const float* bne = (const float*)d_in[27];

    float* x_out = (float*)d_out;
    float* e_out = (float*)d_out + (size_t)ROWS_X * XD_;

    float *Q, *Km, *newX, *hx, *h1x, *h2x, *wvx, *bvx, *zero, *w2, *beoF;
    char *wemP, *weoP, *w2P, *we1P, *we2P;
    cudaGetSymbolAddress((void**)&Q,    g_Q);
    cudaGetSymbolAddress((void**)&Km,   g_Km);
    cudaGetSymbolAddress((void**)&newX, g_newX);
    cudaGetSymbolAddress((void**)&hx,   g_hx);
    cudaGetSymbolAddress((void**)&h1x,  g_h1x);
    cudaGetSymbolAddress((void**)&h2x,  g_h2x);
    cudaGetSymbolAddress((void**)&wvx,  g_wvx);
    cudaGetSymbolAddress((void**)&bvx,  g_bvx);
    cudaGetSymbolAddress((void**)&zero, g_zero);
    cudaGetSymbolAddress((void**)&w2,   g_w2);
    cudaGetSymbolAddress((void**)&beoF, g_beoF);
    cudaGetSymbolAddress((void**)&wemP, g_wemP);
    cudaGetSymbolAddress((void**)&weoP, g_weoP);
    cudaGetSymbolAddress((void**)&w2P,  g_w2P);
    cudaGetSymbolAddress((void**)&we1P, g_we1P);
    cudaGetSymbolAddress((void**)&we2P, g_we2P);

    cudaFuncSetAttribute(edge_fused_kernel, cudaFuncAttributeMaxDynamicSharedMemorySize, EF_BYTES);
    cudaFuncSetAttribute(prep_all12,        cudaFuncAttributeMaxDynamicSharedMemorySize, 128 * 129 * 4);
    cudaFuncSetAttribute(prep_w2,           cudaFuncAttributeMaxDynamicSharedMemorySize, 128 * 129 * 4);

    // one-time side-stream/event setup (host objects only)
    static cudaStream_t sNode = nullptr, sQK = nullptr, sW2 = nullptr;
    static cudaEvent_t evFork = nullptr, evJoin = nullptr, evQK = nullptr, evW2 = nullptr;
    if (!sNode) {
        cudaStreamCreateWithFlags(&sNode, cudaStreamNonBlocking);
        cudaStreamCreateWithFlags(&sQK,   cudaStreamNonBlocking);
        cudaStreamCreateWithFlags(&sW2,   cudaStreamNonBlocking);
        cudaEventCreateWithFlags(&evFork, cudaEventDisableTiming);
        cudaEventCreateWithFlags(&evJoin, cudaEventDisableTiming);
        cudaEventCreateWithFlags(&evQK,   cudaEventDisableTiming);
        cudaEventCreateWithFlags(&evW2,   cudaEventDisableTiming);
    }

    dim3 blk(256);
    auto grid_of = [](int M, int N) { return dim3((unsigned)(N/64), (unsigned)(M/64)); };

    // ---- fork ----
    cudaEventRecord(evFork, 0);
    cudaStreamWaitEvent(sNode, evFork, 0);
    cudaStreamWaitEvent(sQK,   evFork, 0);
    cudaStreamWaitEvent(sW2,   evFork, 0);

    // node side on sNode (softmax collapses: wV == V; fold wv@wxo)
    gemm_kernel<false><<<grid_of(XD_, XD_), blk, 0, sNode>>>(wv, wxo, zero, wvx, XD_, XD_, XD_, 1.f);
    fold_bias<<<1, 256, 0, sNode>>>(bv, wxo, bxo, bvx);
    gemm_kernel<false><<<grid_of(ROWS_X, XD_), blk, 0, sNode>>>(x, wvx, bvx, newX, ROWS_X, XD_, XD_, 1.f);
    ln_kernel<<<ROWS_X, XD_, 0, sNode>>>(x, newX, gnx, bnx, hx);
    gemm_kernel<true ><<<grid_of(ROWS_X, FFX), blk, 0, sNode>>>(hx,  wx1, bx1, h1x, ROWS_X, FFX, XD_, 1.f);
    gemm_kernel<false><<<grid_of(ROWS_X, XD_), blk, 0, sNode>>>(h1x, wx2, bx2, h2x, ROWS_X, XD_, FFX, 1.f);
    ln_kernel<<<ROWS_X, XD_, 0, sNode>>>(x, h2x, gnx, bnx, x_out);
    cudaEventRecord(evJoin, sNode);

    // Q/K projections on sQK
    gemm_kernel<false><<<grid_of(ROWS_X, XD_), blk, 0, sQK>>>(x, wq, bq, Q,  ROWS_X, XD_, XD_, INV_SQRT_DF);
    gemm_kernel<false><<<grid_of(ROWS_X, XD_), blk, 0, sQK>>>(x, wk, bk, Km, ROWS_X, XD_, XD_, 1.f);
    cudaEventRecord(evQK, sQK);

    // W2 chain on sW2: W2 = wea@weo -> fold_beo -> prep w2 tile
    gemm_kernel<false><<<grid_of(ED_, ED_), blk, 0, sW2>>>(wea, weo, zero, w2, ED_, ED_, XD_, 1.f);
    fold_beo<<<1, 128, 0, sW2>>>(bea, weo, beo, beoF);
    prep_w2<<<1, 256, 128 * 129 * 4, sW2>>>(w2, w2P);
    cudaEventRecord(evW2, sW2);

    // main stream: prep of the 12 direct weight tiles, then edge
    prep_all12<<<12, 256, 128 * 129 * 4>>>(wem, weo, we1, we2, wemP, weoP, we1P, we2P);
    cudaStreamWaitEvent(0, evQK, 0);
    cudaStreamWaitEvent(0, evW2, 0);

    edge_fused_kernel<<<ROWS_E / 128, blk, EF_BYTES>>>(
        e, Q, Km, w2P, wemP, weoP, we1P, we2P,
        bem, beoF, be1, be2, gne, bne, e_out);

    // ---- join ----
    cudaStreamWaitEvent(0, evJoin, 0);
}

// round 13
// speedup vs baseline: 5.5862x; 1.1327x over previous
#include <cuda_runtime.h>
#include <cuda_bf16.h>
#include <math.h>
#include <stdint.h>

#define BB  8
#define NN  128
#define XD_ 256
#define ED_ 128
#define FFX 1024
#define FFE 512
#define ROWS_X (BB*NN)
#define ROWS_E (BB*NN*NN)
#define INV_SQRT_DF 0.17677669529663687f

#define PITCH   272           // bytes per bf16 tile row (136 bf16)
#define TILE_W  34816         // 128 * 272 (one bf16 128x128 weight tile)

// ---------------- scratch ----------------
__device__ float g_Q   [ROWS_X * XD_];
__device__ float g_Km  [ROWS_X * XD_];
__device__ float g_newX[ROWS_X * XD_];
__device__ float g_hx  [ROWS_X * XD_];
__device__ float g_h1x [ROWS_X * FFX];
__device__ float g_h2x [ROWS_X * XD_];
__device__ float g_wvx [XD_ * XD_];
__device__ float g_bvx [XD_];
__device__ float g_zero[FFX];
__device__ float g_w2  [ED_ * ED_];      // wea @ weo (fp32)
__device__ float g_beoF[ED_];            // beo + bea @ weo
__device__ __align__(16) char g_wemP[2 * TILE_W];
__device__ __align__(16) char g_weoP[2 * TILE_W];
__device__ __align__(16) char g_w2P [TILE_W];
__device__ __align__(16) char g_we1P[4 * TILE_W];
__device__ __align__(16) char g_we2P[4 * TILE_W];

// ---------------- helpers ----------------
__device__ __forceinline__ uint32_t smem_u32(const void* p) {
    uint32_t a;
    asm("{ .reg .u64 t; cvta.to.shared.u64 t, %1; cvt.u32.u64 %0, t; }" : "=r"(a) : "l"(p));
    return a;
}

#define CPA16(dst, src) asm volatile("cp.async.cg.shared.global [%0], [%1], 16;" :: "r"(dst), "l"(src))
#define CP_COMMIT() asm volatile("cp.async.commit_group;" ::: "memory")
#define CP_WAIT0()  asm volatile("cp.async.wait_group 0;" ::: "memory")

__device__ __forceinline__ void prefetch_w(uint32_t dstS, const char* src, int tid) {
    #pragma unroll 4
    for (int t = tid; t < 2176; t += 256)
        CPA16(dstS + (uint32_t)t * 16, src + (size_t)t * 16);
    CP_COMMIT();
}

__device__ __forceinline__ void mma16816(float* c, uint32_t a0, uint32_t a1, uint32_t a2,
                                         uint32_t a3, uint32_t b0, uint32_t b1) {
    asm volatile(
        "mma.sync.aligned.m16n8k16.row.col.f32.bf16.bf16.f32 "
        "{%0,%1,%2,%3},{%4,%5,%6,%7},{%8,%9},{%0,%1,%2,%3};"
        : "+f"(c[0]), "+f"(c[1]), "+f"(c[2]), "+f"(c[3])
        : "r"(a0), "r"(a1), "r"(a2), "r"(a3), "r"(b0), "r"(b1));
}

__device__ __forceinline__ void ldsm4(uint32_t& r0, uint32_t& r1, uint32_t& r2, uint32_t& r3,
                                      uint32_t a) {
    asm volatile("ldmatrix.sync.aligned.m8n8.x4.shared.b16 {%0,%1,%2,%3},[%4];"
                 : "=r"(r0), "=r"(r1), "=r"(r2), "=r"(r3) : "r"(a));
}

// A fragment: 32 rows x 16 k
__device__ __forceinline__ void ldA8(uint32_t a[8], uint32_t base, int r0, int k0, int lane) {
    uint32_t addr = base + (uint32_t)(r0 + (lane & 15)) * PITCH
                  + (uint32_t)(k0 + ((lane >> 4) << 3)) * 2;
    ldsm4(a[0], a[1], a[2], a[3], addr);
    ldsm4(a[4], a[5], a[6], a[7], addr + 16 * PITCH);
}

// B fragment: 32 n x 16 k
__device__ __forceinline__ void ldB8(uint32_t b[8], uint32_t base, int n0, int k0, int lane) {
    uint32_t addr = base + (uint32_t)(n0 + ((lane >> 4) << 3) + (lane & 7)) * PITCH
                  + (uint32_t)(k0 + (((lane >> 3) & 1) << 3)) * 2;
    ldsm4(b[0], b[1], b[2], b[3], addr);
    ldsm4(b[4], b[5], b[6], b[7], addr + 16 * PITCH);
}

__device__ __forceinline__ void mma_pass(float (&acc)[2][4][4], const uint32_t a[8],
                                         const uint32_t b[8]) {
    #pragma unroll
    for (int mf = 0; mf < 2; mf++)
        #pragma unroll
        for (int nf = 0; nf < 4; nf++)
            mma16816(acc[mf][nf], a[mf*4], a[mf*4+1], a[mf*4+2], a[mf*4+3],
                     b[nf*2], b[nf*2+1]);
}

// 1-pass bf16 GEMM tile (M=64 local, K=128)
__device__ __forceinline__ void compute_ktile(float (&acc)[2][4][4], uint32_t aB,
                                              uint32_t bB, int wm, int wn, int lane) {
    #pragma unroll 2
    for (int ks = 0; ks < 8; ks++) {
        uint32_t ah[8], bh[8];
        ldA8(ah, aB, wm * 32, ks * 16, lane);
        ldB8(bh, bB, wn * 32, ks * 16, lane);
        mma_pass(acc, ah, bh);
    }
}

__device__ __forceinline__ uint32_t pkf2(float x, float y) {
    __nv_bfloat162 t = __floats2bfloat162_rn(x, y);
    return *reinterpret_cast<uint32_t*>(&t);
}

// stage 64x128 fp32 -> bf16 pitched tile
__device__ __forceinline__ void stage_a_fp32(char* sm, const float* src, int stride, int tid) {
    #pragma unroll 2
    for (int t = tid; t < 2048; t += 256) {
        int r = t >> 5, c4 = (t & 31) << 2;
        float4 v = *(const float4*)(src + (size_t)r * stride + c4);
        uint32_t p0 = pkf2(v.x, v.y);
        uint32_t p1 = pkf2(v.z, v.w);
        *(uint2*)(sm + (uint32_t)r * PITCH + (uint32_t)c4 * 2) = make_uint2(p0, p1);
    }
}

// ---------------- weight prep ----------------
__device__ __forceinline__ void prep_tile(const float* W, char* out, int N, int kc, int nc,
                                          float* tl, int tid) {
    for (int t = tid; t < 16384; t += 256) {
        int k = t >> 7, n = t & 127;
        tl[k * 129 + n] = W[(size_t)(kc * 128 + k) * N + nc * 128 + n];
    }
    __syncthreads();
    for (int t = tid; t < 8192; t += 256) {
        int n = t >> 6, k = (t & 63) << 1;
        float v0 = tl[k * 129 + n], v1 = tl[(k + 1) * 129 + n];
        *(uint32_t*)(out + (uint32_t)n * PITCH + (uint32_t)k * 2) = pkf2(v0, v1);
    }
}

__global__ void prep_all12(const float* __restrict__ wem, const float* __restrict__ weo,
                           const float* __restrict__ we1, const float* __restrict__ we2,
                           char* __restrict__ wemP, char* __restrict__ weoP,
                           char* __restrict__ we1P, char* __restrict__ we2P)
{
    extern __shared__ float tl[];   // 128 x 129
    int s = blockIdx.x;
    const float* W; char* out; int N, kc, nc;
    if (s < 2)       { W = wem; out = wemP + (size_t)s       * TILE_W; N = 256; kc = 0;     nc = s;     }
    else if (s < 4)  { W = weo; out = weoP + (size_t)(s - 2) * TILE_W; N = 128; kc = s - 2; nc = 0;     }
    else if (s < 8)  { W = we1; out = we1P + (size_t)(s - 4) * TILE_W; N = 512; kc = 0;     nc = s - 4; }
    else             { W = we2; out = we2P + (size_t)(s - 8) * TILE_W; N = 128; kc = s - 8; nc = 0;     }
    prep_tile(W, out, N, kc, nc, tl, threadIdx.x);
}

__global__ void prep_w2(const float* __restrict__ w2, char* __restrict__ w2P) {
    extern __shared__ float tl[];
    prep_tile(w2, w2P, 128, 0, 0, tl, threadIdx.x);
}

__global__ void fold_bias(const float* __restrict__ bv, const float* __restrict__ wxo,
                          const float* __restrict__ bxo, float* __restrict__ bvx) {
    int n = threadIdx.x;
    float s = bxo[n];
    for (int k = 0; k < XD_; ++k) s += bv[k] * wxo[k * XD_ + n];
    bvx[n] = s;
}

__global__ void fold_beo(const float* __restrict__ bea, const float* __restrict__ weo,
                         const float* __restrict__ beo, float* __restrict__ beoF) {
    int n = threadIdx.x;
    float s = beo[n];
    for (int c = 0; c < XD_; ++c) s += bea[c] * weo[c * ED_ + n];
    beoF[n] = s;
}

// ================ fused edge kernel, 64-row tiles, 2 CTAs/SM ================
#define R_A   0          // 17408
#define R_B0  17408      // 34816
#define R_B1  52224      // 34816
#define R_C   87040      // 17408
#define R_SM  104448
#define EF_BYTES (104448 + 8192)

__global__ void __launch_bounds__(256, 2) edge_fused_kernel(
    const float* __restrict__ e, const float* __restrict__ Qs, const float* __restrict__ Km,
    const char* __restrict__ w2P, const char* __restrict__ wemP, const char* __restrict__ weoP,
    const char* __restrict__ we1P, const char* __restrict__ we2P,
    const float* __restrict__ bem, const float* __restrict__ beoF,
    const float* __restrict__ be1, const float* __restrict__ be2,
    const float* __restrict__ gne, const float* __restrict__ bne,
    float* __restrict__ e_out)
{
    extern __shared__ char sm[];
    const int tid = threadIdx.x;
    const int lane = tid & 31, w = tid >> 5;
    const int wm = w & 1, wn = w >> 1;      // 2 x 4 warp grid
    const int g = lane >> 2, q = lane & 3;
    const int blk = blockIdx.x;
    const size_t row0 = (size_t)blk * 64;
    const int b = (int)(row0 >> 14);
    const int i = (int)((row0 >> 7) & 127);
    const int j0 = (int)(row0 & 127);       // 0 or 64

    uint32_t smB = smem_u32(sm);
    float* qS   = (float*)(sm + R_SM);              // 256
    float* bemS = qS + 256;                          // 256
    float* beoS = bemS + 256;                        // 128
    float* gneS = beoS + 128;                        // 128
    float* bneS = gneS + 128;                        // 128
    float* be1S = bneS + 128;                        // 512
    float* be2S = be1S + 512;                        // 128
    float* red  = be2S + 128;                        // 256
    float* red2 = red + 256;                         // 256

    const uint32_t aB = smB + R_A;
    const uint32_t cB = smB + R_C;
    const uint32_t Bb[2] = {smB + R_B0, smB + R_B1};
    const char* tiles[13] = {
        w2P, wemP, weoP, wemP + TILE_W, weoP + TILE_W,
        we1P,              we2P,
        we1P + TILE_W,     we2P + TILE_W,
        we1P + 2 * TILE_W, we2P + 2 * TILE_W,
        we1P + 3 * TILE_W, we2P + 3 * TILE_W};

    prefetch_w(Bb[0], tiles[0], tid);               // tile 0 in flight
    stage_a_fp32(sm + R_A, e + row0 * ED_, ED_, tid);
    qS[tid]   = Qs[((size_t)(b * NN + i)) * XD_ + tid];
    bemS[tid] = bem[tid];
    if (tid < 128) { beoS[tid] = beoF[tid]; gneS[tid] = gne[tid]; bneS[tid] = bne[tid]; }
    if (tid < 128) be2S[tid] = be2[tid];
    for (int t = tid; t < 512; t += 256) be1S[t] = be1[t];
    CP_WAIT0(); __syncthreads();
    prefetch_w(Bb[1], tiles[1], tid);               // tile 1 in flight

    // =================== attention phase ===================
    float accNE[2][4][4] = {};

    // ---- phase 0: accNE = e @ W2   (collapsed E2 path)
    compute_ktile(accNE, aB, Bb[0], wm, wn, lane);
    CP_WAIT0(); __syncthreads();
    prefetch_w(Bb[0], tiles[2], tid);

    #pragma unroll 1
    for (int nc = 0; nc < 2; nc++) {
        const int p = 1 + nc * 2;
        // ---- phase p (wem[nc]): E1 = e@wem; Y = q*km*(E1+bem+1) -> bf16 into C
        {
            float acc[2][4][4] = {};
            compute_ktile(acc, aB, Bb[p & 1], wm, wn, lane);
            #pragma unroll
            for (int mf = 0; mf < 2; mf++)
            #pragma unroll
            for (int h = 0; h < 2; h++) {
                int r = wm * 32 + mf * 16 + h * 8 + g;
                const float* kp = Km + ((size_t)(b * NN + j0 + r)) * XD_ + nc * 128;
                #pragma unroll
                for (int nf = 0; nf < 4; nf++) {
                    int cl = wn * 32 + nf * 8 + q * 2;
                    int cg = nc * 128 + cl;
                    float2 km = *(const float2*)(kp + cl);
                    float y0 = qS[cg]   * km.x * (acc[mf][nf][h*2]   + bemS[cg]   + 1.f);
                    float y1 = qS[cg+1] * km.y * (acc[mf][nf][h*2+1] + bemS[cg+1] + 1.f);
                    *(uint32_t*)(sm + R_C + (uint32_t)r * PITCH + (uint32_t)cl * 2) = pkf2(y0, y1);
                }
            }
        }
        CP_WAIT0(); __syncthreads();
        prefetch_w(Bb[p & 1], tiles[p + 2], tid);
        // ---- phase p+1 (weo[nc]): accNE += Y @ weo
        compute_ktile(accNE, cB, Bb[(p + 1) & 1], wm, wn, lane);
        CP_WAIT0(); __syncthreads();
        prefetch_w(Bb[(p + 1) & 1], tiles[p + 3], tid);
    }

    // ---- attn epilogue: he = LN(e + accNE + beoF)*gne + bne -> bf16 INTO A REGION
    #pragma unroll
    for (int mf = 0; mf < 2; mf++)
    #pragma unroll
    for (int h = 0; h < 2; h++) {
        int r = wm * 32 + mf * 16 + h * 8 + g;
        #pragma unroll
        for (int nf = 0; nf < 4; nf++) {
            int cl = wn * 32 + nf * 8 + q * 2;
            float2 ev = *(const float2*)(e + (row0 + r) * ED_ + cl);
            accNE[mf][nf][h*2+0] += beoS[cl]   + ev.x;
            accNE[mf][nf][h*2+1] += beoS[cl+1] + ev.y;
        }
    }
    {
        float mean[2][2], rstd[2][2];
        #pragma unroll
        for (int mf = 0; mf < 2; mf++)
        #pragma unroll
        for (int h = 0; h < 2; h++) {
            float s = 0.f;
            #pragma unroll
            for (int nf = 0; nf < 4; nf++) s += accNE[mf][nf][h*2] + accNE[mf][nf][h*2+1];
            s += __shfl_xor_sync(0xffffffffu, s, 1);
            s += __shfl_xor_sync(0xffffffffu, s, 2);
            if (q == 0) red[wn * 64 + wm * 32 + mf * 16 + h * 8 + g] = s;
        }
        __syncthreads();
        #pragma unroll
        for (int mf = 0; mf < 2; mf++)
        #pragma unroll
        for (int h = 0; h < 2; h++) {
            int r = wm * 32 + mf * 16 + h * 8 + g;
            mean[mf][h] = (red[r] + red[64 + r] + red[128 + r] + red[192 + r]) * (1.f / 128.f);
            float s = 0.f;
            #pragma unroll
            for (int nf = 0; nf < 4; nf++) {
                float d0 = accNE[mf][nf][h*2]   - mean[mf][h];
                float d1 = accNE[mf][nf][h*2+1] - mean[mf][h];
                s += d0 * d0 + d1 * d1;
            }
            s += __shfl_xor_sync(0xffffffffu, s, 1);
            s += __shfl_xor_sync(0xffffffffu, s, 2);
            if (q == 0) red2[wn * 64 + r] = s;
        }
        __syncthreads();
        #pragma unroll
        for (int mf = 0; mf < 2; mf++)
        #pragma unroll
        for (int h = 0; h < 2; h++) {
            int r = wm * 32 + mf * 16 + h * 8 + g;
            rstd[mf][h] = rsqrtf((red2[r] + red2[64 + r] + red2[128 + r] + red2[192 + r])
                                 * (1.f / 128.f) + 1e-5f);
            #pragma unroll
            for (int nf = 0; nf < 4; nf++) {
                int cl = wn * 32 + nf * 8 + q * 2;
                float o0 = (accNE[mf][nf][h*2]   - mean[mf][h]) * rstd[mf][h] * gneS[cl]   + bneS[cl];
                float o1 = (accNE[mf][nf][h*2+1] - mean[mf][h]) * rstd[mf][h] * gneS[cl+1] + bneS[cl+1];
                // he -> A region, MMA layout (e-tile is dead now)
                *(uint32_t*)(sm + R_A + (uint32_t)r * PITCH + (uint32_t)cl * 2) = pkf2(o0, o1);
            }
        }
    }
    __syncthreads();   // he visible to all warps before FF ktiles

    // =================== FF phase (A = he, C = h1 chunks) ===================
    float accH2[2][4][4] = {};

    #pragma unroll 1
    for (int p = 0; p < 4; p++) {
        const int i0 = 5 + p * 2;
        // ---- tile i0 (we1[p]): h1 = relu(he@we1 + be1) -> bf16 into C
        {
            float acc[2][4][4] = {};
            compute_ktile(acc, aB, Bb[i0 & 1], wm, wn, lane);
            #pragma unroll
            for (int mf = 0; mf < 2; mf++)
            #pragma unroll
            for (int h = 0; h < 2; h++) {
                int r = wm * 32 + mf * 16 + h * 8 + g;
                #pragma unroll
                for (int nf = 0; nf < 4; nf++) {
                    int cl = wn * 32 + nf * 8 + q * 2;
                    int cgl = p * 128 + cl;
                    float o0 = fmaxf(acc[mf][nf][h*2]   + be1S[cgl],   0.f);
                    float o1 = fmaxf(acc[mf][nf][h*2+1] + be1S[cgl+1], 0.f);
                    *(uint32_t*)(sm + R_C + (uint32_t)r * PITCH + (uint32_t)cl * 2) = pkf2(o0, o1);
                }
            }
        }
        CP_WAIT0(); __syncthreads();
        if (i0 + 2 < 13) prefetch_w(Bb[i0 & 1], tiles[i0 + 2], tid);
        // ---- tile i0+1 (we2[p]): h2 += h1chunk @ we2
        compute_ktile(accH2, cB, Bb[(i0 + 1) & 1], wm, wn, lane);
        CP_WAIT0(); __syncthreads();
        if (i0 + 3 < 13) prefetch_w(Bb[(i0 + 1) & 1], tiles[i0 + 3], tid);
    }

    // ---- FF epilogue: e_out = LN(e + h2 + be2) * gne + bne
    #pragma unroll
    for (int mf = 0; mf < 2; mf++)
    #pragma unroll
    for (int h = 0; h < 2; h++) {
        int r = wm * 32 + mf * 16 + h * 8 + g;
        #pragma unroll
        for (int nf = 0; nf < 4; nf++) {
            int cl = wn * 32 + nf * 8 + q * 2;
            float2 ev = *(const float2*)(e + (row0 + r) * ED_ + cl);
            accH2[mf][nf][h*2+0] += be2S[cl]   + ev.x;
            accH2[mf][nf][h*2+1] += be2S[cl+1] + ev.y;
        }
    }
    float mean[2][2], rstd[2][2];
    #pragma unroll
    for (int mf = 0; mf < 2; mf++)
    #pragma unroll
    for (int h = 0; h < 2; h++) {
        float s = 0.f;
        #pragma unroll
        for (int nf = 0; nf < 4; nf++) s += accH2[mf][nf][h*2] + accH2[mf][nf][h*2+1];
        s += __shfl_xor_sync(0xffffffffu, s, 1);
        s += __shfl_xor_sync(0xffffffffu, s, 2);
        if (q == 0) red[wn * 64 + wm * 32 + mf * 16 + h * 8 + g] = s;
    }
    __syncthreads();
    #pragma unroll
    for (int mf = 0; mf < 2; mf++)
    #pragma unroll
    for (int h = 0; h < 2; h++) {
        int r = wm * 32 + mf * 16 + h * 8 + g;
        mean[mf][h] = (red[r] + red[64 + r] + red[128 + r] + red[192 + r]) * (1.f / 128.f);
        float s = 0.f;
        #pragma unroll
        for (int nf = 0; nf < 4; nf++) {
            float d0 = accH2[mf][nf][h*2]   - mean[mf][h];
            float d1 = accH2[mf][nf][h*2+1] - mean[mf][h];
            s += d0 * d0 + d1 * d1;
        }
        s += __shfl_xor_sync(0xffffffffu, s, 1);
        s += __shfl_xor_sync(0xffffffffu, s, 2);
        if (q == 0) red2[wn * 64 + r] = s;
    }
    __syncthreads();
    #pragma unroll
    for (int mf = 0; mf < 2; mf++)
    #pragma unroll
    for (int h = 0; h < 2; h++) {
        int r = wm * 32 + mf * 16 + h * 8 + g;
        rstd[mf][h] = rsqrtf((red2[r] + red2[64 + r] + red2[128 + r] + red2[192 + r])
                             * (1.f / 128.f) + 1e-5f);
        #pragma unroll
        for (int nf = 0; nf < 4; nf++) {
            int cl = wn * 32 + nf * 8 + q * 2;
            float o0 = (accH2[mf][nf][h*2]   - mean[mf][h]) * rstd[mf][h] * gneS[cl]   + bneS[cl];
            float o1 = (accH2[mf][nf][h*2+1] - mean[mf][h]) * rstd[mf][h] * gneS[cl+1] + bneS[cl+1];
            *(float2*)(e_out + (row0 + r) * ED_ + cl) = make_float2(o0, o1);
        }
    }
}

// ---------------- node-side SIMT GEMM + LN ----------------
template<bool RELU>
__global__ void __launch_bounds__(256) gemm_kernel(
    const float* __restrict__ A, const float* __restrict__ W,
    const float* __restrict__ bias, float* __restrict__ C,
    int M, int N, int K, float alpha)
{
    __shared__ __align__(16) float aS[64][68];
    __shared__ __align__(16) float wS[64][68];
    const int tid = threadIdx.x;
    const int tx  = tid & 15;
    const int ty  = tid >> 4;
    const size_t row0 = (size_t)blockIdx.y * 64;
    const int    col0 = blockIdx.x * 64;
    float acc[4][4] = {};
    for (int k0 = 0; k0 < K; k0 += 64) {
        #pragma unroll
        for (int t = tid; t < 1024; t += 256) {
            int r = t >> 4, c4 = (t & 15) << 2;
            float4 av = *(const float4*)(A + (row0 + r) * K + k0 + c4);
            aS[r][c4+0]=av.x; aS[r][c4+1]=av.y; aS[r][c4+2]=av.z; aS[r][c4+3]=av.w;
            float4 wv = *(const float4*)(W + (size_t)(k0 + r) * N + col0 + c4);
            wS[r][c4+0]=wv.x; wS[r][c4+1]=wv.y; wS[r][c4+2]=wv.z; wS[r][c4+3]=wv.w;
        }
        __syncthreads();
        #pragma unroll 16
        for (int k = 0; k < 64; ++k) {
            float a0=aS[ty*4+0][k], a1=aS[ty*4+1][k], a2=aS[ty*4+2][k], a3=aS[ty*4+3][k];
            float4 bv = *(const float4*)&wS[k][tx*4];
            acc[0][0]+=a0*bv.x; acc[0][1]+=a0*bv.y; acc[0][2]+=a0*bv.z; acc[0][3]+=a0*bv.w;
            acc[1][0]+=a1*bv.x; acc[1][1]+=a1*bv.y; acc[1][2]+=a1*bv.z; acc[1][3]+=a1*bv.w;
            acc[2][0]+=a2*bv.x; acc[2][1]+=a2*bv.y; acc[2][2]+=a2*bv.z; acc[2][3]+=a2*bv.w;
            acc[3][0]+=a3*bv.x; acc[3][1]+=a3*bv.y; acc[3][2]+=a3*bv.z; acc[3][3]+=a3*bv.w;
        }
        __syncthreads();
    }
    const int c = col0 + tx * 4;
    float b0=bias[c+0], b1=bias[c+1], b2=bias[c+2], b3=bias[c+3];
    #pragma unroll
    for (int m = 0; m < 4; ++m) {
        float4 o;
        o.x = alpha*(acc[m][0]+b0); o.y = alpha*(acc[m][1]+b1);
        o.z = alpha*(acc[m][2]+b2); o.w = alpha*(acc[m][3]+b3);
        if (RELU) { o.x=fmaxf(o.x,0.f); o.y=fmaxf(o.y,0.f); o.z=fmaxf(o.z,0.f); o.w=fmaxf(o.w,0.f); }
        *(float4*)(C + (row0 + ty*4 + m) * N + c) = o;
    }
}

__global__ void ln_kernel(const float* __restrict__ A, const float* __restrict__ Bv,
                          const float* __restrict__ g, const float* __restrict__ be,
                          float* __restrict__ out)
{
    __shared__ float red[8];
    const int D = blockDim.x;
    const size_t base = (size_t)blockIdx.x * D + threadIdx.x;
    const int lane = threadIdx.x & 31;
    const int w    = threadIdx.x >> 5;
    const int nw   = D >> 5;
    float v = A[base] + Bv[base];
    float s = v;
    #pragma unroll
    for (int o = 16; o; o >>= 1) s += __shfl_xor_sync(0xffffffffu, s, o);
    if (lane == 0) red[w] = s;
    __syncthreads();
    float tot = 0.f;
    for (int ww = 0; ww < nw; ++ww) tot += red[ww];
    float mean = tot / (float)D;
    float d = v - mean;
    __syncthreads();
    float s2 = d * d;
    #pragma unroll
    for (int o = 16; o; o >>= 1) s2 += __shfl_xor_sync(0xffffffffu, s2, o);
    if (lane == 0) red[w] = s2;
    __syncthreads();
    float tot2 = 0.f;
    for (int ww = 0; ww < nw; ++ww) tot2 += red[ww];
    float var = tot2 / (float)D;
    out[base] = d * rsqrtf(var + 1e-5f) * g[threadIdx.x] + be[threadIdx.x];
}

// ---------------- launcher ----------------
extern "C" void kernel_launch(void* const* d_in, const int* in_sizes, int n_in,
                              void* d_out, int out_size)
{
    const float* x   = (const float*)d_in[0];
    const float* e   = (const float*)d_in[1];
    const float* wq  = (const float*)d_in[2];
    const float* wk  = (const float*)d_in[3];
    const float* wv  = (const float*)d_in[4];
    const float* wem = (const float*)d_in[5];
    const float* wea = (const float*)d_in[6];
    const float* wxo = (const float*)d_in[7];
    const float* weo = (const float*)d_in[8];
    const float* wx1 = (const float*)d_in[9];
    const float* wx2 = (const float*)d_in[10];
    const float* we1 = (const float*)d_in[11];
    const float* we2 = (const float*)d_in[12];
    const float* bq  = (const float*)d_in[13];
    const float* bk  = (const float*)d_in[14];
    const float* bv  = (const float*)d_in[15];
    const float* bem = (const float*)d_in[16];
    const float* bea = (const float*)d_in[17];
    const float* bxo = (const float*)d_in[18];
    const float* beo = (const float*)d_in[19];
    const float* bx1 = (const float*)d_in[20];
    const float* bx2 = (const float*)d_in[21];
    const float* be1 = (const float*)d_in[22];
    const float* be2 = (const float*)d_in[23];
    const float* gnx = (const float*)d_in[24];
    const float* bnx = (const float*)d_in[25];
    const float* gne = (const float*)d_in[26];
    const float* bne = (const float*)d_in[27];

    float* x_out = (float*)d_out;
    float* e_out = (float*)d_out + (size_t)ROWS_X * XD_;

    float *Q, *Km, *newX, *hx, *h1x, *h2x, *wvx, *bvx, *zero, *w2, *beoF;
    char *wemP, *weoP, *w2P, *we1P, *we2P;
    cudaGetSymbolAddress((void**)&Q,    g_Q);
    cudaGetSymbolAddress((void**)&Km,   g_Km);
    cudaGetSymbolAddress((void**)&newX, g_newX);
    cudaGetSymbolAddress((void**)&hx,   g_hx);
    cudaGetSymbolAddress((void**)&h1x,  g_h1x);
    cudaGetSymbolAddress((void**)&h2x,  g_h2x);
    cudaGetSymbolAddress((void**)&wvx,  g_wvx);
    cudaGetSymbolAddress((void**)&bvx,  g_bvx);
    cudaGetSymbolAddress((void**)&zero, g_zero);
    cudaGetSymbolAddress((void**)&w2,   g_w2);
    cudaGetSymbolAddress((void**)&beoF, g_beoF);
    cudaGetSymbolAddress((void**)&wemP, g_wemP);
    cudaGetSymbolAddress((void**)&weoP, g_weoP);
    cudaGetSymbolAddress((void**)&w2P,  g_w2P);
    cudaGetSymbolAddress((void**)&we1P, g_we1P);
    cudaGetSymbolAddress((void**)&we2P, g_we2P);

    cudaFuncSetAttribute(edge_fused_kernel, cudaFuncAttributeMaxDynamicSharedMemorySize, EF_BYTES);
    cudaFuncSetAttribute(prep_all12,        cudaFuncAttributeMaxDynamicSharedMemorySize, 128 * 129 * 4);
    cudaFuncSetAttribute(prep_w2,           cudaFuncAttributeMaxDynamicSharedMemorySize, 128 * 129 * 4);

    // one-time side-stream/event setup (host objects only)
    static cudaStream_t sNode = nullptr, sQK = nullptr, sW2 = nullptr;
    static cudaEvent_t evFork = nullptr, evJoin = nullptr, evQK = nullptr, evW2 = nullptr;
    if (!sNode) {
        cudaStreamCreateWithFlags(&sNode, cudaStreamNonBlocking);
        cudaStreamCreateWithFlags(&sQK,   cudaStreamNonBlocking);
        cudaStreamCreateWithFlags(&sW2,   cudaStreamNonBlocking);
        cudaEventCreateWithFlags(&evFork, cudaEventDisableTiming);
        cudaEventCreateWithFlags(&evJoin, cudaEventDisableTiming);
        cudaEventCreateWithFlags(&evQK,   cudaEventDisableTiming);
        cudaEventCreateWithFlags(&evW2,   cudaEventDisableTiming);
    }

    dim3 blk(256);
    auto grid_of = [](int M, int N) { return dim3((unsigned)(N/64), (unsigned)(M/64)); };

    // ---- fork ----
    cudaEventRecord(evFork, 0);
    cudaStreamWaitEvent(sNode, evFork, 0);
    cudaStreamWaitEvent(sQK,   evFork, 0);
    cudaStreamWaitEvent(sW2,   evFork, 0);

    // node side on sNode (softmax collapses: wV == V; fold wv@wxo)
    gemm_kernel<false><<<grid_of(XD_, XD_), blk, 0, sNode>>>(wv, wxo, zero, wvx, XD_, XD_, XD_, 1.f);
    fold_bias<<<1, 256, 0, sNode>>>(bv, wxo, bxo, bvx);
    gemm_kernel<false><<<grid_of(ROWS_X, XD_), blk, 0, sNode>>>(x, wvx, bvx, newX, ROWS_X, XD_, XD_, 1.f);
    ln_kernel<<<ROWS_X, XD_, 0, sNode>>>(x, newX, gnx, bnx, hx);
    gemm_kernel<true ><<<grid_of(ROWS_X, FFX), blk, 0, sNode>>>(hx,  wx1, bx1, h1x, ROWS_X, FFX, XD_, 1.f);
    gemm_kernel<false><<<grid_of(ROWS_X, XD_), blk, 0, sNode>>>(h1x, wx2, bx2, h2x, ROWS_X, XD_, FFX, 1.f);
    ln_kernel<<<ROWS_X, XD_, 0, sNode>>>(x, h2x, gnx, bnx, x_out);
    cudaEventRecord(evJoin, sNode);

    // Q/K projections on sQK
    gemm_kernel<false><<<grid_of(ROWS_X, XD_), blk, 0, sQK>>>(x, wq, bq, Q,  ROWS_X, XD_, XD_, INV_SQRT_DF);
    gemm_kernel<false><<<grid_of(ROWS_X, XD_), blk, 0, sQK>>>(x, wk, bk, Km, ROWS_X, XD_, XD_, 1.f);
    cudaEventRecord(evQK, sQK);

    // W2 chain on sW2: W2 = wea@weo -> fold_beo -> prep w2 tile
    gemm_kernel<false><<<grid_of(ED_, ED_), blk, 0, sW2>>>(wea, weo, zero, w2, ED_, ED_, XD_, 1.f);
    fold_beo<<<1, 128, 0, sW2>>>(bea, weo, beo, beoF);
    prep_w2<<<1, 256, 128 * 129 * 4, sW2>>>(w2, w2P);
    cudaEventRecord(evW2, sW2);

    // main stream: prep of the 12 direct weight tiles, then edge
    prep_all12<<<12, 256, 128 * 129 * 4>>>(wem, weo, we1, we2, wemP, weoP, we1P, we2P);
    cudaStreamWaitEvent(0, evQK, 0);
    cudaStreamWaitEvent(0, evW2, 0);

    edge_fused_kernel<<<ROWS_E / 64, blk, EF_BYTES>>>(
        e, Q, Km, w2P, wemP, weoP, we1P, we2P,
        bem, beoF, be1, be2, gne, bne, e_out);

    // ---- join ----
    cudaStreamWaitEvent(0, evJoin, 0);
}